// round 8
// baseline (speedup 1.0000x reference)
#include <cuda_runtime.h>
#include <cuda_bf16.h>
#include <math.h>
#include <stdint.h>

// ---------------------------------------------------------------------------
// Problem constants
// ---------------------------------------------------------------------------
#define BATCH   8
#define HH      128
#define WW_     128
#define LL      (HH*WW_)
#define CC      192
#define HEADS   6
#define HD      32
#define WS      8
#define NWIN    64
#define SHIFT   4
#define HIDDEN  768
#define MROWS   (BATCH*LL)                 // 131072
#define NWINDOWS (BATCH*(HH/WS)*(WW_/WS))  // 2048
#define POS_DIM 12
#define POS_TAB 225
#define QSCALE  0.17677669529663687f

// ---------------------------------------------------------------------------
// Device scratch
// ---------------------------------------------------------------------------
__device__ __nv_bfloat16 gb_xw[(size_t)MROWS * CC];
__device__ __nv_bfloat16 gb_qkv[(size_t)MROWS * 3 * CC];
__device__ __nv_bfloat16 gb_attn[(size_t)MROWS * CC];
__device__ __nv_bfloat16 gb_ln2[(size_t)MROWS * CC];
__device__ __nv_bfloat16 gb_hid[(size_t)MROWS * HIDDEN];
__device__ float g_pos[POS_TAB * HEADS];
__device__ float g_bias[4 * HEADS * NWIN * NWIN];   // [type][h][r][j]
__device__ __nv_bfloat16 gb_wt_qkv[3 * CC * CC];
__device__ __nv_bfloat16 gb_wt_proj[CC * CC];
__device__ __nv_bfloat16 gb_wt_fc1[HIDDEN * CC];
__device__ __nv_bfloat16 gb_wt_fc2[CC * HIDDEN];

// ---------------------------------------------------------------------------
// Helpers
// ---------------------------------------------------------------------------
__device__ __forceinline__ uint32_t smem_u32(const void* p) {
    uint32_t a;
    asm("{ .reg .u64 t; cvta.to.shared.u64 t, %1; cvt.u32.u64 %0, t; }" : "=r"(a) : "l"(p));
    return a;
}
__device__ __forceinline__ void cpasync16(uint32_t s, const void* g) {
    asm volatile("cp.async.cg.shared.global [%0], [%1], 16;" :: "r"(s), "l"(g));
}
__device__ __forceinline__ void cp_commit() {
    asm volatile("cp.async.commit_group;" ::: "memory");
}
__device__ __forceinline__ void cp_wait1() {
    asm volatile("cp.async.wait_group 1;" ::: "memory");
}
__device__ __forceinline__ void ldsm_x4(uint32_t addr, uint32_t* r) {
    asm volatile("ldmatrix.sync.aligned.m8n8.x4.shared.b16 {%0,%1,%2,%3}, [%4];"
                 : "=r"(r[0]), "=r"(r[1]), "=r"(r[2]), "=r"(r[3]) : "r"(addr));
}
__device__ __forceinline__ void mma_bf16(float* d, const uint32_t* a, const uint32_t* b) {
    asm volatile(
        "mma.sync.aligned.m16n8k16.row.col.f32.bf16.bf16.f32 "
        "{%0,%1,%2,%3}, {%4,%5,%6,%7}, {%8,%9}, {%0,%1,%2,%3};"
        : "+f"(d[0]), "+f"(d[1]), "+f"(d[2]), "+f"(d[3])
        : "r"(a[0]), "r"(a[1]), "r"(a[2]), "r"(a[3]), "r"(b[0]), "r"(b[1]));
}
__device__ __forceinline__ uint32_t packbf2(float x, float y) {
    __nv_bfloat162 t = __float22bfloat162_rn(make_float2(x, y));
    return *(uint32_t*)&t;
}
__device__ __forceinline__ float gelu_exact(float x) {
    return 0.5f * x * (1.0f + erff(x * 0.7071067811865476f));
}

// ---------------------------------------------------------------------------
// Combined weight transpose
// ---------------------------------------------------------------------------
#define TW_QKV (3*CC*CC)
#define TW_PROJ (CC*CC)
#define TW_FC1 (CC*HIDDEN)
#define TW_FC2 (HIDDEN*CC)
#define TW_TOTAL (TW_QKV + TW_PROJ + TW_FC1 + TW_FC2)

__global__ void transpose_all(const float* __restrict__ qkv_w, const float* __restrict__ proj_w,
                              const float* __restrict__ fc1_w, const float* __restrict__ fc2_w) {
    int i = blockIdx.x * 256 + threadIdx.x;
    if (i >= TW_TOTAL) return;
    const float* w; __nv_bfloat16* wt; int K, N, off;
    if (i < TW_QKV) { w = qkv_w; wt = gb_wt_qkv; K = CC; N = 3 * CC; off = i; }
    else if (i < TW_QKV + TW_PROJ) { w = proj_w; wt = gb_wt_proj; K = CC; N = CC; off = i - TW_QKV; }
    else if (i < TW_QKV + TW_PROJ + TW_FC1) { w = fc1_w; wt = gb_wt_fc1; K = CC; N = HIDDEN; off = i - TW_QKV - TW_PROJ; }
    else { w = fc2_w; wt = gb_wt_fc2; K = HIDDEN; N = CC; off = i - TW_QKV - TW_PROJ - TW_FC1; }
    int k = off / N, n = off % N;
    wt[(size_t)n * K + k] = __float2bfloat16(w[off]);
}

// ---------------------------------------------------------------------------
// Position-bias MLP
// ---------------------------------------------------------------------------
__device__ __forceinline__ void ln_relu12(const float* p, float* q,
                                          const float* g, const float* b) {
    float s = 0.f, s2 = 0.f;
#pragma unroll
    for (int i = 0; i < POS_DIM; i++) { s += p[i]; s2 += p[i] * p[i]; }
    float mu = s / 12.0f;
    float var = s2 / 12.0f - mu * mu;
    float rs = rsqrtf(var + 1e-5f);
#pragma unroll
    for (int i = 0; i < POS_DIM; i++) q[i] = fmaxf((p[i] - mu) * rs * g[i] + b[i], 0.0f);
}

__global__ void pos_mlp_kernel(
    const float* __restrict__ pp_w, const float* __restrict__ pp_b,
    const float* __restrict__ p1_g, const float* __restrict__ p1_b,
    const float* __restrict__ p1_w, const float* __restrict__ p1_bias,
    const float* __restrict__ p2_g, const float* __restrict__ p2_b,
    const float* __restrict__ p2_w, const float* __restrict__ p2_bias,
    const float* __restrict__ p3_g, const float* __restrict__ p3_b,
    const float* __restrict__ p3_w, const float* __restrict__ p3_bias) {
    int t = blockIdx.x * blockDim.x + threadIdx.x;
    if (t >= POS_TAB) return;
    float bh = (float)(t / 15 - 7), bw = (float)(t % 15 - 7);
    float p[POS_DIM], q[POS_DIM];
#pragma unroll
    for (int j = 0; j < POS_DIM; j++) p[j] = bh * pp_w[j] + bw * pp_w[POS_DIM + j] + pp_b[j];
    ln_relu12(p, q, p1_g, p1_b);
#pragma unroll
    for (int j = 0; j < POS_DIM; j++) {
        float s = p1_bias[j];
#pragma unroll
        for (int i = 0; i < POS_DIM; i++) s += q[i] * p1_w[i * POS_DIM + j];
        p[j] = s;
    }
    ln_relu12(p, q, p2_g, p2_b);
#pragma unroll
    for (int j = 0; j < POS_DIM; j++) {
        float s = p2_bias[j];
#pragma unroll
        for (int i = 0; i < POS_DIM; i++) s += q[i] * p2_w[i * POS_DIM + j];
        p[j] = s;
    }
    ln_relu12(p, q, p3_g, p3_b);
#pragma unroll
    for (int h = 0; h < HEADS; h++) {
        float s = p3_bias[h];
#pragma unroll
        for (int i = 0; i < POS_DIM; i++) s += q[i] * p3_w[i * HEADS + h];
        g_pos[t * HEADS + h] = s;
    }
}

// ---------------------------------------------------------------------------
// Bias table: [type][h][r][j]
// ---------------------------------------------------------------------------
__global__ void bias_build() {
    int idx = blockIdx.x * 256 + threadIdx.x;
    if (idx >= 4 * HEADS * NWIN * NWIN) return;
    int j = idx & 63;
    int r = (idx >> 6) & 63;
    int h = (idx >> 12) % HEADS;
    int t = idx / (HEADS * NWIN * NWIN);
    int ry = r >> 3, rx = r & 7, jy = j >> 3, jx = j & 7;
    float bias = g_pos[(((ry - jy + 7) * 15) + (rx - jx + 7)) * HEADS + h];
    int lhr = (t & 2) ? (ry < (WS - SHIFT) ? 1 : 2) : 0;
    int lhj = (t & 2) ? (jy < (WS - SHIFT) ? 1 : 2) : 0;
    int lwr = (t & 1) ? (rx < (WS - SHIFT) ? 1 : 2) : 0;
    int lwj = (t & 1) ? (jx < (WS - SHIFT) ? 1 : 2) : 0;
    if (lhr != lhj || lwr != lwj) bias -= 100.0f;
    g_bias[idx] = bias;
}

// ---------------------------------------------------------------------------
// LayerNorm1: warp per row, fp32 in -> bf16 out, shift+window gather
// ---------------------------------------------------------------------------
__global__ void __launch_bounds__(256) ln1_kernel(
    const float* __restrict__ in, __nv_bfloat16* __restrict__ out,
    const float* __restrict__ gamma, const float* __restrict__ beta) {
    int warp = threadIdx.x >> 5, lane = threadIdx.x & 31;
    int row = blockIdx.x * 8 + warp;
    int bb = row >> 14, rem = row & 16383;
    int win = rem >> 6, r = rem & 63;
    int wy = win >> 4, wx = win & 15, ry = r >> 3, rx = r & 7;
    int hh = (wy * WS + ry + SHIFT) & 127;
    int ww = (wx * WS + rx + SHIFT) & 127;
    size_t src = (size_t)bb * LL + hh * WW_ + ww;

    const float* p = in + src * CC;
    float v[6], s = 0.f, s2 = 0.f;
#pragma unroll
    for (int k = 0; k < 6; k++) { v[k] = p[lane + 32 * k]; s += v[k]; s2 += v[k] * v[k]; }
#pragma unroll
    for (int o = 16; o > 0; o >>= 1) {
        s += __shfl_xor_sync(0xFFFFFFFFu, s, o);
        s2 += __shfl_xor_sync(0xFFFFFFFFu, s2, o);
    }
    float mu = s * (1.0f / 192.0f);
    float rs = rsqrtf(s2 * (1.0f / 192.0f) - mu * mu + 1e-5f);
    __nv_bfloat16* q = out + (size_t)row * CC;
#pragma unroll
    for (int k = 0; k < 6; k++) {
        int c = lane + 32 * k;
        q[c] = __float2bfloat16((v[k] - mu) * rs * gamma[c] + beta[c]);
    }
}

// ---------------------------------------------------------------------------
// bf16 mma GEMM v3: 256x64 CTA tile, BK=64, warp tile 64x32, dynamic smem.
// SMEM rows: 0-255 A, 256-319 B; 8 16B-chunks/row, XOR swizzle.
// EPI 0: +bias, Q-scale cols<192 -> bf16   1: gelu(+bias) -> bf16
// EPI 3: +bias +res -> fp32
// ---------------------------------------------------------------------------
#define GCH_PER_BUF (320 * 8)
#define GEMM_SMEM (2 * GCH_PER_BUF * 16)

template <int EPI>
__global__ void __launch_bounds__(256, 2) gemm_mma(
    const __nv_bfloat16* __restrict__ A, const __nv_bfloat16* __restrict__ BT,
    const float* __restrict__ bias, const float* __restrict__ res,
    void* __restrict__ outv, int K, int NOUT) {
    extern __shared__ __align__(16) uint4 gsm[];
    uint32_t sbase = smem_u32(gsm);
    int tid = threadIdx.x;
    int wid = tid >> 5, lane = tid & 31;
    int wm = wid & 3, wn = wid >> 2;
    int m0 = blockIdx.y * 256, n0 = blockIdx.x * 64;
    const __nv_bfloat16* Ab = A + (size_t)m0 * K;
    const __nv_bfloat16* Bb = BT + (size_t)n0 * K;
    int NCH = K >> 6;

    float acc[4][4][4];
#pragma unroll
    for (int i = 0; i < 4; i++)
#pragma unroll
        for (int j = 0; j < 4; j++)
#pragma unroll
            for (int k = 0; k < 4; k++) acc[i][j][k] = 0.f;

    // cp.async: A one row/thread (8 chunks); B row = tid>>2, 2 chunks
    int b_row = tid >> 2;
    int b_ch0 = (tid & 3) * 2;

    int l15 = lane & 15, lhi = lane >> 4;
    int a_lrow = wm * 64 + l15;
    int a_sw = l15 & 7;
    int b_lrow = 256 + wn * 32 + (lhi << 3) + (lane & 7);
    int b_sw = lane & 7;
    int b_chlo = (lane >> 3) & 1;

    {
        uint32_t dst = sbase;
#pragma unroll
        for (int ch = 0; ch < 8; ch++) {
            cpasync16(dst + (tid * 8 + (ch ^ (tid & 7))) * 16,
                      Ab + (size_t)tid * K + ch * 8);
        }
#pragma unroll
        for (int i = 0; i < 2; i++) {
            int ch = b_ch0 + i;
            cpasync16(dst + ((256 + b_row) * 8 + (ch ^ (b_row & 7))) * 16,
                      Bb + (size_t)b_row * K + ch * 8);
        }
        cp_commit();
    }

    for (int c = 0; c < NCH; c++) {
        if (c + 1 < NCH) {
            int k0 = (c + 1) << 6;
            uint32_t dst = sbase + ((c + 1) & 1) * GCH_PER_BUF * 16;
#pragma unroll
            for (int ch = 0; ch < 8; ch++) {
                cpasync16(dst + (tid * 8 + (ch ^ (tid & 7))) * 16,
                          Ab + (size_t)tid * K + k0 + ch * 8);
            }
#pragma unroll
            for (int i = 0; i < 2; i++) {
                int ch = b_ch0 + i;
                cpasync16(dst + ((256 + b_row) * 8 + (ch ^ (b_row & 7))) * 16,
                          Bb + (size_t)b_row * K + k0 + ch * 8);
            }
        }
        cp_commit();
        cp_wait1();
        __syncthreads();

        uint32_t buf = sbase + (c & 1) * GCH_PER_BUF * 16;
#pragma unroll
        for (int ks = 0; ks < 4; ks++) {
            uint32_t a[4][4], b[2][4];
            int achk = 2 * ks + lhi;
#pragma unroll
            for (int mt = 0; mt < 4; mt++) {
                uint32_t idx = (a_lrow + mt * 16) * 8 + (achk ^ a_sw);
                ldsm_x4(buf + idx * 16, a[mt]);
            }
            int bchk = 2 * ks + b_chlo;
#pragma unroll
            for (int nt16 = 0; nt16 < 2; nt16++) {
                uint32_t idx = (b_lrow + nt16 * 16) * 8 + (bchk ^ b_sw);
                ldsm_x4(buf + idx * 16, b[nt16]);
            }
#pragma unroll
            for (int mt = 0; mt < 4; mt++) {
#pragma unroll
                for (int nt16 = 0; nt16 < 2; nt16++) {
                    mma_bf16(acc[mt][nt16 * 2 + 0], a[mt], &b[nt16][0]);
                    mma_bf16(acc[mt][nt16 * 2 + 1], a[mt], &b[nt16][2]);
                }
            }
        }
        __syncthreads();
    }

#pragma unroll
    for (int mt = 0; mt < 4; mt++) {
        int g0 = m0 + wm * 64 + mt * 16 + (lane >> 2);
        int g1 = g0 + 8;
        size_t ob0 = (size_t)g0 * NOUT;
        size_t ob1 = (size_t)g1 * NOUT;
#pragma unroll
        for (int nt = 0; nt < 4; nt++) {
            int col = n0 + wn * 32 + nt * 8 + 2 * (lane & 3);
            float b0 = bias[col], b1 = bias[col + 1];
            float2 v0 = make_float2(acc[mt][nt][0] + b0, acc[mt][nt][1] + b1);
            float2 v1 = make_float2(acc[mt][nt][2] + b0, acc[mt][nt][3] + b1);
            if (EPI == 0) {
                float sc = (col < CC) ? QSCALE : 1.0f;
                v0.x *= sc; v0.y *= sc; v1.x *= sc; v1.y *= sc;
            }
            if (EPI == 1) {
                v0.x = gelu_exact(v0.x); v0.y = gelu_exact(v0.y);
                v1.x = gelu_exact(v1.x); v1.y = gelu_exact(v1.y);
            }
            if (EPI == 0 || EPI == 1) {
                __nv_bfloat16* out = (__nv_bfloat16*)outv;
                *(__nv_bfloat162*)(out + ob0 + col) = __float22bfloat162_rn(v0);
                *(__nv_bfloat162*)(out + ob1 + col) = __float22bfloat162_rn(v1);
            } else {
                float* out = (float*)outv;
                float2 r0 = *(const float2*)(res + ob0 + col);
                float2 r1 = *(const float2*)(res + ob1 + col);
                v0.x += r0.x; v0.y += r0.y;
                v1.x += r1.x; v1.y += r1.y;
                *(float2*)(out + ob0 + col) = v0;
                *(float2*)(out + ob1 + col) = v1;
            }
        }
    }
}

// ---------------------------------------------------------------------------
// Proj GEMM + scatter + residual + LN2 (fused)
// ---------------------------------------------------------------------------
#define PCH_PER_BUF (320 * 8)
#define PROJ_SMEM (2 * PCH_PER_BUF * 16)

__global__ void __launch_bounds__(256) gemm_proj_ln(
    const __nv_bfloat16* __restrict__ A, const __nv_bfloat16* __restrict__ BT,
    const float* __restrict__ bias, const float* __restrict__ x,
    float* __restrict__ y, __nv_bfloat16* __restrict__ ln2out,
    const float* __restrict__ n2g, const float* __restrict__ n2b) {
    extern __shared__ __align__(16) uint4 psm[];
    uint32_t sbase = smem_u32(psm);
    int tid = threadIdx.x;
    int wid = tid >> 5, lane = tid & 31;
    int m0 = blockIdx.x * 128;
    const __nv_bfloat16* Ab = A + (size_t)m0 * CC;

    float acc[24][4];
#pragma unroll
    for (int j = 0; j < 24; j++)
#pragma unroll
        for (int k = 0; k < 4; k++) acc[j][k] = 0.f;

    int a_row = tid >> 1;
    int a_ch0 = (tid & 1) * 4;
    int b_row = tid >> 2;
    int b_ch0 = (tid & 3) * 2;

    int l15 = lane & 15, lhi = lane >> 4;
    int a_lrow = wid * 16 + l15;
    int a_sw = l15 & 7;
    int b_lbase = 128 + (lhi << 3) + (lane & 7);
    int b_sw = lane & 7;
    int b_chlo = (lane >> 3) & 1;

    {
        uint32_t dst = sbase;
#pragma unroll
        for (int i = 0; i < 4; i++) {
            int ch = a_ch0 + i;
            cpasync16(dst + (a_row * 8 + (ch ^ (a_row & 7))) * 16,
                      Ab + (size_t)a_row * CC + ch * 8);
        }
#pragma unroll
        for (int r3 = 0; r3 < 3; r3++) {
            int row = r3 * 64 + b_row;
#pragma unroll
            for (int i = 0; i < 2; i++) {
                int ch = b_ch0 + i;
                cpasync16(dst + ((128 + row) * 8 + (ch ^ (row & 7))) * 16,
                          BT + (size_t)row * CC + ch * 8);
            }
        }
        cp_commit();
    }

    for (int c = 0; c < 3; c++) {
        if (c + 1 < 3) {
            int k0 = (c + 1) << 6;
            uint32_t dst = sbase + ((c + 1) & 1) * PCH_PER_BUF * 16;
#pragma unroll
            for (int i = 0; i < 4; i++) {
                int ch = a_ch0 + i;
                cpasync16(dst + (a_row * 8 + (ch ^ (a_row & 7))) * 16,
                          Ab + (size_t)a_row * CC + k0 + ch * 8);
            }
#pragma unroll
            for (int r3 = 0; r3 < 3; r3++) {
                int row = r3 * 64 + b_row;
#pragma unroll
                for (int i = 0; i < 2; i++) {
                    int ch = b_ch0 + i;
                    cpasync16(dst + ((128 + row) * 8 + (ch ^ (row & 7))) * 16,
                              BT + (size_t)row * CC + k0 + ch * 8);
                }
            }
        }
        cp_commit();
        cp_wait1();
        __syncthreads();

        uint32_t buf = sbase + (c & 1) * PCH_PER_BUF * 16;
#pragma unroll
        for (int ks = 0; ks < 4; ks++) {
            uint32_t a[4];
            int achk = 2 * ks + lhi;
            ldsm_x4(buf + (a_lrow * 8 + (achk ^ a_sw)) * 16, a);
            int bchk = 2 * ks + b_chlo;
#pragma unroll
            for (int nt16 = 0; nt16 < 12; nt16++) {
                uint32_t b[4];
                ldsm_x4(buf + ((b_lbase + nt16 * 16) * 8 + (bchk ^ b_sw)) * 16, b);
                mma_bf16(acc[nt16 * 2 + 0], a, &b[0]);
                mma_bf16(acc[nt16 * 2 + 1], a, &b[2]);
            }
        }
        __syncthreads();
    }

    int lq = lane & 3;
#pragma unroll
    for (int half = 0; half < 2; half++) {
        int g = m0 + wid * 16 + (lane >> 2) + half * 8;
        int bb = g >> 14, rem = g & 16383;
        int win = rem >> 6, rr = rem & 63;
        int wy = win >> 4, wx = win & 15, ry = rr >> 3, rx = rr & 7;
        int hh = (wy * WS + ry + SHIFT) & 127;
        int ww = (wx * WS + rx + SHIFT) & 127;
        size_t ob = ((size_t)bb * LL + hh * WW_ + ww) * CC;

        float vals[48];
        float s = 0.f, s2 = 0.f;
#pragma unroll
        for (int nt = 0; nt < 24; nt++) {
            int col = nt * 8 + 2 * lq;
            float v0 = acc[nt][half * 2 + 0] + bias[col];
            float v1 = acc[nt][half * 2 + 1] + bias[col + 1];
            float2 rv = *(const float2*)(x + ob + col);
            v0 += rv.x; v1 += rv.y;
            *(float2*)(y + ob + col) = make_float2(v0, v1);
            s += v0 + v1;
            s2 += v0 * v0 + v1 * v1;
            vals[nt * 2] = v0; vals[nt * 2 + 1] = v1;
        }
        s += __shfl_xor_sync(0xFFFFFFFFu, s, 1);
        s2 += __shfl_xor_sync(0xFFFFFFFFu, s2, 1);
        s += __shfl_xor_sync(0xFFFFFFFFu, s, 2);
        s2 += __shfl_xor_sync(0xFFFFFFFFu, s2, 2);
        float mu = s * (1.0f / 192.0f);
        float rs = rsqrtf(s2 * (1.0f / 192.0f) - mu * mu + 1e-5f);
#pragma unroll
        for (int nt = 0; nt < 24; nt++) {
            int col = nt * 8 + 2 * lq;
            float2 gg = *(const float2*)(n2g + col);
            float2 bb2 = *(const float2*)(n2b + col);
            float2 o;
            o.x = (vals[nt * 2] - mu) * rs * gg.x + bb2.x;
            o.y = (vals[nt * 2 + 1] - mu) * rs * gg.y + bb2.y;
            *(__nv_bfloat162*)(ln2out + ob + col) = __float22bfloat162_rn(o);
        }
    }
}

// ---------------------------------------------------------------------------
// Tensor-core windowed attention (round-7 version, unchanged)
// ---------------------------------------------------------------------------
#define KSTR 200
#define VSTR 72
#define ATTN_SMEM ((NWIN * KSTR + CC * VSTR) * 2)

__global__ void __launch_bounds__(384) attn_kernel(
    const __nv_bfloat16* __restrict__ qkv, __nv_bfloat16* __restrict__ outp) {
    extern __shared__ __nv_bfloat16 smh[];
    __nv_bfloat16* k_s = smh;                 // [64][KSTR]
    __nv_bfloat16* vt_s = smh + NWIN * KSTR;  // [192][VSTR]

    int w = blockIdx.x;
    int tid = threadIdx.x;
    int lane = tid & 31, wid = tid >> 5;
    const __nv_bfloat16* base = qkv + (size_t)w * NWIN * 576;

    for (int idx = tid; idx < NWIN * 24; idx += 384) {
        int j = idx / 24, c = idx % 24;
        uint4 uk = *(const uint4*)(base + (size_t)j * 576 + 192 + c * 8);
        *(uint4*)(k_s + j * KSTR + c * 8) = uk;
        uint4 uv = *(const uint4*)(base + (size_t)j * 576 + 384 + c * 8);
        const unsigned short* e = (const unsigned short*)&uv;
#pragma unroll
        for (int i = 0; i < 8; i++) {
            int k = (i + lane) & 7;
            *((unsigned short*)vt_s + (c * 8 + k) * VSTR + j) = e[k];
        }
    }
    __syncthreads();

    int h = wid >> 1;
    int mbase = (wid & 1) * 32;
    int winloc = w & 255;
    int wy = winloc >> 4, wx = winloc & 15;
    int type = ((wy == 15) ? 2 : 0) | ((wx == 15) ? 1 : 0);
    const float* btab = g_bias + ((size_t)(type * HEADS + h) * NWIN) * NWIN;

    int rq = lane >> 2, cq = 2 * (lane & 3);
    int brow = ((lane >> 4) << 3) + (lane & 7);
    int bchlo = (lane >> 3) & 1;

    uint32_t a[2][2][4];
#pragma unroll
    for (int mt = 0; mt < 2; mt++)
#pragma unroll
        for (int ks = 0; ks < 2; ks++)
#pragma unroll
            for (int i = 0; i < 4; i++) {
                int row = mbase + mt * 16 + rq + (i & 1) * 8;
                int col = h * HD + ks * 16 + cq + (i >> 1) * 8;
                a[mt][ks][i] = *(const uint32_t*)(base + (size_t)row * 576 + col);
            }

    float p[2][8][4];
#pragma unroll
    for (int i = 0; i < 2; i++)
#pragma unroll
        for (int j = 0; j < 8; j++)
#pragma unroll
            for (int k = 0; k < 4; k++) p[i][j][k] = 0.f;

    uint32_t ksm = smem_u32(k_s);
#pragma unroll
    for (int kg = 0; kg < 4; kg++) {
#pragma unroll
        for (int ks = 0; ks < 2; ks++) {
            uint32_t b[4];
            uint32_t addr = ksm + ((kg * 16 + brow) * KSTR + (h * 4 + ks * 2 + bchlo) * 8) * 2;
            ldsm_x4(addr, b);
#pragma unroll
            for (int mt = 0; mt < 2; mt++) {
                mma_bf16(p[mt][kg * 2 + 0], a[mt][ks], &b[0]);
                mma_bf16(p[mt][kg * 2 + 1], a[mt][ks], &b[2]);
            }
        }
    }

    float sums[2][2];
#pragma unroll
    for (int mt = 0; mt < 2; mt++) {
#pragma unroll
        for (int rl = 0; rl < 2; rl++) {
            int r = mbase + mt * 16 + rq + rl * 8;
            const float* br_ = btab + r * NWIN;
            float m = -1e30f;
#pragma unroll
            for (int nt = 0; nt < 8; nt++) {
                float2 bv = *(const float2*)(br_ + nt * 8 + cq);
                p[mt][nt][rl * 2 + 0] += bv.x;
                p[mt][nt][rl * 2 + 1] += bv.y;
                m = fmaxf(m, fmaxf(p[mt][nt][rl * 2], p[mt][nt][rl * 2 + 1]));
            }
            m = fmaxf(m, __shfl_xor_sync(0xFFFFFFFFu, m, 1));
            m = fmaxf(m, __shfl_xor_sync(0xFFFFFFFFu, m, 2));
            float s = 0.f;
#pragma unroll
            for (int nt = 0; nt < 8; nt++) {
                float e0 = __expf(p[mt][nt][rl * 2] - m);
                float e1 = __expf(p[mt][nt][rl * 2 + 1] - m);
                p[mt][nt][rl * 2] = e0; p[mt][nt][rl * 2 + 1] = e1;
                s += e0 + e1;
            }
            s += __shfl_xor_sync(0xFFFFFFFFu, s, 1);
            s += __shfl_xor_sync(0xFFFFFFFFu, s, 2);
            sums[mt][rl] = s;
        }
    }

    uint32_t pa[2][4][4];
#pragma unroll
    for (int mt = 0; mt < 2; mt++)
#pragma unroll
        for (int s4 = 0; s4 < 4; s4++) {
            pa[mt][s4][0] = packbf2(p[mt][2 * s4][0], p[mt][2 * s4][1]);
            pa[mt][s4][1] = packbf2(p[mt][2 * s4][2], p[mt][2 * s4][3]);
            pa[mt][s4][2] = packbf2(p[mt][2 * s4 + 1][0], p[mt][2 * s4 + 1][1]);
            pa[mt][s4][3] = packbf2(p[mt][2 * s4 + 1][2], p[mt][2 * s4 + 1][3]);
        }

    float o[2][4][4];
#pragma unroll
    for (int i = 0; i < 2; i++)
#pragma unroll
        for (int j = 0; j < 4; j++)
#pragma unroll
            for (int k = 0; k < 4; k++) o[i][j][k] = 0.f;

    uint32_t vsm = smem_u32(vt_s);
#pragma unroll
    for (int s4 = 0; s4 < 4; s4++) {
#pragma unroll
        for (int n16 = 0; n16 < 2; n16++) {
            uint32_t b[4];
            uint32_t addr = vsm + ((h * HD + n16 * 16 + brow) * VSTR + (s4 * 2 + bchlo) * 8) * 2;
            ldsm_x4(addr, b);
#pragma unroll
            for (int mt = 0; mt < 2; mt++) {
                mma_bf16(o[mt][n16 * 2 + 0], pa[mt][s4], &b[0]);
                mma_bf16(o[mt][n16 * 2 + 1], pa[mt][s4], &b[2]);
            }
        }
    }

#pragma unroll
    for (int mt = 0; mt < 2; mt++) {
        float i0 = 1.0f / sums[mt][0];
        float i1 = 1.0f / sums[mt][1];
        int r0 = mbase + mt * 16 + rq;
        __nv_bfloat16* op0 = outp + (size_t)(w * NWIN + r0) * CC + h * HD;
        __nv_bfloat16* op1 = op0 + 8 * CC;
#pragma unroll
        for (int nt = 0; nt < 4; nt++) {
            *(__nv_bfloat162*)(op0 + nt * 8 + cq) =
                __float22bfloat162_rn(make_float2(o[mt][nt][0] * i0, o[mt][nt][1] * i0));
            *(__nv_bfloat162*)(op1 + nt * 8 + cq) =
                __float22bfloat162_rn(make_float2(o[mt][nt][2] * i1, o[mt][nt][3] * i1));
        }
    }
}

// ---------------------------------------------------------------------------
// Launch
// ---------------------------------------------------------------------------
extern "C" void kernel_launch(void* const* d_in, const int* in_sizes, int n_in,
                              void* d_out, int out_size) {
    const float* x      = (const float*)d_in[0];
    const float* n1_g   = (const float*)d_in[4];
    const float* n1_b   = (const float*)d_in[5];
    const float* qkv_w  = (const float*)d_in[6];
    const float* qkv_b  = (const float*)d_in[7];
    const float* proj_w = (const float*)d_in[8];
    const float* proj_b = (const float*)d_in[9];
    const float* pp_w   = (const float*)d_in[10];
    const float* pp_b   = (const float*)d_in[11];
    const float* p1_g   = (const float*)d_in[12];
    const float* p1_b   = (const float*)d_in[13];
    const float* p1_w   = (const float*)d_in[14];
    const float* p1_bi  = (const float*)d_in[15];
    const float* p2_g   = (const float*)d_in[16];
    const float* p2_b   = (const float*)d_in[17];
    const float* p2_w   = (const float*)d_in[18];
    const float* p2_bi  = (const float*)d_in[19];
    const float* p3_g   = (const float*)d_in[20];
    const float* p3_b   = (const float*)d_in[21];
    const float* p3_w   = (const float*)d_in[22];
    const float* p3_bi  = (const float*)d_in[23];
    const float* n2_g   = (const float*)d_in[24];
    const float* n2_b   = (const float*)d_in[25];
    const float* fc1_w  = (const float*)d_in[26];
    const float* fc1_b  = (const float*)d_in[27];
    const float* fc2_w  = (const float*)d_in[28];
    const float* fc2_b  = (const float*)d_in[29];
    float* out = (float*)d_out;

    __nv_bfloat16 *xw, *qkv, *attn, *ln2, *hid;
    __nv_bfloat16 *wt_qkv, *wt_proj, *wt_fc1, *wt_fc2;
    cudaGetSymbolAddress((void**)&xw,   gb_xw);
    cudaGetSymbolAddress((void**)&qkv,  gb_qkv);
    cudaGetSymbolAddress((void**)&attn, gb_attn);
    cudaGetSymbolAddress((void**)&ln2,  gb_ln2);
    cudaGetSymbolAddress((void**)&hid,  gb_hid);
    cudaGetSymbolAddress((void**)&wt_qkv,  gb_wt_qkv);
    cudaGetSymbolAddress((void**)&wt_proj, gb_wt_proj);
    cudaGetSymbolAddress((void**)&wt_fc1,  gb_wt_fc1);
    cudaGetSymbolAddress((void**)&wt_fc2,  gb_wt_fc2);

    static bool attr_set = false;
    if (!attr_set) {
        cudaFuncSetAttribute(attn_kernel, cudaFuncAttributeMaxDynamicSharedMemorySize,
                             ATTN_SMEM);
        cudaFuncSetAttribute(gemm_proj_ln, cudaFuncAttributeMaxDynamicSharedMemorySize,
                             PROJ_SMEM);
        cudaFuncSetAttribute(gemm_mma<0>, cudaFuncAttributeMaxDynamicSharedMemorySize, GEMM_SMEM);
        cudaFuncSetAttribute(gemm_mma<1>, cudaFuncAttributeMaxDynamicSharedMemorySize, GEMM_SMEM);
        cudaFuncSetAttribute(gemm_mma<3>, cudaFuncAttributeMaxDynamicSharedMemorySize, GEMM_SMEM);
        attr_set = true;
    }

    // 0. weight transposes
    transpose_all<<<(TW_TOTAL + 255) / 256, 256>>>(qkv_w, proj_w, fc1_w, fc2_w);

    // 1. position-bias MLP + bias table
    pos_mlp_kernel<<<1, 256>>>(pp_w, pp_b, p1_g, p1_b, p1_w, p1_bi,
                               p2_g, p2_b, p2_w, p2_bi, p3_g, p3_b, p3_w, p3_bi);
    bias_build<<<(4 * HEADS * NWIN * NWIN + 255) / 256, 256>>>();

    // 2. LN1 + shift + window partition -> bf16
    ln1_kernel<<<MROWS / 8, 256>>>(x, xw, n1_g, n1_b);

    // 3. QKV GEMM -> bf16 (Q pre-scaled)
    gemm_mma<0><<<dim3(576 / 64, MROWS / 256), 256, GEMM_SMEM>>>(xw, wt_qkv, qkv_b, nullptr, qkv, CC, 576);

    // 4. tensor-core attention -> bf16
    attn_kernel<<<NWINDOWS, 384, ATTN_SMEM>>>(qkv, attn);

    // 5. proj + scatter + residual + LN2 (fused)
    gemm_proj_ln<<<MROWS / 128, 256, PROJ_SMEM>>>(attn, wt_proj, proj_b, x, out, ln2, n2_g, n2_b);

    // 6. FC1 + GELU -> bf16
    gemm_mma<1><<<dim3(HIDDEN / 64, MROWS / 256), 256, GEMM_SMEM>>>(ln2, wt_fc1, fc1_b, nullptr, hid, CC, HIDDEN);

    // 7. FC2 + residual -> fp32 out
    gemm_mma<3><<<dim3(CC / 64, MROWS / 256), 256, GEMM_SMEM>>>(hid, wt_fc2, fc2_b, out, out, HIDDEN, CC);
}

// round 9
// speedup vs baseline: 1.0502x; 1.0502x over previous
#include <cuda_runtime.h>
#include <cuda_bf16.h>
#include <math.h>
#include <stdint.h>

// ---------------------------------------------------------------------------
// Problem constants
// ---------------------------------------------------------------------------
#define BATCH   8
#define HH      128
#define WW_     128
#define LL      (HH*WW_)
#define CC      192
#define HEADS   6
#define HD      32
#define WS      8
#define NWIN    64
#define SHIFT   4
#define HIDDEN  768
#define MROWS   (BATCH*LL)                 // 131072
#define NWINDOWS (BATCH*(HH/WS)*(WW_/WS))  // 2048
#define POS_DIM 12
#define POS_TAB 225
#define QSCALE  0.17677669529663687f

// ---------------------------------------------------------------------------
// Device scratch
// ---------------------------------------------------------------------------
__device__ __nv_bfloat16 gb_xw[(size_t)MROWS * CC];
__device__ __nv_bfloat16 gb_qkv[(size_t)MROWS * 3 * CC];
__device__ __nv_bfloat16 gb_attn[(size_t)MROWS * CC];
__device__ __nv_bfloat16 gb_ln2[(size_t)MROWS * CC];
__device__ __nv_bfloat16 gb_hid[(size_t)MROWS * HIDDEN];
__device__ float g_pos[POS_TAB * HEADS];
__device__ float g_bias[4 * HEADS * NWIN * NWIN];   // [type][h][r][j]
__device__ __nv_bfloat16 gb_wt_qkv[3 * CC * CC];
__device__ __nv_bfloat16 gb_wt_proj[CC * CC];
__device__ __nv_bfloat16 gb_wt_fc1[HIDDEN * CC];
__device__ __nv_bfloat16 gb_wt_fc2[CC * HIDDEN];

// ---------------------------------------------------------------------------
// Helpers
// ---------------------------------------------------------------------------
__device__ __forceinline__ uint32_t smem_u32(const void* p) {
    uint32_t a;
    asm("{ .reg .u64 t; cvta.to.shared.u64 t, %1; cvt.u32.u64 %0, t; }" : "=r"(a) : "l"(p));
    return a;
}
__device__ __forceinline__ void cpasync16(uint32_t s, const void* g) {
    asm volatile("cp.async.cg.shared.global [%0], [%1], 16;" :: "r"(s), "l"(g));
}
__device__ __forceinline__ void cp_commit() {
    asm volatile("cp.async.commit_group;" ::: "memory");
}
__device__ __forceinline__ void cp_wait1() {
    asm volatile("cp.async.wait_group 1;" ::: "memory");
}
__device__ __forceinline__ void ldsm_x4(uint32_t addr, uint32_t* r) {
    asm volatile("ldmatrix.sync.aligned.m8n8.x4.shared.b16 {%0,%1,%2,%3}, [%4];"
                 : "=r"(r[0]), "=r"(r[1]), "=r"(r[2]), "=r"(r[3]) : "r"(addr));
}
__device__ __forceinline__ void mma_bf16(float* d, const uint32_t* a, const uint32_t* b) {
    asm volatile(
        "mma.sync.aligned.m16n8k16.row.col.f32.bf16.bf16.f32 "
        "{%0,%1,%2,%3}, {%4,%5,%6,%7}, {%8,%9}, {%0,%1,%2,%3};"
        : "+f"(d[0]), "+f"(d[1]), "+f"(d[2]), "+f"(d[3])
        : "r"(a[0]), "r"(a[1]), "r"(a[2]), "r"(a[3]), "r"(b[0]), "r"(b[1]));
}
__device__ __forceinline__ uint32_t packbf2(float x, float y) {
    __nv_bfloat162 t = __float22bfloat162_rn(make_float2(x, y));
    return *(uint32_t*)&t;
}
__device__ __forceinline__ float gelu_exact(float x) {
    return 0.5f * x * (1.0f + erff(x * 0.7071067811865476f));
}

// ---------------------------------------------------------------------------
// Combined weight transpose
// ---------------------------------------------------------------------------
#define TW_QKV (3*CC*CC)
#define TW_PROJ (CC*CC)
#define TW_FC1 (CC*HIDDEN)
#define TW_FC2 (HIDDEN*CC)
#define TW_TOTAL (TW_QKV + TW_PROJ + TW_FC1 + TW_FC2)

__global__ void transpose_all(const float* __restrict__ qkv_w, const float* __restrict__ proj_w,
                              const float* __restrict__ fc1_w, const float* __restrict__ fc2_w) {
    int i = blockIdx.x * 256 + threadIdx.x;
    if (i >= TW_TOTAL) return;
    const float* w; __nv_bfloat16* wt; int K, N, off;
    if (i < TW_QKV) { w = qkv_w; wt = gb_wt_qkv; K = CC; N = 3 * CC; off = i; }
    else if (i < TW_QKV + TW_PROJ) { w = proj_w; wt = gb_wt_proj; K = CC; N = CC; off = i - TW_QKV; }
    else if (i < TW_QKV + TW_PROJ + TW_FC1) { w = fc1_w; wt = gb_wt_fc1; K = CC; N = HIDDEN; off = i - TW_QKV - TW_PROJ; }
    else { w = fc2_w; wt = gb_wt_fc2; K = HIDDEN; N = CC; off = i - TW_QKV - TW_PROJ - TW_FC1; }
    int k = off / N, n = off % N;
    wt[(size_t)n * K + k] = __float2bfloat16(w[off]);
}

// ---------------------------------------------------------------------------
// Position-bias MLP
// ---------------------------------------------------------------------------
__device__ __forceinline__ void ln_relu12(const float* p, float* q,
                                          const float* g, const float* b) {
    float s = 0.f, s2 = 0.f;
#pragma unroll
    for (int i = 0; i < POS_DIM; i++) { s += p[i]; s2 += p[i] * p[i]; }
    float mu = s / 12.0f;
    float var = s2 / 12.0f - mu * mu;
    float rs = rsqrtf(var + 1e-5f);
#pragma unroll
    for (int i = 0; i < POS_DIM; i++) q[i] = fmaxf((p[i] - mu) * rs * g[i] + b[i], 0.0f);
}

__global__ void pos_mlp_kernel(
    const float* __restrict__ pp_w, const float* __restrict__ pp_b,
    const float* __restrict__ p1_g, const float* __restrict__ p1_b,
    const float* __restrict__ p1_w, const float* __restrict__ p1_bias,
    const float* __restrict__ p2_g, const float* __restrict__ p2_b,
    const float* __restrict__ p2_w, const float* __restrict__ p2_bias,
    const float* __restrict__ p3_g, const float* __restrict__ p3_b,
    const float* __restrict__ p3_w, const float* __restrict__ p3_bias) {
    int t = blockIdx.x * blockDim.x + threadIdx.x;
    if (t >= POS_TAB) return;
    float bh = (float)(t / 15 - 7), bw = (float)(t % 15 - 7);
    float p[POS_DIM], q[POS_DIM];
#pragma unroll
    for (int j = 0; j < POS_DIM; j++) p[j] = bh * pp_w[j] + bw * pp_w[POS_DIM + j] + pp_b[j];
    ln_relu12(p, q, p1_g, p1_b);
#pragma unroll
    for (int j = 0; j < POS_DIM; j++) {
        float s = p1_bias[j];
#pragma unroll
        for (int i = 0; i < POS_DIM; i++) s += q[i] * p1_w[i * POS_DIM + j];
        p[j] = s;
    }
    ln_relu12(p, q, p2_g, p2_b);
#pragma unroll
    for (int j = 0; j < POS_DIM; j++) {
        float s = p2_bias[j];
#pragma unroll
        for (int i = 0; i < POS_DIM; i++) s += q[i] * p2_w[i * POS_DIM + j];
        p[j] = s;
    }
    ln_relu12(p, q, p3_g, p3_b);
#pragma unroll
    for (int h = 0; h < HEADS; h++) {
        float s = p3_bias[h];
#pragma unroll
        for (int i = 0; i < POS_DIM; i++) s += q[i] * p3_w[i * HEADS + h];
        g_pos[t * HEADS + h] = s;
    }
}

// ---------------------------------------------------------------------------
// Bias table: [type][h][r][j]
// ---------------------------------------------------------------------------
__global__ void bias_build() {
    int idx = blockIdx.x * 256 + threadIdx.x;
    if (idx >= 4 * HEADS * NWIN * NWIN) return;
    int j = idx & 63;
    int r = (idx >> 6) & 63;
    int h = (idx >> 12) % HEADS;
    int t = idx / (HEADS * NWIN * NWIN);
    int ry = r >> 3, rx = r & 7, jy = j >> 3, jx = j & 7;
    float bias = g_pos[(((ry - jy + 7) * 15) + (rx - jx + 7)) * HEADS + h];
    int lhr = (t & 2) ? (ry < (WS - SHIFT) ? 1 : 2) : 0;
    int lhj = (t & 2) ? (jy < (WS - SHIFT) ? 1 : 2) : 0;
    int lwr = (t & 1) ? (rx < (WS - SHIFT) ? 1 : 2) : 0;
    int lwj = (t & 1) ? (jx < (WS - SHIFT) ? 1 : 2) : 0;
    if (lhr != lhj || lwr != lwj) bias -= 100.0f;
    g_bias[idx] = bias;
}

// ---------------------------------------------------------------------------
// LayerNorm1: warp per row, fp32 in -> bf16 out, shift+window gather
// ---------------------------------------------------------------------------
__global__ void __launch_bounds__(256) ln1_kernel(
    const float* __restrict__ in, __nv_bfloat16* __restrict__ out,
    const float* __restrict__ gamma, const float* __restrict__ beta) {
    int warp = threadIdx.x >> 5, lane = threadIdx.x & 31;
    int row = blockIdx.x * 8 + warp;
    int bb = row >> 14, rem = row & 16383;
    int win = rem >> 6, r = rem & 63;
    int wy = win >> 4, wx = win & 15, ry = r >> 3, rx = r & 7;
    int hh = (wy * WS + ry + SHIFT) & 127;
    int ww = (wx * WS + rx + SHIFT) & 127;
    size_t src = (size_t)bb * LL + hh * WW_ + ww;

    const float* p = in + src * CC;
    float v[6], s = 0.f, s2 = 0.f;
#pragma unroll
    for (int k = 0; k < 6; k++) { v[k] = p[lane + 32 * k]; s += v[k]; s2 += v[k] * v[k]; }
#pragma unroll
    for (int o = 16; o > 0; o >>= 1) {
        s += __shfl_xor_sync(0xFFFFFFFFu, s, o);
        s2 += __shfl_xor_sync(0xFFFFFFFFu, s2, o);
    }
    float mu = s * (1.0f / 192.0f);
    float rs = rsqrtf(s2 * (1.0f / 192.0f) - mu * mu + 1e-5f);
    __nv_bfloat16* q = out + (size_t)row * CC;
#pragma unroll
    for (int k = 0; k < 6; k++) {
        int c = lane + 32 * k;
        q[c] = __float2bfloat16((v[k] - mu) * rs * gamma[c] + beta[c]);
    }
}

// ---------------------------------------------------------------------------
// bf16 mma GEMM v4: 128x64 CTA tile, 4 warps (128 thr), warp tile 32x64.
// BK=64, static 48KB smem, XOR-swizzled 16B chunks, double buffered.
// Per ks step per warp: 2 A-ldsm + 4 B-ldsm -> 16 mma.
// EPI 0: +bias, Q-scale cols<192 -> bf16   1: gelu(+bias) -> bf16
// ---------------------------------------------------------------------------
#define CH_PER_BUF (192 * 8)

template <int EPI>
__global__ void __launch_bounds__(128) gemm_mma(
    const __nv_bfloat16* __restrict__ A, const __nv_bfloat16* __restrict__ BT,
    const float* __restrict__ bias, void* __restrict__ outv, int K, int NOUT) {
    __shared__ __align__(16) uint4 smq[2 * CH_PER_BUF];
    uint32_t sbase = smem_u32(smq);
    int tid = threadIdx.x;
    int wid = tid >> 5, lane = tid & 31;
    int m0 = blockIdx.y * 128, n0 = blockIdx.x * 64;
    const __nv_bfloat16* Ab = A + (size_t)m0 * K;
    const __nv_bfloat16* Bb = BT + (size_t)n0 * K;
    int NCH = K >> 6;

    float acc[2][8][4];
#pragma unroll
    for (int i = 0; i < 2; i++)
#pragma unroll
        for (int j = 0; j < 8; j++)
#pragma unroll
            for (int k = 0; k < 4; k++) acc[i][j][k] = 0.f;

    // cp.async: A row = tid (8 chunks); B row = 128 + (tid>>1), 4 chunks
    int b_row = tid >> 1;
    int b_ch0 = (tid & 1) * 4;

    int l15 = lane & 15, lhi = lane >> 4;
    int a_lrow = wid * 32 + l15;
    int a_sw = l15 & 7;
    int b_lrow = 128 + (lhi << 3) + (lane & 7);
    int b_sw = lane & 7;
    int b_chlo = (lane >> 3) & 1;

    {
        uint32_t dst = sbase;
#pragma unroll
        for (int ch = 0; ch < 8; ch++) {
            cpasync16(dst + (tid * 8 + (ch ^ (tid & 7))) * 16,
                      Ab + (size_t)tid * K + ch * 8);
        }
#pragma unroll
        for (int i = 0; i < 4; i++) {
            int ch = b_ch0 + i;
            cpasync16(dst + ((128 + b_row) * 8 + (ch ^ (b_row & 7))) * 16,
                      Bb + (size_t)b_row * K + ch * 8);
        }
        cp_commit();
    }

    for (int c = 0; c < NCH; c++) {
        if (c + 1 < NCH) {
            int k0 = (c + 1) << 6;
            uint32_t dst = sbase + ((c + 1) & 1) * CH_PER_BUF * 16;
#pragma unroll
            for (int ch = 0; ch < 8; ch++) {
                cpasync16(dst + (tid * 8 + (ch ^ (tid & 7))) * 16,
                          Ab + (size_t)tid * K + k0 + ch * 8);
            }
#pragma unroll
            for (int i = 0; i < 4; i++) {
                int ch = b_ch0 + i;
                cpasync16(dst + ((128 + b_row) * 8 + (ch ^ (b_row & 7))) * 16,
                          Bb + (size_t)b_row * K + k0 + ch * 8);
            }
        }
        cp_commit();
        cp_wait1();
        __syncthreads();

        uint32_t buf = sbase + (c & 1) * CH_PER_BUF * 16;
#pragma unroll
        for (int ks = 0; ks < 4; ks++) {
            uint32_t a[2][4], b[4][4];
            int achk = 2 * ks + lhi;
#pragma unroll
            for (int mt = 0; mt < 2; mt++) {
                uint32_t idx = (a_lrow + mt * 16) * 8 + (achk ^ a_sw);
                ldsm_x4(buf + idx * 16, a[mt]);
            }
            int bchk = 2 * ks + b_chlo;
#pragma unroll
            for (int nt16 = 0; nt16 < 4; nt16++) {
                uint32_t idx = (b_lrow + nt16 * 16) * 8 + (bchk ^ b_sw);
                ldsm_x4(buf + idx * 16, b[nt16]);
            }
#pragma unroll
            for (int mt = 0; mt < 2; mt++) {
#pragma unroll
                for (int nt16 = 0; nt16 < 4; nt16++) {
                    mma_bf16(acc[mt][nt16 * 2 + 0], a[mt], &b[nt16][0]);
                    mma_bf16(acc[mt][nt16 * 2 + 1], a[mt], &b[nt16][2]);
                }
            }
        }
        __syncthreads();
    }

#pragma unroll
    for (int mt = 0; mt < 2; mt++) {
        int g0 = m0 + wid * 32 + mt * 16 + (lane >> 2);
        int g1 = g0 + 8;
        size_t ob0 = (size_t)g0 * NOUT;
        size_t ob1 = (size_t)g1 * NOUT;
#pragma unroll
        for (int nt = 0; nt < 8; nt++) {
            int col = n0 + nt * 8 + 2 * (lane & 3);
            float b0 = bias[col], b1 = bias[col + 1];
            float2 v0 = make_float2(acc[mt][nt][0] + b0, acc[mt][nt][1] + b1);
            float2 v1 = make_float2(acc[mt][nt][2] + b0, acc[mt][nt][3] + b1);
            if (EPI == 0) {
                float sc = (col < CC) ? QSCALE : 1.0f;
                v0.x *= sc; v0.y *= sc; v1.x *= sc; v1.y *= sc;
            }
            if (EPI == 1) {
                v0.x = gelu_exact(v0.x); v0.y = gelu_exact(v0.y);
                v1.x = gelu_exact(v1.x); v1.y = gelu_exact(v1.y);
            }
            __nv_bfloat16* out = (__nv_bfloat16*)outv;
            *(__nv_bfloat162*)(out + ob0 + col) = __float22bfloat162_rn(v0);
            *(__nv_bfloat162*)(out + ob1 + col) = __float22bfloat162_rn(v1);
        }
    }
}

// ---------------------------------------------------------------------------
// FC2 GEMM: full-row tile 128x192, K=768. hid read ONCE (no N-tiling).
// +bias +res(y) -> fp32 out. Proj-style mainloop, 8 warps x 16 rows.
// ---------------------------------------------------------------------------
#define PCH_PER_BUF (320 * 8)
#define PROJ_SMEM (2 * PCH_PER_BUF * 16)

__global__ void __launch_bounds__(256) gemm_fc2(
    const __nv_bfloat16* __restrict__ A, const __nv_bfloat16* __restrict__ BT,
    const float* __restrict__ bias, const float* __restrict__ res,
    float* __restrict__ out) {
    extern __shared__ __align__(16) uint4 psm[];
    uint32_t sbase = smem_u32(psm);
    int tid = threadIdx.x;
    int wid = tid >> 5, lane = tid & 31;
    int m0 = blockIdx.x * 128;
    const int K = HIDDEN;
    const __nv_bfloat16* Ab = A + (size_t)m0 * K;

    float acc[24][4];
#pragma unroll
    for (int j = 0; j < 24; j++)
#pragma unroll
        for (int k = 0; k < 4; k++) acc[j][k] = 0.f;

    int a_row = tid >> 1;
    int a_ch0 = (tid & 1) * 4;
    int b_row = tid >> 2;
    int b_ch0 = (tid & 3) * 2;

    int l15 = lane & 15, lhi = lane >> 4;
    int a_lrow = wid * 16 + l15;
    int a_sw = l15 & 7;
    int b_lbase = 128 + (lhi << 3) + (lane & 7);
    int b_sw = lane & 7;
    int b_chlo = (lane >> 3) & 1;

    {
        uint32_t dst = sbase;
#pragma unroll
        for (int i = 0; i < 4; i++) {
            int ch = a_ch0 + i;
            cpasync16(dst + (a_row * 8 + (ch ^ (a_row & 7))) * 16,
                      Ab + (size_t)a_row * K + ch * 8);
        }
#pragma unroll
        for (int r3 = 0; r3 < 3; r3++) {
            int row = r3 * 64 + b_row;
#pragma unroll
            for (int i = 0; i < 2; i++) {
                int ch = b_ch0 + i;
                cpasync16(dst + ((128 + row) * 8 + (ch ^ (row & 7))) * 16,
                          BT + (size_t)row * K + ch * 8);
            }
        }
        cp_commit();
    }

    const int NCH = K >> 6;  // 12
    for (int c = 0; c < NCH; c++) {
        if (c + 1 < NCH) {
            int k0 = (c + 1) << 6;
            uint32_t dst = sbase + ((c + 1) & 1) * PCH_PER_BUF * 16;
#pragma unroll
            for (int i = 0; i < 4; i++) {
                int ch = a_ch0 + i;
                cpasync16(dst + (a_row * 8 + (ch ^ (a_row & 7))) * 16,
                          Ab + (size_t)a_row * K + k0 + ch * 8);
            }
#pragma unroll
            for (int r3 = 0; r3 < 3; r3++) {
                int row = r3 * 64 + b_row;
#pragma unroll
                for (int i = 0; i < 2; i++) {
                    int ch = b_ch0 + i;
                    cpasync16(dst + ((128 + row) * 8 + (ch ^ (row & 7))) * 16,
                              BT + (size_t)row * K + k0 + ch * 8);
                }
            }
        }
        cp_commit();
        cp_wait1();
        __syncthreads();

        uint32_t buf = sbase + (c & 1) * PCH_PER_BUF * 16;
#pragma unroll
        for (int ks = 0; ks < 4; ks++) {
            uint32_t a[4];
            int achk = 2 * ks + lhi;
            ldsm_x4(buf + (a_lrow * 8 + (achk ^ a_sw)) * 16, a);
            int bchk = 2 * ks + b_chlo;
#pragma unroll
            for (int nt16 = 0; nt16 < 12; nt16++) {
                uint32_t b[4];
                ldsm_x4(buf + ((b_lbase + nt16 * 16) * 8 + (bchk ^ b_sw)) * 16, b);
                mma_bf16(acc[nt16 * 2 + 0], a, &b[0]);
                mma_bf16(acc[nt16 * 2 + 1], a, &b[2]);
            }
        }
        __syncthreads();
    }

    int lq = lane & 3;
#pragma unroll
    for (int half = 0; half < 2; half++) {
        int g = m0 + wid * 16 + (lane >> 2) + half * 8;
        size_t ob = (size_t)g * CC;
#pragma unroll
        for (int nt = 0; nt < 24; nt++) {
            int col = nt * 8 + 2 * lq;
            float v0 = acc[nt][half * 2 + 0] + bias[col];
            float v1 = acc[nt][half * 2 + 1] + bias[col + 1];
            float2 rv = *(const float2*)(res + ob + col);
            v0 += rv.x; v1 += rv.y;
            *(float2*)(out + ob + col) = make_float2(v0, v1);
        }
    }
}

// ---------------------------------------------------------------------------
// Proj GEMM + scatter + residual + LN2 (fused) — unchanged (round 6/7)
// ---------------------------------------------------------------------------
__global__ void __launch_bounds__(256) gemm_proj_ln(
    const __nv_bfloat16* __restrict__ A, const __nv_bfloat16* __restrict__ BT,
    const float* __restrict__ bias, const float* __restrict__ x,
    float* __restrict__ y, __nv_bfloat16* __restrict__ ln2out,
    const float* __restrict__ n2g, const float* __restrict__ n2b) {
    extern __shared__ __align__(16) uint4 psm[];
    uint32_t sbase = smem_u32(psm);
    int tid = threadIdx.x;
    int wid = tid >> 5, lane = tid & 31;
    int m0 = blockIdx.x * 128;
    const __nv_bfloat16* Ab = A + (size_t)m0 * CC;

    float acc[24][4];
#pragma unroll
    for (int j = 0; j < 24; j++)
#pragma unroll
        for (int k = 0; k < 4; k++) acc[j][k] = 0.f;

    int a_row = tid >> 1;
    int a_ch0 = (tid & 1) * 4;
    int b_row = tid >> 2;
    int b_ch0 = (tid & 3) * 2;

    int l15 = lane & 15, lhi = lane >> 4;
    int a_lrow = wid * 16 + l15;
    int a_sw = l15 & 7;
    int b_lbase = 128 + (lhi << 3) + (lane & 7);
    int b_sw = lane & 7;
    int b_chlo = (lane >> 3) & 1;

    {
        uint32_t dst = sbase;
#pragma unroll
        for (int i = 0; i < 4; i++) {
            int ch = a_ch0 + i;
            cpasync16(dst + (a_row * 8 + (ch ^ (a_row & 7))) * 16,
                      Ab + (size_t)a_row * CC + ch * 8);
        }
#pragma unroll
        for (int r3 = 0; r3 < 3; r3++) {
            int row = r3 * 64 + b_row;
#pragma unroll
            for (int i = 0; i < 2; i++) {
                int ch = b_ch0 + i;
                cpasync16(dst + ((128 + row) * 8 + (ch ^ (row & 7))) * 16,
                          BT + (size_t)row * CC + ch * 8);
            }
        }
        cp_commit();
    }

    for (int c = 0; c < 3; c++) {
        if (c + 1 < 3) {
            int k0 = (c + 1) << 6;
            uint32_t dst = sbase + ((c + 1) & 1) * PCH_PER_BUF * 16;
#pragma unroll
            for (int i = 0; i < 4; i++) {
                int ch = a_ch0 + i;
                cpasync16(dst + (a_row * 8 + (ch ^ (a_row & 7))) * 16,
                          Ab + (size_t)a_row * CC + k0 + ch * 8);
            }
#pragma unroll
            for (int r3 = 0; r3 < 3; r3++) {
                int row = r3 * 64 + b_row;
#pragma unroll
                for (int i = 0; i < 2; i++) {
                    int ch = b_ch0 + i;
                    cpasync16(dst + ((128 + row) * 8 + (ch ^ (row & 7))) * 16,
                              BT + (size_t)row * CC + k0 + ch * 8);
                }
            }
        }
        cp_commit();
        cp_wait1();
        __syncthreads();

        uint32_t buf = sbase + (c & 1) * PCH_PER_BUF * 16;
#pragma unroll
        for (int ks = 0; ks < 4; ks++) {
            uint32_t a[4];
            int achk = 2 * ks + lhi;
            ldsm_x4(buf + (a_lrow * 8 + (achk ^ a_sw)) * 16, a);
            int bchk = 2 * ks + b_chlo;
#pragma unroll
            for (int nt16 = 0; nt16 < 12; nt16++) {
                uint32_t b[4];
                ldsm_x4(buf + ((b_lbase + nt16 * 16) * 8 + (bchk ^ b_sw)) * 16, b);
                mma_bf16(acc[nt16 * 2 + 0], a, &b[0]);
                mma_bf16(acc[nt16 * 2 + 1], a, &b[2]);
            }
        }
        __syncthreads();
    }

    int lq = lane & 3;
#pragma unroll
    for (int half = 0; half < 2; half++) {
        int g = m0 + wid * 16 + (lane >> 2) + half * 8;
        int bb = g >> 14, rem = g & 16383;
        int win = rem >> 6, rr = rem & 63;
        int wy = win >> 4, wx = win & 15, ry = rr >> 3, rx = rr & 7;
        int hh = (wy * WS + ry + SHIFT) & 127;
        int ww = (wx * WS + rx + SHIFT) & 127;
        size_t ob = ((size_t)bb * LL + hh * WW_ + ww) * CC;

        float vals[48];
        float s = 0.f, s2 = 0.f;
#pragma unroll
        for (int nt = 0; nt < 24; nt++) {
            int col = nt * 8 + 2 * lq;
            float v0 = acc[nt][half * 2 + 0] + bias[col];
            float v1 = acc[nt][half * 2 + 1] + bias[col + 1];
            float2 rv = *(const float2*)(x + ob + col);
            v0 += rv.x; v1 += rv.y;
            *(float2*)(y + ob + col) = make_float2(v0, v1);
            s += v0 + v1;
            s2 += v0 * v0 + v1 * v1;
            vals[nt * 2] = v0; vals[nt * 2 + 1] = v1;
        }
        s += __shfl_xor_sync(0xFFFFFFFFu, s, 1);
        s2 += __shfl_xor_sync(0xFFFFFFFFu, s2, 1);
        s += __shfl_xor_sync(0xFFFFFFFFu, s, 2);
        s2 += __shfl_xor_sync(0xFFFFFFFFu, s2, 2);
        float mu = s * (1.0f / 192.0f);
        float rs = rsqrtf(s2 * (1.0f / 192.0f) - mu * mu + 1e-5f);
#pragma unroll
        for (int nt = 0; nt < 24; nt++) {
            int col = nt * 8 + 2 * lq;
            float2 gg = *(const float2*)(n2g + col);
            float2 bb2 = *(const float2*)(n2b + col);
            float2 o;
            o.x = (vals[nt * 2] - mu) * rs * gg.x + bb2.x;
            o.y = (vals[nt * 2 + 1] - mu) * rs * gg.y + bb2.y;
            *(__nv_bfloat162*)(ln2out + ob + col) = __float22bfloat162_rn(o);
        }
    }
}

// ---------------------------------------------------------------------------
// Tensor-core windowed attention (round-7 version, unchanged)
// ---------------------------------------------------------------------------
#define KSTR 200
#define VSTR 72
#define ATTN_SMEM ((NWIN * KSTR + CC * VSTR) * 2)

__global__ void __launch_bounds__(384) attn_kernel(
    const __nv_bfloat16* __restrict__ qkv, __nv_bfloat16* __restrict__ outp) {
    extern __shared__ __nv_bfloat16 smh[];
    __nv_bfloat16* k_s = smh;
    __nv_bfloat16* vt_s = smh + NWIN * KSTR;

    int w = blockIdx.x;
    int tid = threadIdx.x;
    int lane = tid & 31, wid = tid >> 5;
    const __nv_bfloat16* base = qkv + (size_t)w * NWIN * 576;

    for (int idx = tid; idx < NWIN * 24; idx += 384) {
        int j = idx / 24, c = idx % 24;
        uint4 uk = *(const uint4*)(base + (size_t)j * 576 + 192 + c * 8);
        *(uint4*)(k_s + j * KSTR + c * 8) = uk;
        uint4 uv = *(const uint4*)(base + (size_t)j * 576 + 384 + c * 8);
        const unsigned short* e = (const unsigned short*)&uv;
#pragma unroll
        for (int i = 0; i < 8; i++) {
            int k = (i + lane) & 7;
            *((unsigned short*)vt_s + (c * 8 + k) * VSTR + j) = e[k];
        }
    }
    __syncthreads();

    int h = wid >> 1;
    int mbase = (wid & 1) * 32;
    int winloc = w & 255;
    int wy = winloc >> 4, wx = winloc & 15;
    int type = ((wy == 15) ? 2 : 0) | ((wx == 15) ? 1 : 0);
    const float* btab = g_bias + ((size_t)(type * HEADS + h) * NWIN) * NWIN;

    int rq = lane >> 2, cq = 2 * (lane & 3);
    int brow = ((lane >> 4) << 3) + (lane & 7);
    int bchlo = (lane >> 3) & 1;

    uint32_t a[2][2][4];
#pragma unroll
    for (int mt = 0; mt < 2; mt++)
#pragma unroll
        for (int ks = 0; ks < 2; ks++)
#pragma unroll
            for (int i = 0; i < 4; i++) {
                int row = mbase + mt * 16 + rq + (i & 1) * 8;
                int col = h * HD + ks * 16 + cq + (i >> 1) * 8;
                a[mt][ks][i] = *(const uint32_t*)(base + (size_t)row * 576 + col);
            }

    float p[2][8][4];
#pragma unroll
    for (int i = 0; i < 2; i++)
#pragma unroll
        for (int j = 0; j < 8; j++)
#pragma unroll
            for (int k = 0; k < 4; k++) p[i][j][k] = 0.f;

    uint32_t ksm = smem_u32(k_s);
#pragma unroll
    for (int kg = 0; kg < 4; kg++) {
#pragma unroll
        for (int ks = 0; ks < 2; ks++) {
            uint32_t b[4];
            uint32_t addr = ksm + ((kg * 16 + brow) * KSTR + (h * 4 + ks * 2 + bchlo) * 8) * 2;
            ldsm_x4(addr, b);
#pragma unroll
            for (int mt = 0; mt < 2; mt++) {
                mma_bf16(p[mt][kg * 2 + 0], a[mt][ks], &b[0]);
                mma_bf16(p[mt][kg * 2 + 1], a[mt][ks], &b[2]);
            }
        }
    }

    float sums[2][2];
#pragma unroll
    for (int mt = 0; mt < 2; mt++) {
#pragma unroll
        for (int rl = 0; rl < 2; rl++) {
            int r = mbase + mt * 16 + rq + rl * 8;
            const float* br_ = btab + r * NWIN;
            float m = -1e30f;
#pragma unroll
            for (int nt = 0; nt < 8; nt++) {
                float2 bv = *(const float2*)(br_ + nt * 8 + cq);
                p[mt][nt][rl * 2 + 0] += bv.x;
                p[mt][nt][rl * 2 + 1] += bv.y;
                m = fmaxf(m, fmaxf(p[mt][nt][rl * 2], p[mt][nt][rl * 2 + 1]));
            }
            m = fmaxf(m, __shfl_xor_sync(0xFFFFFFFFu, m, 1));
            m = fmaxf(m, __shfl_xor_sync(0xFFFFFFFFu, m, 2));
            float s = 0.f;
#pragma unroll
            for (int nt = 0; nt < 8; nt++) {
                float e0 = __expf(p[mt][nt][rl * 2] - m);
                float e1 = __expf(p[mt][nt][rl * 2 + 1] - m);
                p[mt][nt][rl * 2] = e0; p[mt][nt][rl * 2 + 1] = e1;
                s += e0 + e1;
            }
            s += __shfl_xor_sync(0xFFFFFFFFu, s, 1);
            s += __shfl_xor_sync(0xFFFFFFFFu, s, 2);
            sums[mt][rl] = s;
        }
    }

    uint32_t pa[2][4][4];
#pragma unroll
    for (int mt = 0; mt < 2; mt++)
#pragma unroll
        for (int s4 = 0; s4 < 4; s4++) {
            pa[mt][s4][0] = packbf2(p[mt][2 * s4][0], p[mt][2 * s4][1]);
            pa[mt][s4][1] = packbf2(p[mt][2 * s4][2], p[mt][2 * s4][3]);
            pa[mt][s4][2] = packbf2(p[mt][2 * s4 + 1][0], p[mt][2 * s4 + 1][1]);
            pa[mt][s4][3] = packbf2(p[mt][2 * s4 + 1][2], p[mt][2 * s4 + 1][3]);
        }

    float o[2][4][4];
#pragma unroll
    for (int i = 0; i < 2; i++)
#pragma unroll
        for (int j = 0; j < 4; j++)
#pragma unroll
            for (int k = 0; k < 4; k++) o[i][j][k] = 0.f;

    uint32_t vsm = smem_u32(vt_s);
#pragma unroll
    for (int s4 = 0; s4 < 4; s4++) {
#pragma unroll
        for (int n16 = 0; n16 < 2; n16++) {
            uint32_t b[4];
            uint32_t addr = vsm + ((h * HD + n16 * 16 + brow) * VSTR + (s4 * 2 + bchlo) * 8) * 2;
            ldsm_x4(addr, b);
#pragma unroll
            for (int mt = 0; mt < 2; mt++) {
                mma_bf16(o[mt][n16 * 2 + 0], pa[mt][s4], &b[0]);
                mma_bf16(o[mt][n16 * 2 + 1], pa[mt][s4], &b[2]);
            }
        }
    }

#pragma unroll
    for (int mt = 0; mt < 2; mt++) {
        float i0 = 1.0f / sums[mt][0];
        float i1 = 1.0f / sums[mt][1];
        int r0 = mbase + mt * 16 + rq;
        __nv_bfloat16* op0 = outp + (size_t)(w * NWIN + r0) * CC + h * HD;
        __nv_bfloat16* op1 = op0 + 8 * CC;
#pragma unroll
        for (int nt = 0; nt < 4; nt++) {
            *(__nv_bfloat162*)(op0 + nt * 8 + cq) =
                __float22bfloat162_rn(make_float2(o[mt][nt][0] * i0, o[mt][nt][1] * i0));
            *(__nv_bfloat162*)(op1 + nt * 8 + cq) =
                __float22bfloat162_rn(make_float2(o[mt][nt][2] * i1, o[mt][nt][3] * i1));
        }
    }
}

// ---------------------------------------------------------------------------
// Launch
// ---------------------------------------------------------------------------
extern "C" void kernel_launch(void* const* d_in, const int* in_sizes, int n_in,
                              void* d_out, int out_size) {
    const float* x      = (const float*)d_in[0];
    const float* n1_g   = (const float*)d_in[4];
    const float* n1_b   = (const float*)d_in[5];
    const float* qkv_w  = (const float*)d_in[6];
    const float* qkv_b  = (const float*)d_in[7];
    const float* proj_w = (const float*)d_in[8];
    const float* proj_b = (const float*)d_in[9];
    const float* pp_w   = (const float*)d_in[10];
    const float* pp_b   = (const float*)d_in[11];
    const float* p1_g   = (const float*)d_in[12];
    const float* p1_b   = (const float*)d_in[13];
    const float* p1_w   = (const float*)d_in[14];
    const float* p1_bi  = (const float*)d_in[15];
    const float* p2_g   = (const float*)d_in[16];
    const float* p2_b   = (const float*)d_in[17];
    const float* p2_w   = (const float*)d_in[18];
    const float* p2_bi  = (const float*)d_in[19];
    const float* p3_g   = (const float*)d_in[20];
    const float* p3_b   = (const float*)d_in[21];
    const float* p3_w   = (const float*)d_in[22];
    const float* p3_bi  = (const float*)d_in[23];
    const float* n2_g   = (const float*)d_in[24];
    const float* n2_b   = (const float*)d_in[25];
    const float* fc1_w  = (const float*)d_in[26];
    const float* fc1_b  = (const float*)d_in[27];
    const float* fc2_w  = (const float*)d_in[28];
    const float* fc2_b  = (const float*)d_in[29];
    float* out = (float*)d_out;

    __nv_bfloat16 *xw, *qkv, *attn, *ln2, *hid;
    __nv_bfloat16 *wt_qkv, *wt_proj, *wt_fc1, *wt_fc2;
    cudaGetSymbolAddress((void**)&xw,   gb_xw);
    cudaGetSymbolAddress((void**)&qkv,  gb_qkv);
    cudaGetSymbolAddress((void**)&attn, gb_attn);
    cudaGetSymbolAddress((void**)&ln2,  gb_ln2);
    cudaGetSymbolAddress((void**)&hid,  gb_hid);
    cudaGetSymbolAddress((void**)&wt_qkv,  gb_wt_qkv);
    cudaGetSymbolAddress((void**)&wt_proj, gb_wt_proj);
    cudaGetSymbolAddress((void**)&wt_fc1,  gb_wt_fc1);
    cudaGetSymbolAddress((void**)&wt_fc2,  gb_wt_fc2);

    static bool attr_set = false;
    if (!attr_set) {
        cudaFuncSetAttribute(attn_kernel, cudaFuncAttributeMaxDynamicSharedMemorySize,
                             ATTN_SMEM);
        cudaFuncSetAttribute(gemm_proj_ln, cudaFuncAttributeMaxDynamicSharedMemorySize,
                             PROJ_SMEM);
        cudaFuncSetAttribute(gemm_fc2, cudaFuncAttributeMaxDynamicSharedMemorySize,
                             PROJ_SMEM);
        attr_set = true;
    }

    // 0. weight transposes
    transpose_all<<<(TW_TOTAL + 255) / 256, 256>>>(qkv_w, proj_w, fc1_w, fc2_w);

    // 1. position-bias MLP + bias table
    pos_mlp_kernel<<<1, 256>>>(pp_w, pp_b, p1_g, p1_b, p1_w, p1_bi,
                               p2_g, p2_b, p2_w, p2_bi, p3_g, p3_b, p3_w, p3_bi);
    bias_build<<<(4 * HEADS * NWIN * NWIN + 255) / 256, 256>>>();

    // 2. LN1 + shift + window partition -> bf16
    ln1_kernel<<<MROWS / 8, 256>>>(x, xw, n1_g, n1_b);

    // 3. QKV GEMM -> bf16 (Q pre-scaled)
    gemm_mma<0><<<dim3(576 / 64, MROWS / 128), 128>>>(xw, wt_qkv, qkv_b, qkv, CC, 576);

    // 4. tensor-core attention -> bf16
    attn_kernel<<<NWINDOWS, 384, ATTN_SMEM>>>(qkv, attn);

    // 5. proj + scatter + residual + LN2 (fused)
    gemm_proj_ln<<<MROWS / 128, 256, PROJ_SMEM>>>(attn, wt_proj, proj_b, x, out, ln2, n2_g, n2_b);

    // 6. FC1 + GELU -> bf16
    gemm_mma<1><<<dim3(HIDDEN / 64, MROWS / 128), 128>>>(ln2, wt_fc1, fc1_b, hid, CC, HIDDEN);

    // 7. FC2 + residual -> fp32 out (single N-tile: hid read once)
    gemm_fc2<<<MROWS / 128, 256, PROJ_SMEM>>>(hid, wt_fc2, fc2_b, out, out);
}

// round 10
// speedup vs baseline: 1.1148x; 1.0616x over previous
#include <cuda_runtime.h>
#include <cuda_bf16.h>
#include <math.h>
#include <stdint.h>

// ---------------------------------------------------------------------------
// Problem constants
// ---------------------------------------------------------------------------
#define BATCH   8
#define HH      128
#define WW_     128
#define LL      (HH*WW_)
#define CC      192
#define HEADS   6
#define HD      32
#define WS      8
#define NWIN    64
#define SHIFT   4
#define HIDDEN  768
#define MROWS   (BATCH*LL)                 // 131072
#define NWINDOWS (BATCH*(HH/WS)*(WW_/WS))  // 2048
#define POS_DIM 12
#define POS_TAB 225
#define QSCALE  0.17677669529663687f

// ---------------------------------------------------------------------------
// Device scratch
// ---------------------------------------------------------------------------
__device__ __nv_bfloat16 gb_xw[(size_t)MROWS * CC];
__device__ __nv_bfloat16 gb_qkv[(size_t)MROWS * 3 * CC];
__device__ __nv_bfloat16 gb_attn[(size_t)MROWS * CC];
__device__ __nv_bfloat16 gb_ln2[(size_t)MROWS * CC];
__device__ __nv_bfloat16 gb_hid[(size_t)MROWS * HIDDEN];
__device__ float g_pos[POS_TAB * HEADS];
__device__ float g_bias[4 * HEADS * NWIN * NWIN];   // [type][h][r][j]
__device__ __nv_bfloat16 gb_wt_qkv[3 * CC * CC];
__device__ __nv_bfloat16 gb_wt_proj[CC * CC];
__device__ __nv_bfloat16 gb_wt_fc1[HIDDEN * CC];
__device__ __nv_bfloat16 gb_wt_fc2[CC * HIDDEN];

// ---------------------------------------------------------------------------
// Helpers
// ---------------------------------------------------------------------------
__device__ __forceinline__ uint32_t smem_u32(const void* p) {
    uint32_t a;
    asm("{ .reg .u64 t; cvta.to.shared.u64 t, %1; cvt.u32.u64 %0, t; }" : "=r"(a) : "l"(p));
    return a;
}
__device__ __forceinline__ void cpasync16(uint32_t s, const void* g) {
    asm volatile("cp.async.cg.shared.global [%0], [%1], 16;" :: "r"(s), "l"(g));
}
__device__ __forceinline__ void cp_commit() {
    asm volatile("cp.async.commit_group;" ::: "memory");
}
__device__ __forceinline__ void cp_wait1() {
    asm volatile("cp.async.wait_group 1;" ::: "memory");
}
__device__ __forceinline__ void ldsm_x4(uint32_t addr, uint32_t* r) {
    asm volatile("ldmatrix.sync.aligned.m8n8.x4.shared.b16 {%0,%1,%2,%3}, [%4];"
                 : "=r"(r[0]), "=r"(r[1]), "=r"(r[2]), "=r"(r[3]) : "r"(addr));
}
__device__ __forceinline__ void mma_bf16(float* d, const uint32_t* a, const uint32_t* b) {
    asm volatile(
        "mma.sync.aligned.m16n8k16.row.col.f32.bf16.bf16.f32 "
        "{%0,%1,%2,%3}, {%4,%5,%6,%7}, {%8,%9}, {%0,%1,%2,%3};"
        : "+f"(d[0]), "+f"(d[1]), "+f"(d[2]), "+f"(d[3])
        : "r"(a[0]), "r"(a[1]), "r"(a[2]), "r"(a[3]), "r"(b[0]), "r"(b[1]));
}
__device__ __forceinline__ uint32_t packbf2(float x, float y) {
    __nv_bfloat162 t = __float22bfloat162_rn(make_float2(x, y));
    return *(uint32_t*)&t;
}
__device__ __forceinline__ float gelu_exact(float x) {
    return 0.5f * x * (1.0f + erff(x * 0.7071067811865476f));
}

// ---------------------------------------------------------------------------
// Combined weight transpose
// ---------------------------------------------------------------------------
#define TW_QKV (3*CC*CC)
#define TW_PROJ (CC*CC)
#define TW_FC1 (CC*HIDDEN)
#define TW_FC2 (HIDDEN*CC)
#define TW_TOTAL (TW_QKV + TW_PROJ + TW_FC1 + TW_FC2)

__global__ void transpose_all(const float* __restrict__ qkv_w, const float* __restrict__ proj_w,
                              const float* __restrict__ fc1_w, const float* __restrict__ fc2_w) {
    int i = blockIdx.x * 256 + threadIdx.x;
    if (i >= TW_TOTAL) return;
    const float* w; __nv_bfloat16* wt; int K, N, off;
    if (i < TW_QKV) { w = qkv_w; wt = gb_wt_qkv; K = CC; N = 3 * CC; off = i; }
    else if (i < TW_QKV + TW_PROJ) { w = proj_w; wt = gb_wt_proj; K = CC; N = CC; off = i - TW_QKV; }
    else if (i < TW_QKV + TW_PROJ + TW_FC1) { w = fc1_w; wt = gb_wt_fc1; K = CC; N = HIDDEN; off = i - TW_QKV - TW_PROJ; }
    else { w = fc2_w; wt = gb_wt_fc2; K = HIDDEN; N = CC; off = i - TW_QKV - TW_PROJ - TW_FC1; }
    int k = off / N, n = off % N;
    wt[(size_t)n * K + k] = __float2bfloat16(w[off]);
}

// ---------------------------------------------------------------------------
// Position-bias MLP
// ---------------------------------------------------------------------------
__device__ __forceinline__ void ln_relu12(const float* p, float* q,
                                          const float* g, const float* b) {
    float s = 0.f, s2 = 0.f;
#pragma unroll
    for (int i = 0; i < POS_DIM; i++) { s += p[i]; s2 += p[i] * p[i]; }
    float mu = s / 12.0f;
    float var = s2 / 12.0f - mu * mu;
    float rs = rsqrtf(var + 1e-5f);
#pragma unroll
    for (int i = 0; i < POS_DIM; i++) q[i] = fmaxf((p[i] - mu) * rs * g[i] + b[i], 0.0f);
}

__global__ void pos_mlp_kernel(
    const float* __restrict__ pp_w, const float* __restrict__ pp_b,
    const float* __restrict__ p1_g, const float* __restrict__ p1_b,
    const float* __restrict__ p1_w, const float* __restrict__ p1_bias,
    const float* __restrict__ p2_g, const float* __restrict__ p2_b,
    const float* __restrict__ p2_w, const float* __restrict__ p2_bias,
    const float* __restrict__ p3_g, const float* __restrict__ p3_b,
    const float* __restrict__ p3_w, const float* __restrict__ p3_bias) {
    int t = blockIdx.x * blockDim.x + threadIdx.x;
    if (t >= POS_TAB) return;
    float bh = (float)(t / 15 - 7), bw = (float)(t % 15 - 7);
    float p[POS_DIM], q[POS_DIM];
#pragma unroll
    for (int j = 0; j < POS_DIM; j++) p[j] = bh * pp_w[j] + bw * pp_w[POS_DIM + j] + pp_b[j];
    ln_relu12(p, q, p1_g, p1_b);
#pragma unroll
    for (int j = 0; j < POS_DIM; j++) {
        float s = p1_bias[j];
#pragma unroll
        for (int i = 0; i < POS_DIM; i++) s += q[i] * p1_w[i * POS_DIM + j];
        p[j] = s;
    }
    ln_relu12(p, q, p2_g, p2_b);
#pragma unroll
    for (int j = 0; j < POS_DIM; j++) {
        float s = p2_bias[j];
#pragma unroll
        for (int i = 0; i < POS_DIM; i++) s += q[i] * p2_w[i * POS_DIM + j];
        p[j] = s;
    }
    ln_relu12(p, q, p3_g, p3_b);
#pragma unroll
    for (int h = 0; h < HEADS; h++) {
        float s = p3_bias[h];
#pragma unroll
        for (int i = 0; i < POS_DIM; i++) s += q[i] * p3_w[i * HEADS + h];
        g_pos[t * HEADS + h] = s;
    }
}

// ---------------------------------------------------------------------------
// Bias table: [type][h][r][j]
// ---------------------------------------------------------------------------
__global__ void bias_build() {
    int idx = blockIdx.x * 256 + threadIdx.x;
    if (idx >= 4 * HEADS * NWIN * NWIN) return;
    int j = idx & 63;
    int r = (idx >> 6) & 63;
    int h = (idx >> 12) % HEADS;
    int t = idx / (HEADS * NWIN * NWIN);
    int ry = r >> 3, rx = r & 7, jy = j >> 3, jx = j & 7;
    float bias = g_pos[(((ry - jy + 7) * 15) + (rx - jx + 7)) * HEADS + h];
    int lhr = (t & 2) ? (ry < (WS - SHIFT) ? 1 : 2) : 0;
    int lhj = (t & 2) ? (jy < (WS - SHIFT) ? 1 : 2) : 0;
    int lwr = (t & 1) ? (rx < (WS - SHIFT) ? 1 : 2) : 0;
    int lwj = (t & 1) ? (jx < (WS - SHIFT) ? 1 : 2) : 0;
    if (lhr != lhj || lwr != lwj) bias -= 100.0f;
    g_bias[idx] = bias;
}

// ---------------------------------------------------------------------------
// LayerNorm1: warp per row, fp32 in -> bf16 out, shift+window gather
// ---------------------------------------------------------------------------
__global__ void __launch_bounds__(256) ln1_kernel(
    const float* __restrict__ in, __nv_bfloat16* __restrict__ out,
    const float* __restrict__ gamma, const float* __restrict__ beta) {
    int warp = threadIdx.x >> 5, lane = threadIdx.x & 31;
    int row = blockIdx.x * 8 + warp;
    int bb = row >> 14, rem = row & 16383;
    int win = rem >> 6, r = rem & 63;
    int wy = win >> 4, wx = win & 15, ry = r >> 3, rx = r & 7;
    int hh = (wy * WS + ry + SHIFT) & 127;
    int ww = (wx * WS + rx + SHIFT) & 127;
    size_t src = (size_t)bb * LL + hh * WW_ + ww;

    const float* p = in + src * CC;
    float v[6], s = 0.f, s2 = 0.f;
#pragma unroll
    for (int k = 0; k < 6; k++) { v[k] = p[lane + 32 * k]; s += v[k]; s2 += v[k] * v[k]; }
#pragma unroll
    for (int o = 16; o > 0; o >>= 1) {
        s += __shfl_xor_sync(0xFFFFFFFFu, s, o);
        s2 += __shfl_xor_sync(0xFFFFFFFFu, s2, o);
    }
    float mu = s * (1.0f / 192.0f);
    float rs = rsqrtf(s2 * (1.0f / 192.0f) - mu * mu + 1e-5f);
    __nv_bfloat16* q = out + (size_t)row * CC;
#pragma unroll
    for (int k = 0; k < 6; k++) {
        int c = lane + 32 * k;
        q[c] = __float2bfloat16((v[k] - mu) * rs * gamma[c] + beta[c]);
    }
}

// ---------------------------------------------------------------------------
// bf16 mma GEMM v2 (round-7 config): 128x64 CTA tile, 8 warps, BK=64,
// ldmatrix, XOR-swizzled smem, static 48KB.
// EPI 0: +bias, Q-scale cols<192 -> bf16   1: gelu(+bias) -> bf16
// ---------------------------------------------------------------------------
#define CH_PER_BUF (192 * 8)

template <int EPI>
__global__ void __launch_bounds__(256) gemm_mma(
    const __nv_bfloat16* __restrict__ A, const __nv_bfloat16* __restrict__ BT,
    const float* __restrict__ bias, void* __restrict__ outv, int K, int NOUT) {
    __shared__ __align__(16) uint4 smq[2 * CH_PER_BUF];
    uint32_t sbase = smem_u32(smq);
    int tid = threadIdx.x;
    int wid = tid >> 5, lane = tid & 31;
    int wm = wid & 3, wn = wid >> 2;
    int m0 = blockIdx.y * 128, n0 = blockIdx.x * 64;
    const __nv_bfloat16* Ab = A + (size_t)m0 * K;
    const __nv_bfloat16* Bb = BT + (size_t)n0 * K;
    int NCH = K >> 6;

    float acc[2][4][4];
#pragma unroll
    for (int i = 0; i < 2; i++)
#pragma unroll
        for (int j = 0; j < 4; j++)
#pragma unroll
            for (int k = 0; k < 4; k++) acc[i][j][k] = 0.f;

    int a_row = tid >> 1;
    int a_ch0 = (tid & 1) * 4;
    int b_row = tid >> 2;
    int b_ch0 = (tid & 3) * 2;

    int l15 = lane & 15, lhi = lane >> 4;
    int a_lrow = wm * 32 + l15;
    int a_sw = l15 & 7;
    int b_lrow = 128 + wn * 32 + (lhi << 3) + (lane & 7);
    int b_sw = lane & 7;
    int b_chlo = (lane >> 3) & 1;

    {
        uint32_t dst = sbase;
#pragma unroll
        for (int i = 0; i < 4; i++) {
            int ch = a_ch0 + i;
            cpasync16(dst + (a_row * 8 + (ch ^ (a_row & 7))) * 16,
                      Ab + (size_t)a_row * K + ch * 8);
        }
#pragma unroll
        for (int i = 0; i < 2; i++) {
            int ch = b_ch0 + i;
            cpasync16(dst + ((128 + b_row) * 8 + (ch ^ (b_row & 7))) * 16,
                      Bb + (size_t)b_row * K + ch * 8);
        }
        cp_commit();
    }

    for (int c = 0; c < NCH; c++) {
        if (c + 1 < NCH) {
            int k0 = (c + 1) << 6;
            uint32_t dst = sbase + ((c + 1) & 1) * CH_PER_BUF * 16;
#pragma unroll
            for (int i = 0; i < 4; i++) {
                int ch = a_ch0 + i;
                cpasync16(dst + (a_row * 8 + (ch ^ (a_row & 7))) * 16,
                          Ab + (size_t)a_row * K + k0 + ch * 8);
            }
#pragma unroll
            for (int i = 0; i < 2; i++) {
                int ch = b_ch0 + i;
                cpasync16(dst + ((128 + b_row) * 8 + (ch ^ (b_row & 7))) * 16,
                          Bb + (size_t)b_row * K + k0 + ch * 8);
            }
        }
        cp_commit();
        cp_wait1();
        __syncthreads();

        uint32_t buf = sbase + (c & 1) * CH_PER_BUF * 16;
#pragma unroll
        for (int ks = 0; ks < 4; ks++) {
            uint32_t a[2][4], b[2][4];
            int achk = 2 * ks + lhi;
#pragma unroll
            for (int mt = 0; mt < 2; mt++) {
                uint32_t idx = (a_lrow + mt * 16) * 8 + (achk ^ a_sw);
                ldsm_x4(buf + idx * 16, a[mt]);
            }
            int bchk = 2 * ks + b_chlo;
#pragma unroll
            for (int nt16 = 0; nt16 < 2; nt16++) {
                uint32_t idx = (b_lrow + nt16 * 16) * 8 + (bchk ^ b_sw);
                ldsm_x4(buf + idx * 16, b[nt16]);
            }
#pragma unroll
            for (int mt = 0; mt < 2; mt++) {
#pragma unroll
                for (int nt16 = 0; nt16 < 2; nt16++) {
                    mma_bf16(acc[mt][nt16 * 2 + 0], a[mt], &b[nt16][0]);
                    mma_bf16(acc[mt][nt16 * 2 + 1], a[mt], &b[nt16][2]);
                }
            }
        }
        __syncthreads();
    }

#pragma unroll
    for (int mt = 0; mt < 2; mt++) {
        int g0 = m0 + wm * 32 + mt * 16 + (lane >> 2);
        int g1 = g0 + 8;
        size_t ob0 = (size_t)g0 * NOUT;
        size_t ob1 = (size_t)g1 * NOUT;
#pragma unroll
        for (int nt = 0; nt < 4; nt++) {
            int col = n0 + wn * 32 + nt * 8 + 2 * (lane & 3);
            float b0 = bias[col], b1 = bias[col + 1];
            float2 v0 = make_float2(acc[mt][nt][0] + b0, acc[mt][nt][1] + b1);
            float2 v1 = make_float2(acc[mt][nt][2] + b0, acc[mt][nt][3] + b1);
            if (EPI == 0) {
                float sc = (col < CC) ? QSCALE : 1.0f;
                v0.x *= sc; v0.y *= sc; v1.x *= sc; v1.y *= sc;
            }
            if (EPI == 1) {
                v0.x = gelu_exact(v0.x); v0.y = gelu_exact(v0.y);
                v1.x = gelu_exact(v1.x); v1.y = gelu_exact(v1.y);
            }
            __nv_bfloat16* out = (__nv_bfloat16*)outv;
            *(__nv_bfloat162*)(out + ob0 + col) = __float22bfloat162_rn(v0);
            *(__nv_bfloat162*)(out + ob1 + col) = __float22bfloat162_rn(v1);
        }
    }
}

// ---------------------------------------------------------------------------
// FC2 GEMM: full-row tile 128x192, K=768, hid read ONCE. +bias +res -> fp32.
// ---------------------------------------------------------------------------
#define PCH_PER_BUF (320 * 8)
#define PROJ_SMEM (2 * PCH_PER_BUF * 16)

__global__ void __launch_bounds__(256) gemm_fc2(
    const __nv_bfloat16* __restrict__ A, const __nv_bfloat16* __restrict__ BT,
    const float* __restrict__ bias, const float* __restrict__ res,
    float* __restrict__ out) {
    extern __shared__ __align__(16) uint4 psm[];
    uint32_t sbase = smem_u32(psm);
    int tid = threadIdx.x;
    int wid = tid >> 5, lane = tid & 31;
    int m0 = blockIdx.x * 128;
    const int K = HIDDEN;
    const __nv_bfloat16* Ab = A + (size_t)m0 * K;

    float acc[24][4];
#pragma unroll
    for (int j = 0; j < 24; j++)
#pragma unroll
        for (int k = 0; k < 4; k++) acc[j][k] = 0.f;

    int a_row = tid >> 1;
    int a_ch0 = (tid & 1) * 4;
    int b_row = tid >> 2;
    int b_ch0 = (tid & 3) * 2;

    int l15 = lane & 15, lhi = lane >> 4;
    int a_lrow = wid * 16 + l15;
    int a_sw = l15 & 7;
    int b_lbase = 128 + (lhi << 3) + (lane & 7);
    int b_sw = lane & 7;
    int b_chlo = (lane >> 3) & 1;

    {
        uint32_t dst = sbase;
#pragma unroll
        for (int i = 0; i < 4; i++) {
            int ch = a_ch0 + i;
            cpasync16(dst + (a_row * 8 + (ch ^ (a_row & 7))) * 16,
                      Ab + (size_t)a_row * K + ch * 8);
        }
#pragma unroll
        for (int r3 = 0; r3 < 3; r3++) {
            int row = r3 * 64 + b_row;
#pragma unroll
            for (int i = 0; i < 2; i++) {
                int ch = b_ch0 + i;
                cpasync16(dst + ((128 + row) * 8 + (ch ^ (row & 7))) * 16,
                          BT + (size_t)row * K + ch * 8);
            }
        }
        cp_commit();
    }

    const int NCH = K >> 6;  // 12
    for (int c = 0; c < NCH; c++) {
        if (c + 1 < NCH) {
            int k0 = (c + 1) << 6;
            uint32_t dst = sbase + ((c + 1) & 1) * PCH_PER_BUF * 16;
#pragma unroll
            for (int i = 0; i < 4; i++) {
                int ch = a_ch0 + i;
                cpasync16(dst + (a_row * 8 + (ch ^ (a_row & 7))) * 16,
                          Ab + (size_t)a_row * K + k0 + ch * 8);
            }
#pragma unroll
            for (int r3 = 0; r3 < 3; r3++) {
                int row = r3 * 64 + b_row;
#pragma unroll
                for (int i = 0; i < 2; i++) {
                    int ch = b_ch0 + i;
                    cpasync16(dst + ((128 + row) * 8 + (ch ^ (row & 7))) * 16,
                              BT + (size_t)row * K + k0 + ch * 8);
                }
            }
        }
        cp_commit();
        cp_wait1();
        __syncthreads();

        uint32_t buf = sbase + (c & 1) * PCH_PER_BUF * 16;
#pragma unroll
        for (int ks = 0; ks < 4; ks++) {
            uint32_t a[4];
            int achk = 2 * ks + lhi;
            ldsm_x4(buf + (a_lrow * 8 + (achk ^ a_sw)) * 16, a);
            int bchk = 2 * ks + b_chlo;
#pragma unroll
            for (int nt16 = 0; nt16 < 12; nt16++) {
                uint32_t b[4];
                ldsm_x4(buf + ((b_lbase + nt16 * 16) * 8 + (bchk ^ b_sw)) * 16, b);
                mma_bf16(acc[nt16 * 2 + 0], a, &b[0]);
                mma_bf16(acc[nt16 * 2 + 1], a, &b[2]);
            }
        }
        __syncthreads();
    }

    int lq = lane & 3;
#pragma unroll
    for (int half = 0; half < 2; half++) {
        int g = m0 + wid * 16 + (lane >> 2) + half * 8;
        size_t ob = (size_t)g * CC;
#pragma unroll
        for (int nt = 0; nt < 24; nt++) {
            int col = nt * 8 + 2 * lq;
            float v0 = acc[nt][half * 2 + 0] + bias[col];
            float v1 = acc[nt][half * 2 + 1] + bias[col + 1];
            float2 rv = *(const float2*)(res + ob + col);
            v0 += rv.x; v1 += rv.y;
            *(float2*)(out + ob + col) = make_float2(v0, v1);
        }
    }
}

// ---------------------------------------------------------------------------
// Proj GEMM + scatter + residual + LN2 (fused)
// ---------------------------------------------------------------------------
__global__ void __launch_bounds__(256) gemm_proj_ln(
    const __nv_bfloat16* __restrict__ A, const __nv_bfloat16* __restrict__ BT,
    const float* __restrict__ bias, const float* __restrict__ x,
    float* __restrict__ y, __nv_bfloat16* __restrict__ ln2out,
    const float* __restrict__ n2g, const float* __restrict__ n2b) {
    extern __shared__ __align__(16) uint4 psm[];
    uint32_t sbase = smem_u32(psm);
    int tid = threadIdx.x;
    int wid = tid >> 5, lane = tid & 31;
    int m0 = blockIdx.x * 128;
    const __nv_bfloat16* Ab = A + (size_t)m0 * CC;

    float acc[24][4];
#pragma unroll
    for (int j = 0; j < 24; j++)
#pragma unroll
        for (int k = 0; k < 4; k++) acc[j][k] = 0.f;

    int a_row = tid >> 1;
    int a_ch0 = (tid & 1) * 4;
    int b_row = tid >> 2;
    int b_ch0 = (tid & 3) * 2;

    int l15 = lane & 15, lhi = lane >> 4;
    int a_lrow = wid * 16 + l15;
    int a_sw = l15 & 7;
    int b_lbase = 128 + (lhi << 3) + (lane & 7);
    int b_sw = lane & 7;
    int b_chlo = (lane >> 3) & 1;

    {
        uint32_t dst = sbase;
#pragma unroll
        for (int i = 0; i < 4; i++) {
            int ch = a_ch0 + i;
            cpasync16(dst + (a_row * 8 + (ch ^ (a_row & 7))) * 16,
                      Ab + (size_t)a_row * CC + ch * 8);
        }
#pragma unroll
        for (int r3 = 0; r3 < 3; r3++) {
            int row = r3 * 64 + b_row;
#pragma unroll
            for (int i = 0; i < 2; i++) {
                int ch = b_ch0 + i;
                cpasync16(dst + ((128 + row) * 8 + (ch ^ (row & 7))) * 16,
                          BT + (size_t)row * CC + ch * 8);
            }
        }
        cp_commit();
    }

    for (int c = 0; c < 3; c++) {
        if (c + 1 < 3) {
            int k0 = (c + 1) << 6;
            uint32_t dst = sbase + ((c + 1) & 1) * PCH_PER_BUF * 16;
#pragma unroll
            for (int i = 0; i < 4; i++) {
                int ch = a_ch0 + i;
                cpasync16(dst + (a_row * 8 + (ch ^ (a_row & 7))) * 16,
                          Ab + (size_t)a_row * CC + k0 + ch * 8);
            }
#pragma unroll
            for (int r3 = 0; r3 < 3; r3++) {
                int row = r3 * 64 + b_row;
#pragma unroll
                for (int i = 0; i < 2; i++) {
                    int ch = b_ch0 + i;
                    cpasync16(dst + ((128 + row) * 8 + (ch ^ (row & 7))) * 16,
                              BT + (size_t)row * CC + k0 + ch * 8);
                }
            }
        }
        cp_commit();
        cp_wait1();
        __syncthreads();

        uint32_t buf = sbase + (c & 1) * PCH_PER_BUF * 16;
#pragma unroll
        for (int ks = 0; ks < 4; ks++) {
            uint32_t a[4];
            int achk = 2 * ks + lhi;
            ldsm_x4(buf + (a_lrow * 8 + (achk ^ a_sw)) * 16, a);
            int bchk = 2 * ks + b_chlo;
#pragma unroll
            for (int nt16 = 0; nt16 < 12; nt16++) {
                uint32_t b[4];
                ldsm_x4(buf + ((b_lbase + nt16 * 16) * 8 + (bchk ^ b_sw)) * 16, b);
                mma_bf16(acc[nt16 * 2 + 0], a, &b[0]);
                mma_bf16(acc[nt16 * 2 + 1], a, &b[2]);
            }
        }
        __syncthreads();
    }

    int lq = lane & 3;
#pragma unroll
    for (int half = 0; half < 2; half++) {
        int g = m0 + wid * 16 + (lane >> 2) + half * 8;
        int bb = g >> 14, rem = g & 16383;
        int win = rem >> 6, rr = rem & 63;
        int wy = win >> 4, wx = win & 15, ry = rr >> 3, rx = rr & 7;
        int hh = (wy * WS + ry + SHIFT) & 127;
        int ww = (wx * WS + rx + SHIFT) & 127;
        size_t ob = ((size_t)bb * LL + hh * WW_ + ww) * CC;

        float vals[48];
        float s = 0.f, s2 = 0.f;
#pragma unroll
        for (int nt = 0; nt < 24; nt++) {
            int col = nt * 8 + 2 * lq;
            float v0 = acc[nt][half * 2 + 0] + bias[col];
            float v1 = acc[nt][half * 2 + 1] + bias[col + 1];
            float2 rv = *(const float2*)(x + ob + col);
            v0 += rv.x; v1 += rv.y;
            *(float2*)(y + ob + col) = make_float2(v0, v1);
            s += v0 + v1;
            s2 += v0 * v0 + v1 * v1;
            vals[nt * 2] = v0; vals[nt * 2 + 1] = v1;
        }
        s += __shfl_xor_sync(0xFFFFFFFFu, s, 1);
        s2 += __shfl_xor_sync(0xFFFFFFFFu, s2, 1);
        s += __shfl_xor_sync(0xFFFFFFFFu, s, 2);
        s2 += __shfl_xor_sync(0xFFFFFFFFu, s2, 2);
        float mu = s * (1.0f / 192.0f);
        float rs = rsqrtf(s2 * (1.0f / 192.0f) - mu * mu + 1e-5f);
#pragma unroll
        for (int nt = 0; nt < 24; nt++) {
            int col = nt * 8 + 2 * lq;
            float2 gg = *(const float2*)(n2g + col);
            float2 bb2 = *(const float2*)(n2b + col);
            float2 o;
            o.x = (vals[nt * 2] - mu) * rs * gg.x + bb2.x;
            o.y = (vals[nt * 2 + 1] - mu) * rs * gg.y + bb2.y;
            *(__nv_bfloat162*)(ln2out + ob + col) = __float22bfloat162_rn(o);
        }
    }
}

// ---------------------------------------------------------------------------
// Tensor-core windowed attention (round-7 version, unchanged)
// ---------------------------------------------------------------------------
#define KSTR 200
#define VSTR 72
#define ATTN_SMEM ((NWIN * KSTR + CC * VSTR) * 2)

__global__ void __launch_bounds__(384) attn_kernel(
    const __nv_bfloat16* __restrict__ qkv, __nv_bfloat16* __restrict__ outp) {
    extern __shared__ __nv_bfloat16 smh[];
    __nv_bfloat16* k_s = smh;
    __nv_bfloat16* vt_s = smh + NWIN * KSTR;

    int w = blockIdx.x;
    int tid = threadIdx.x;
    int lane = tid & 31, wid = tid >> 5;
    const __nv_bfloat16* base = qkv + (size_t)w * NWIN * 576;

    for (int idx = tid; idx < NWIN * 24; idx += 384) {
        int j = idx / 24, c = idx % 24;
        uint4 uk = *(const uint4*)(base + (size_t)j * 576 + 192 + c * 8);
        *(uint4*)(k_s + j * KSTR + c * 8) = uk;
        uint4 uv = *(const uint4*)(base + (size_t)j * 576 + 384 + c * 8);
        const unsigned short* e = (const unsigned short*)&uv;
#pragma unroll
        for (int i = 0; i < 8; i++) {
            int k = (i + lane) & 7;
            *((unsigned short*)vt_s + (c * 8 + k) * VSTR + j) = e[k];
        }
    }
    __syncthreads();

    int h = wid >> 1;
    int mbase = (wid & 1) * 32;
    int winloc = w & 255;
    int wy = winloc >> 4, wx = winloc & 15;
    int type = ((wy == 15) ? 2 : 0) | ((wx == 15) ? 1 : 0);
    const float* btab = g_bias + ((size_t)(type * HEADS + h) * NWIN) * NWIN;

    int rq = lane >> 2, cq = 2 * (lane & 3);
    int brow = ((lane >> 4) << 3) + (lane & 7);
    int bchlo = (lane >> 3) & 1;

    uint32_t a[2][2][4];
#pragma unroll
    for (int mt = 0; mt < 2; mt++)
#pragma unroll
        for (int ks = 0; ks < 2; ks++)
#pragma unroll
            for (int i = 0; i < 4; i++) {
                int row = mbase + mt * 16 + rq + (i & 1) * 8;
                int col = h * HD + ks * 16 + cq + (i >> 1) * 8;
                a[mt][ks][i] = *(const uint32_t*)(base + (size_t)row * 576 + col);
            }

    float p[2][8][4];
#pragma unroll
    for (int i = 0; i < 2; i++)
#pragma unroll
        for (int j = 0; j < 8; j++)
#pragma unroll
            for (int k = 0; k < 4; k++) p[i][j][k] = 0.f;

    uint32_t ksm = smem_u32(k_s);
#pragma unroll
    for (int kg = 0; kg < 4; kg++) {
#pragma unroll
        for (int ks = 0; ks < 2; ks++) {
            uint32_t b[4];
            uint32_t addr = ksm + ((kg * 16 + brow) * KSTR + (h * 4 + ks * 2 + bchlo) * 8) * 2;
            ldsm_x4(addr, b);
#pragma unroll
            for (int mt = 0; mt < 2; mt++) {
                mma_bf16(p[mt][kg * 2 + 0], a[mt][ks], &b[0]);
                mma_bf16(p[mt][kg * 2 + 1], a[mt][ks], &b[2]);
            }
        }
    }

    float sums[2][2];
#pragma unroll
    for (int mt = 0; mt < 2; mt++) {
#pragma unroll
        for (int rl = 0; rl < 2; rl++) {
            int r = mbase + mt * 16 + rq + rl * 8;
            const float* br_ = btab + r * NWIN;
            float m = -1e30f;
#pragma unroll
            for (int nt = 0; nt < 8; nt++) {
                float2 bv = *(const float2*)(br_ + nt * 8 + cq);
                p[mt][nt][rl * 2 + 0] += bv.x;
                p[mt][nt][rl * 2 + 1] += bv.y;
                m = fmaxf(m, fmaxf(p[mt][nt][rl * 2], p[mt][nt][rl * 2 + 1]));
            }
            m = fmaxf(m, __shfl_xor_sync(0xFFFFFFFFu, m, 1));
            m = fmaxf(m, __shfl_xor_sync(0xFFFFFFFFu, m, 2));
            float s = 0.f;
#pragma unroll
            for (int nt = 0; nt < 8; nt++) {
                float e0 = __expf(p[mt][nt][rl * 2] - m);
                float e1 = __expf(p[mt][nt][rl * 2 + 1] - m);
                p[mt][nt][rl * 2] = e0; p[mt][nt][rl * 2 + 1] = e1;
                s += e0 + e1;
            }
            s += __shfl_xor_sync(0xFFFFFFFFu, s, 1);
            s += __shfl_xor_sync(0xFFFFFFFFu, s, 2);
            sums[mt][rl] = s;
        }
    }

    uint32_t pa[2][4][4];
#pragma unroll
    for (int mt = 0; mt < 2; mt++)
#pragma unroll
        for (int s4 = 0; s4 < 4; s4++) {
            pa[mt][s4][0] = packbf2(p[mt][2 * s4][0], p[mt][2 * s4][1]);
            pa[mt][s4][1] = packbf2(p[mt][2 * s4][2], p[mt][2 * s4][3]);
            pa[mt][s4][2] = packbf2(p[mt][2 * s4 + 1][0], p[mt][2 * s4 + 1][1]);
            pa[mt][s4][3] = packbf2(p[mt][2 * s4 + 1][2], p[mt][2 * s4 + 1][3]);
        }

    float o[2][4][4];
#pragma unroll
    for (int i = 0; i < 2; i++)
#pragma unroll
        for (int j = 0; j < 4; j++)
#pragma unroll
            for (int k = 0; k < 4; k++) o[i][j][k] = 0.f;

    uint32_t vsm = smem_u32(vt_s);
#pragma unroll
    for (int s4 = 0; s4 < 4; s4++) {
#pragma unroll
        for (int n16 = 0; n16 < 2; n16++) {
            uint32_t b[4];
            uint32_t addr = vsm + ((h * HD + n16 * 16 + brow) * VSTR + (s4 * 2 + bchlo) * 8) * 2;
            ldsm_x4(addr, b);
#pragma unroll
            for (int mt = 0; mt < 2; mt++) {
                mma_bf16(o[mt][n16 * 2 + 0], pa[mt][s4], &b[0]);
                mma_bf16(o[mt][n16 * 2 + 1], pa[mt][s4], &b[2]);
            }
        }
    }

#pragma unroll
    for (int mt = 0; mt < 2; mt++) {
        float i0 = 1.0f / sums[mt][0];
        float i1 = 1.0f / sums[mt][1];
        int r0 = mbase + mt * 16 + rq;
        __nv_bfloat16* op0 = outp + (size_t)(w * NWIN + r0) * CC + h * HD;
        __nv_bfloat16* op1 = op0 + 8 * CC;
#pragma unroll
        for (int nt = 0; nt < 4; nt++) {
            *(__nv_bfloat162*)(op0 + nt * 8 + cq) =
                __float22bfloat162_rn(make_float2(o[mt][nt][0] * i0, o[mt][nt][1] * i0));
            *(__nv_bfloat162*)(op1 + nt * 8 + cq) =
                __float22bfloat162_rn(make_float2(o[mt][nt][2] * i1, o[mt][nt][3] * i1));
        }
    }
}

// ---------------------------------------------------------------------------
// Launch
// ---------------------------------------------------------------------------
extern "C" void kernel_launch(void* const* d_in, const int* in_sizes, int n_in,
                              void* d_out, int out_size) {
    const float* x      = (const float*)d_in[0];
    const float* n1_g   = (const float*)d_in[4];
    const float* n1_b   = (const float*)d_in[5];
    const float* qkv_w  = (const float*)d_in[6];
    const float* qkv_b  = (const float*)d_in[7];
    const float* proj_w = (const float*)d_in[8];
    const float* proj_b = (const float*)d_in[9];
    const float* pp_w   = (const float*)d_in[10];
    const float* pp_b   = (const float*)d_in[11];
    const float* p1_g   = (const float*)d_in[12];
    const float* p1_b   = (const float*)d_in[13];
    const float* p1_w   = (const float*)d_in[14];
    const float* p1_bi  = (const float*)d_in[15];
    const float* p2_g   = (const float*)d_in[16];
    const float* p2_b   = (const float*)d_in[17];
    const float* p2_w   = (const float*)d_in[18];
    const float* p2_bi  = (const float*)d_in[19];
    const float* p3_g   = (const float*)d_in[20];
    const float* p3_b   = (const float*)d_in[21];
    const float* p3_w   = (const float*)d_in[22];
    const float* p3_bi  = (const float*)d_in[23];
    const float* n2_g   = (const float*)d_in[24];
    const float* n2_b   = (const float*)d_in[25];
    const float* fc1_w  = (const float*)d_in[26];
    const float* fc1_b  = (const float*)d_in[27];
    const float* fc2_w  = (const float*)d_in[28];
    const float* fc2_b  = (const float*)d_in[29];
    float* out = (float*)d_out;

    __nv_bfloat16 *xw, *qkv, *attn, *ln2, *hid;
    __nv_bfloat16 *wt_qkv, *wt_proj, *wt_fc1, *wt_fc2;
    cudaGetSymbolAddress((void**)&xw,   gb_xw);
    cudaGetSymbolAddress((void**)&qkv,  gb_qkv);
    cudaGetSymbolAddress((void**)&attn, gb_attn);
    cudaGetSymbolAddress((void**)&ln2,  gb_ln2);
    cudaGetSymbolAddress((void**)&hid,  gb_hid);
    cudaGetSymbolAddress((void**)&wt_qkv,  gb_wt_qkv);
    cudaGetSymbolAddress((void**)&wt_proj, gb_wt_proj);
    cudaGetSymbolAddress((void**)&wt_fc1,  gb_wt_fc1);
    cudaGetSymbolAddress((void**)&wt_fc2,  gb_wt_fc2);

    static bool attr_set = false;
    if (!attr_set) {
        cudaFuncSetAttribute(attn_kernel, cudaFuncAttributeMaxDynamicSharedMemorySize,
                             ATTN_SMEM);
        cudaFuncSetAttribute(gemm_proj_ln, cudaFuncAttributeMaxDynamicSharedMemorySize,
                             PROJ_SMEM);
        cudaFuncSetAttribute(gemm_fc2, cudaFuncAttributeMaxDynamicSharedMemorySize,
                             PROJ_SMEM);
        attr_set = true;
    }

    // 0. weight transposes
    transpose_all<<<(TW_TOTAL + 255) / 256, 256>>>(qkv_w, proj_w, fc1_w, fc2_w);

    // 1. position-bias MLP + bias table
    pos_mlp_kernel<<<1, 256>>>(pp_w, pp_b, p1_g, p1_b, p1_w, p1_bi,
                               p2_g, p2_b, p2_w, p2_bi, p3_g, p3_b, p3_w, p3_bi);
    bias_build<<<(4 * HEADS * NWIN * NWIN + 255) / 256, 256>>>();

    // 2. LN1 + shift + window partition -> bf16
    ln1_kernel<<<MROWS / 8, 256>>>(x, xw, n1_g, n1_b);

    // 3. QKV GEMM -> bf16 (Q pre-scaled)   [round-7 v2 config]
    gemm_mma<0><<<dim3(576 / 64, MROWS / 128), 256>>>(xw, wt_qkv, qkv_b, qkv, CC, 576);

    // 4. tensor-core attention -> bf16
    attn_kernel<<<NWINDOWS, 384, ATTN_SMEM>>>(qkv, attn);

    // 5. proj + scatter + residual + LN2 (fused)
    gemm_proj_ln<<<MROWS / 128, 256, PROJ_SMEM>>>(attn, wt_proj, proj_b, x, out, ln2, n2_g, n2_b);

    // 6. FC1 + GELU -> bf16   [round-7 v2 config]
    gemm_mma<1><<<dim3(HIDDEN / 64, MROWS / 128), 256>>>(ln2, wt_fc1, fc1_b, hid, CC, HIDDEN);

    // 7. FC2 + residual -> fp32 out (full-row: hid read once)
    gemm_fc2<<<MROWS / 128, 256, PROJ_SMEM>>>(hid, wt_fc2, fc2_b, out, out);
}

// round 11
// speedup vs baseline: 1.2179x; 1.0924x over previous
#include <cuda_runtime.h>
#include <cuda_bf16.h>
#include <math.h>
#include <stdint.h>

// ---------------------------------------------------------------------------
// Problem constants
// ---------------------------------------------------------------------------
#define BATCH   8
#define HH      128
#define WW_     128
#define LL      (HH*WW_)
#define CC      192
#define HEADS   6
#define HD      32
#define WS      8
#define NWIN    64
#define SHIFT   4
#define HIDDEN  768
#define MROWS   (BATCH*LL)                 // 131072
#define NWINDOWS (BATCH*(HH/WS)*(WW_/WS))  // 2048
#define POS_DIM 12
#define POS_TAB 225
#define QSCALE  0.17677669529663687f

// ---------------------------------------------------------------------------
// Device scratch
// ---------------------------------------------------------------------------
__device__ __nv_bfloat16 gb_xw[(size_t)MROWS * CC];
__device__ __nv_bfloat16 gb_qkv[(size_t)MROWS * 3 * CC];
__device__ __nv_bfloat16 gb_attn[(size_t)MROWS * CC];
__device__ __nv_bfloat16 gb_ln2[(size_t)MROWS * CC];
__device__ __nv_bfloat16 gb_hid[(size_t)MROWS * HIDDEN];
__device__ float g_pos[POS_TAB * HEADS];
__device__ float g_bias[4 * HEADS * NWIN * NWIN];   // [type][h][r][j]
__device__ __nv_bfloat16 gb_wt_qkv[3 * CC * CC];
__device__ __nv_bfloat16 gb_wt_proj[CC * CC];
__device__ __nv_bfloat16 gb_wt_fc1[HIDDEN * CC];
__device__ __nv_bfloat16 gb_wt_fc2[CC * HIDDEN];

// ---------------------------------------------------------------------------
// Helpers
// ---------------------------------------------------------------------------
__device__ __forceinline__ uint32_t smem_u32(const void* p) {
    uint32_t a;
    asm("{ .reg .u64 t; cvta.to.shared.u64 t, %1; cvt.u32.u64 %0, t; }" : "=r"(a) : "l"(p));
    return a;
}
__device__ __forceinline__ void cpasync16(uint32_t s, const void* g) {
    asm volatile("cp.async.cg.shared.global [%0], [%1], 16;" :: "r"(s), "l"(g));
}
__device__ __forceinline__ void cp_commit() {
    asm volatile("cp.async.commit_group;" ::: "memory");
}
__device__ __forceinline__ void cp_wait1() {
    asm volatile("cp.async.wait_group 1;" ::: "memory");
}
__device__ __forceinline__ void ldsm_x4(uint32_t addr, uint32_t* r) {
    asm volatile("ldmatrix.sync.aligned.m8n8.x4.shared.b16 {%0,%1,%2,%3}, [%4];"
                 : "=r"(r[0]), "=r"(r[1]), "=r"(r[2]), "=r"(r[3]) : "r"(addr));
}
__device__ __forceinline__ void mma_bf16(float* d, const uint32_t* a, const uint32_t* b) {
    asm volatile(
        "mma.sync.aligned.m16n8k16.row.col.f32.bf16.bf16.f32 "
        "{%0,%1,%2,%3}, {%4,%5,%6,%7}, {%8,%9}, {%0,%1,%2,%3};"
        : "+f"(d[0]), "+f"(d[1]), "+f"(d[2]), "+f"(d[3])
        : "r"(a[0]), "r"(a[1]), "r"(a[2]), "r"(a[3]), "r"(b[0]), "r"(b[1]));
}
__device__ __forceinline__ uint32_t packbf2(float x, float y) {
    __nv_bfloat162 t = __float22bfloat162_rn(make_float2(x, y));
    return *(uint32_t*)&t;
}
__device__ __forceinline__ float gelu_exact(float x) {
    return 0.5f * x * (1.0f + erff(x * 0.7071067811865476f));
}

// ---------------------------------------------------------------------------
// Combined weight transpose
// ---------------------------------------------------------------------------
#define TW_QKV (3*CC*CC)
#define TW_PROJ (CC*CC)
#define TW_FC1 (CC*HIDDEN)
#define TW_FC2 (HIDDEN*CC)
#define TW_TOTAL (TW_QKV + TW_PROJ + TW_FC1 + TW_FC2)

__global__ void transpose_all(const float* __restrict__ qkv_w, const float* __restrict__ proj_w,
                              const float* __restrict__ fc1_w, const float* __restrict__ fc2_w) {
    int i = blockIdx.x * 256 + threadIdx.x;
    if (i >= TW_TOTAL) return;
    const float* w; __nv_bfloat16* wt; int K, N, off;
    if (i < TW_QKV) { w = qkv_w; wt = gb_wt_qkv; K = CC; N = 3 * CC; off = i; }
    else if (i < TW_QKV + TW_PROJ) { w = proj_w; wt = gb_wt_proj; K = CC; N = CC; off = i - TW_QKV; }
    else if (i < TW_QKV + TW_PROJ + TW_FC1) { w = fc1_w; wt = gb_wt_fc1; K = CC; N = HIDDEN; off = i - TW_QKV - TW_PROJ; }
    else { w = fc2_w; wt = gb_wt_fc2; K = HIDDEN; N = CC; off = i - TW_QKV - TW_PROJ - TW_FC1; }
    int k = off / N, n = off % N;
    wt[(size_t)n * K + k] = __float2bfloat16(w[off]);
}

// ---------------------------------------------------------------------------
// Position-bias MLP
// ---------------------------------------------------------------------------
__device__ __forceinline__ void ln_relu12(const float* p, float* q,
                                          const float* g, const float* b) {
    float s = 0.f, s2 = 0.f;
#pragma unroll
    for (int i = 0; i < POS_DIM; i++) { s += p[i]; s2 += p[i] * p[i]; }
    float mu = s / 12.0f;
    float var = s2 / 12.0f - mu * mu;
    float rs = rsqrtf(var + 1e-5f);
#pragma unroll
    for (int i = 0; i < POS_DIM; i++) q[i] = fmaxf((p[i] - mu) * rs * g[i] + b[i], 0.0f);
}

__global__ void pos_mlp_kernel(
    const float* __restrict__ pp_w, const float* __restrict__ pp_b,
    const float* __restrict__ p1_g, const float* __restrict__ p1_b,
    const float* __restrict__ p1_w, const float* __restrict__ p1_bias,
    const float* __restrict__ p2_g, const float* __restrict__ p2_b,
    const float* __restrict__ p2_w, const float* __restrict__ p2_bias,
    const float* __restrict__ p3_g, const float* __restrict__ p3_b,
    const float* __restrict__ p3_w, const float* __restrict__ p3_bias) {
    int t = blockIdx.x * blockDim.x + threadIdx.x;
    if (t >= POS_TAB) return;
    float bh = (float)(t / 15 - 7), bw = (float)(t % 15 - 7);
    float p[POS_DIM], q[POS_DIM];
#pragma unroll
    for (int j = 0; j < POS_DIM; j++) p[j] = bh * pp_w[j] + bw * pp_w[POS_DIM + j] + pp_b[j];
    ln_relu12(p, q, p1_g, p1_b);
#pragma unroll
    for (int j = 0; j < POS_DIM; j++) {
        float s = p1_bias[j];
#pragma unroll
        for (int i = 0; i < POS_DIM; i++) s += q[i] * p1_w[i * POS_DIM + j];
        p[j] = s;
    }
    ln_relu12(p, q, p2_g, p2_b);
#pragma unroll
    for (int j = 0; j < POS_DIM; j++) {
        float s = p2_bias[j];
#pragma unroll
        for (int i = 0; i < POS_DIM; i++) s += q[i] * p2_w[i * POS_DIM + j];
        p[j] = s;
    }
    ln_relu12(p, q, p3_g, p3_b);
#pragma unroll
    for (int h = 0; h < HEADS; h++) {
        float s = p3_bias[h];
#pragma unroll
        for (int i = 0; i < POS_DIM; i++) s += q[i] * p3_w[i * HEADS + h];
        g_pos[t * HEADS + h] = s;
    }
}

// ---------------------------------------------------------------------------
// Bias table: [type][h][r][j]
// ---------------------------------------------------------------------------
__global__ void bias_build() {
    int idx = blockIdx.x * 256 + threadIdx.x;
    if (idx >= 4 * HEADS * NWIN * NWIN) return;
    int j = idx & 63;
    int r = (idx >> 6) & 63;
    int h = (idx >> 12) % HEADS;
    int t = idx / (HEADS * NWIN * NWIN);
    int ry = r >> 3, rx = r & 7, jy = j >> 3, jx = j & 7;
    float bias = g_pos[(((ry - jy + 7) * 15) + (rx - jx + 7)) * HEADS + h];
    int lhr = (t & 2) ? (ry < (WS - SHIFT) ? 1 : 2) : 0;
    int lhj = (t & 2) ? (jy < (WS - SHIFT) ? 1 : 2) : 0;
    int lwr = (t & 1) ? (rx < (WS - SHIFT) ? 1 : 2) : 0;
    int lwj = (t & 1) ? (jx < (WS - SHIFT) ? 1 : 2) : 0;
    if (lhr != lhj || lwr != lwj) bias -= 100.0f;
    g_bias[idx] = bias;
}

// ---------------------------------------------------------------------------
// LayerNorm1: warp per row, fp32 in -> bf16 out, shift+window gather
// ---------------------------------------------------------------------------
__global__ void __launch_bounds__(256) ln1_kernel(
    const float* __restrict__ in, __nv_bfloat16* __restrict__ out,
    const float* __restrict__ gamma, const float* __restrict__ beta) {
    int warp = threadIdx.x >> 5, lane = threadIdx.x & 31;
    int row = blockIdx.x * 8 + warp;
    int bb = row >> 14, rem = row & 16383;
    int win = rem >> 6, r = rem & 63;
    int wy = win >> 4, wx = win & 15, ry = r >> 3, rx = r & 7;
    int hh = (wy * WS + ry + SHIFT) & 127;
    int ww = (wx * WS + rx + SHIFT) & 127;
    size_t src = (size_t)bb * LL + hh * WW_ + ww;

    const float* p = in + src * CC;
    float v[6], s = 0.f, s2 = 0.f;
#pragma unroll
    for (int k = 0; k < 6; k++) { v[k] = p[lane + 32 * k]; s += v[k]; s2 += v[k] * v[k]; }
#pragma unroll
    for (int o = 16; o > 0; o >>= 1) {
        s += __shfl_xor_sync(0xFFFFFFFFu, s, o);
        s2 += __shfl_xor_sync(0xFFFFFFFFu, s2, o);
    }
    float mu = s * (1.0f / 192.0f);
    float rs = rsqrtf(s2 * (1.0f / 192.0f) - mu * mu + 1e-5f);
    __nv_bfloat16* q = out + (size_t)row * CC;
#pragma unroll
    for (int k = 0; k < 6; k++) {
        int c = lane + 32 * k;
        q[c] = __float2bfloat16((v[k] - mu) * rs * gamma[c] + beta[c]);
    }
}

#define CH_PER_BUF (192 * 8)

// ---------------------------------------------------------------------------
// K=192 GEMM: 128x64 tile, 8 warps, TRIPLE buffer, full-K prefetch.
// All 3 chunk loads issued in prologue; mainloop = wait/sync/mma only.
// EPI 0: +bias, Q-scale cols<192 -> bf16   1: gelu(+bias) -> bf16
// 72KB dynamic smem, 3 CTAs/SM.
// ---------------------------------------------------------------------------
#define K192_SMEM (3 * CH_PER_BUF * 16)

template <int EPI>
__global__ void __launch_bounds__(256) gemm_k192(
    const __nv_bfloat16* __restrict__ A, const __nv_bfloat16* __restrict__ BT,
    const float* __restrict__ bias, void* __restrict__ outv, int NOUT) {
    extern __shared__ __align__(16) uint4 ksmq[];
    uint32_t sbase = smem_u32(ksmq);
    int tid = threadIdx.x;
    int wid = tid >> 5, lane = tid & 31;
    int wm = wid & 3, wn = wid >> 2;
    int m0 = blockIdx.y * 128, n0 = blockIdx.x * 64;
    const __nv_bfloat16* Ab = A + (size_t)m0 * CC;
    const __nv_bfloat16* Bb = BT + (size_t)n0 * CC;

    float acc[2][4][4];
#pragma unroll
    for (int i = 0; i < 2; i++)
#pragma unroll
        for (int j = 0; j < 4; j++)
#pragma unroll
            for (int k = 0; k < 4; k++) acc[i][j][k] = 0.f;

    int a_row = tid >> 1;
    int a_ch0 = (tid & 1) * 4;
    int b_row = tid >> 2;
    int b_ch0 = (tid & 3) * 2;

    int l15 = lane & 15, lhi = lane >> 4;
    int a_lrow = wm * 32 + l15;
    int a_sw = l15 & 7;
    int b_lrow = 128 + wn * 32 + (lhi << 3) + (lane & 7);
    int b_sw = lane & 7;
    int b_chlo = (lane >> 3) & 1;

    // prologue: issue ALL 3 chunks (3 commit groups)
#pragma unroll
    for (int c = 0; c < 3; c++) {
        uint32_t dst = sbase + c * CH_PER_BUF * 16;
        int k0 = c << 6;
#pragma unroll
        for (int i = 0; i < 4; i++) {
            int ch = a_ch0 + i;
            cpasync16(dst + (a_row * 8 + (ch ^ (a_row & 7))) * 16,
                      Ab + (size_t)a_row * CC + k0 + ch * 8);
        }
#pragma unroll
        for (int i = 0; i < 2; i++) {
            int ch = b_ch0 + i;
            cpasync16(dst + ((128 + b_row) * 8 + (ch ^ (b_row & 7))) * 16,
                      Bb + (size_t)b_row * CC + k0 + ch * 8);
        }
        cp_commit();
    }

#pragma unroll
    for (int c = 0; c < 3; c++) {
        if (c == 0)      asm volatile("cp.async.wait_group 2;" ::: "memory");
        else if (c == 1) asm volatile("cp.async.wait_group 1;" ::: "memory");
        else             asm volatile("cp.async.wait_group 0;" ::: "memory");
        __syncthreads();

        uint32_t buf = sbase + c * CH_PER_BUF * 16;
#pragma unroll
        for (int ks = 0; ks < 4; ks++) {
            uint32_t a[2][4], b[2][4];
            int achk = 2 * ks + lhi;
#pragma unroll
            for (int mt = 0; mt < 2; mt++) {
                uint32_t idx = (a_lrow + mt * 16) * 8 + (achk ^ a_sw);
                ldsm_x4(buf + idx * 16, a[mt]);
            }
            int bchk = 2 * ks + b_chlo;
#pragma unroll
            for (int nt16 = 0; nt16 < 2; nt16++) {
                uint32_t idx = (b_lrow + nt16 * 16) * 8 + (bchk ^ b_sw);
                ldsm_x4(buf + idx * 16, b[nt16]);
            }
#pragma unroll
            for (int mt = 0; mt < 2; mt++) {
#pragma unroll
                for (int nt16 = 0; nt16 < 2; nt16++) {
                    mma_bf16(acc[mt][nt16 * 2 + 0], a[mt], &b[nt16][0]);
                    mma_bf16(acc[mt][nt16 * 2 + 1], a[mt], &b[nt16][2]);
                }
            }
        }
        // no trailing sync: buffers are never overwritten
    }

#pragma unroll
    for (int mt = 0; mt < 2; mt++) {
        int g0 = m0 + wm * 32 + mt * 16 + (lane >> 2);
        int g1 = g0 + 8;
        size_t ob0 = (size_t)g0 * NOUT;
        size_t ob1 = (size_t)g1 * NOUT;
#pragma unroll
        for (int nt = 0; nt < 4; nt++) {
            int col = n0 + wn * 32 + nt * 8 + 2 * (lane & 3);
            float b0 = bias[col], b1 = bias[col + 1];
            float2 v0 = make_float2(acc[mt][nt][0] + b0, acc[mt][nt][1] + b1);
            float2 v1 = make_float2(acc[mt][nt][2] + b0, acc[mt][nt][3] + b1);
            if (EPI == 0) {
                float sc = (col < CC) ? QSCALE : 1.0f;
                v0.x *= sc; v0.y *= sc; v1.x *= sc; v1.y *= sc;
            }
            if (EPI == 1) {
                v0.x = gelu_exact(v0.x); v0.y = gelu_exact(v0.y);
                v1.x = gelu_exact(v1.x); v1.y = gelu_exact(v1.y);
            }
            __nv_bfloat16* out = (__nv_bfloat16*)outv;
            *(__nv_bfloat162*)(out + ob0 + col) = __float22bfloat162_rn(v0);
            *(__nv_bfloat162*)(out + ob1 + col) = __float22bfloat162_rn(v1);
        }
    }
}

// ---------------------------------------------------------------------------
// Generic bf16 GEMM (round-7 v2, double buffer): used for FC2 (K=768).
// EPI 3: +bias +res -> fp32
// ---------------------------------------------------------------------------
template <int EPI>
__global__ void __launch_bounds__(256) gemm_mma(
    const __nv_bfloat16* __restrict__ A, const __nv_bfloat16* __restrict__ BT,
    const float* __restrict__ bias, const float* __restrict__ res,
    void* __restrict__ outv, int K, int NOUT) {
    __shared__ __align__(16) uint4 smq[2 * CH_PER_BUF];
    uint32_t sbase = smem_u32(smq);
    int tid = threadIdx.x;
    int wid = tid >> 5, lane = tid & 31;
    int wm = wid & 3, wn = wid >> 2;
    int m0 = blockIdx.y * 128, n0 = blockIdx.x * 64;
    const __nv_bfloat16* Ab = A + (size_t)m0 * K;
    const __nv_bfloat16* Bb = BT + (size_t)n0 * K;
    int NCH = K >> 6;

    float acc[2][4][4];
#pragma unroll
    for (int i = 0; i < 2; i++)
#pragma unroll
        for (int j = 0; j < 4; j++)
#pragma unroll
            for (int k = 0; k < 4; k++) acc[i][j][k] = 0.f;

    int a_row = tid >> 1;
    int a_ch0 = (tid & 1) * 4;
    int b_row = tid >> 2;
    int b_ch0 = (tid & 3) * 2;

    int l15 = lane & 15, lhi = lane >> 4;
    int a_lrow = wm * 32 + l15;
    int a_sw = l15 & 7;
    int b_lrow = 128 + wn * 32 + (lhi << 3) + (lane & 7);
    int b_sw = lane & 7;
    int b_chlo = (lane >> 3) & 1;

    {
        uint32_t dst = sbase;
#pragma unroll
        for (int i = 0; i < 4; i++) {
            int ch = a_ch0 + i;
            cpasync16(dst + (a_row * 8 + (ch ^ (a_row & 7))) * 16,
                      Ab + (size_t)a_row * K + ch * 8);
        }
#pragma unroll
        for (int i = 0; i < 2; i++) {
            int ch = b_ch0 + i;
            cpasync16(dst + ((128 + b_row) * 8 + (ch ^ (b_row & 7))) * 16,
                      Bb + (size_t)b_row * K + ch * 8);
        }
        cp_commit();
    }

    for (int c = 0; c < NCH; c++) {
        if (c + 1 < NCH) {
            int k0 = (c + 1) << 6;
            uint32_t dst = sbase + ((c + 1) & 1) * CH_PER_BUF * 16;
#pragma unroll
            for (int i = 0; i < 4; i++) {
                int ch = a_ch0 + i;
                cpasync16(dst + (a_row * 8 + (ch ^ (a_row & 7))) * 16,
                          Ab + (size_t)a_row * K + k0 + ch * 8);
            }
#pragma unroll
            for (int i = 0; i < 2; i++) {
                int ch = b_ch0 + i;
                cpasync16(dst + ((128 + b_row) * 8 + (ch ^ (b_row & 7))) * 16,
                          Bb + (size_t)b_row * K + k0 + ch * 8);
            }
        }
        cp_commit();
        cp_wait1();
        __syncthreads();

        uint32_t buf = sbase + (c & 1) * CH_PER_BUF * 16;
#pragma unroll
        for (int ks = 0; ks < 4; ks++) {
            uint32_t a[2][4], b[2][4];
            int achk = 2 * ks + lhi;
#pragma unroll
            for (int mt = 0; mt < 2; mt++) {
                uint32_t idx = (a_lrow + mt * 16) * 8 + (achk ^ a_sw);
                ldsm_x4(buf + idx * 16, a[mt]);
            }
            int bchk = 2 * ks + b_chlo;
#pragma unroll
            for (int nt16 = 0; nt16 < 2; nt16++) {
                uint32_t idx = (b_lrow + nt16 * 16) * 8 + (bchk ^ b_sw);
                ldsm_x4(buf + idx * 16, b[nt16]);
            }
#pragma unroll
            for (int mt = 0; mt < 2; mt++) {
#pragma unroll
                for (int nt16 = 0; nt16 < 2; nt16++) {
                    mma_bf16(acc[mt][nt16 * 2 + 0], a[mt], &b[nt16][0]);
                    mma_bf16(acc[mt][nt16 * 2 + 1], a[mt], &b[nt16][2]);
                }
            }
        }
        __syncthreads();
    }

#pragma unroll
    for (int mt = 0; mt < 2; mt++) {
        int g0 = m0 + wm * 32 + mt * 16 + (lane >> 2);
        int g1 = g0 + 8;
        size_t ob0 = (size_t)g0 * NOUT;
        size_t ob1 = (size_t)g1 * NOUT;
#pragma unroll
        for (int nt = 0; nt < 4; nt++) {
            int col = n0 + wn * 32 + nt * 8 + 2 * (lane & 3);
            float b0 = bias[col], b1 = bias[col + 1];
            float2 v0 = make_float2(acc[mt][nt][0] + b0, acc[mt][nt][1] + b1);
            float2 v1 = make_float2(acc[mt][nt][2] + b0, acc[mt][nt][3] + b1);
            if (EPI == 3) {
                float* out = (float*)outv;
                float2 r0 = *(const float2*)(res + ob0 + col);
                float2 r1 = *(const float2*)(res + ob1 + col);
                v0.x += r0.x; v0.y += r0.y;
                v1.x += r1.x; v1.y += r1.y;
                *(float2*)(out + ob0 + col) = v0;
                *(float2*)(out + ob1 + col) = v1;
            } else {
                __nv_bfloat16* out = (__nv_bfloat16*)outv;
                *(__nv_bfloat162*)(out + ob0 + col) = __float22bfloat162_rn(v0);
                *(__nv_bfloat162*)(out + ob1 + col) = __float22bfloat162_rn(v1);
            }
        }
    }
}

// ---------------------------------------------------------------------------
// Proj GEMM + scatter + residual + LN2 (fused)
// ---------------------------------------------------------------------------
#define PCH_PER_BUF (320 * 8)
#define PROJ_SMEM (2 * PCH_PER_BUF * 16)

__global__ void __launch_bounds__(256) gemm_proj_ln(
    const __nv_bfloat16* __restrict__ A, const __nv_bfloat16* __restrict__ BT,
    const float* __restrict__ bias, const float* __restrict__ x,
    float* __restrict__ y, __nv_bfloat16* __restrict__ ln2out,
    const float* __restrict__ n2g, const float* __restrict__ n2b) {
    extern __shared__ __align__(16) uint4 psm[];
    uint32_t sbase = smem_u32(psm);
    int tid = threadIdx.x;
    int wid = tid >> 5, lane = tid & 31;
    int m0 = blockIdx.x * 128;
    const __nv_bfloat16* Ab = A + (size_t)m0 * CC;

    float acc[24][4];
#pragma unroll
    for (int j = 0; j < 24; j++)
#pragma unroll
        for (int k = 0; k < 4; k++) acc[j][k] = 0.f;

    int a_row = tid >> 1;
    int a_ch0 = (tid & 1) * 4;
    int b_row = tid >> 2;
    int b_ch0 = (tid & 3) * 2;

    int l15 = lane & 15, lhi = lane >> 4;
    int a_lrow = wid * 16 + l15;
    int a_sw = l15 & 7;
    int b_lbase = 128 + (lhi << 3) + (lane & 7);
    int b_sw = lane & 7;
    int b_chlo = (lane >> 3) & 1;

    {
        uint32_t dst = sbase;
#pragma unroll
        for (int i = 0; i < 4; i++) {
            int ch = a_ch0 + i;
            cpasync16(dst + (a_row * 8 + (ch ^ (a_row & 7))) * 16,
                      Ab + (size_t)a_row * CC + ch * 8);
        }
#pragma unroll
        for (int r3 = 0; r3 < 3; r3++) {
            int row = r3 * 64 + b_row;
#pragma unroll
            for (int i = 0; i < 2; i++) {
                int ch = b_ch0 + i;
                cpasync16(dst + ((128 + row) * 8 + (ch ^ (row & 7))) * 16,
                          BT + (size_t)row * CC + ch * 8);
            }
        }
        cp_commit();
    }

    for (int c = 0; c < 3; c++) {
        if (c + 1 < 3) {
            int k0 = (c + 1) << 6;
            uint32_t dst = sbase + ((c + 1) & 1) * PCH_PER_BUF * 16;
#pragma unroll
            for (int i = 0; i < 4; i++) {
                int ch = a_ch0 + i;
                cpasync16(dst + (a_row * 8 + (ch ^ (a_row & 7))) * 16,
                          Ab + (size_t)a_row * CC + k0 + ch * 8);
            }
#pragma unroll
            for (int r3 = 0; r3 < 3; r3++) {
                int row = r3 * 64 + b_row;
#pragma unroll
                for (int i = 0; i < 2; i++) {
                    int ch = b_ch0 + i;
                    cpasync16(dst + ((128 + row) * 8 + (ch ^ (row & 7))) * 16,
                              BT + (size_t)row * CC + k0 + ch * 8);
                }
            }
        }
        cp_commit();
        cp_wait1();
        __syncthreads();

        uint32_t buf = sbase + (c & 1) * PCH_PER_BUF * 16;
#pragma unroll
        for (int ks = 0; ks < 4; ks++) {
            uint32_t a[4];
            int achk = 2 * ks + lhi;
            ldsm_x4(buf + (a_lrow * 8 + (achk ^ a_sw)) * 16, a);
            int bchk = 2 * ks + b_chlo;
#pragma unroll
            for (int nt16 = 0; nt16 < 12; nt16++) {
                uint32_t b[4];
                ldsm_x4(buf + ((b_lbase + nt16 * 16) * 8 + (bchk ^ b_sw)) * 16, b);
                mma_bf16(acc[nt16 * 2 + 0], a, &b[0]);
                mma_bf16(acc[nt16 * 2 + 1], a, &b[2]);
            }
        }
        __syncthreads();
    }

    int lq = lane & 3;
#pragma unroll
    for (int half = 0; half < 2; half++) {
        int g = m0 + wid * 16 + (lane >> 2) + half * 8;
        int bb = g >> 14, rem = g & 16383;
        int win = rem >> 6, rr = rem & 63;
        int wy = win >> 4, wx = win & 15, ry = rr >> 3, rx = rr & 7;
        int hh = (wy * WS + ry + SHIFT) & 127;
        int ww = (wx * WS + rx + SHIFT) & 127;
        size_t ob = ((size_t)bb * LL + hh * WW_ + ww) * CC;

        float vals[48];
        float s = 0.f, s2 = 0.f;
#pragma unroll
        for (int nt = 0; nt < 24; nt++) {
            int col = nt * 8 + 2 * lq;
            float v0 = acc[nt][half * 2 + 0] + bias[col];
            float v1 = acc[nt][half * 2 + 1] + bias[col + 1];
            float2 rv = *(const float2*)(x + ob + col);
            v0 += rv.x; v1 += rv.y;
            *(float2*)(y + ob + col) = make_float2(v0, v1);
            s += v0 + v1;
            s2 += v0 * v0 + v1 * v1;
            vals[nt * 2] = v0; vals[nt * 2 + 1] = v1;
        }
        s += __shfl_xor_sync(0xFFFFFFFFu, s, 1);
        s2 += __shfl_xor_sync(0xFFFFFFFFu, s2, 1);
        s += __shfl_xor_sync(0xFFFFFFFFu, s, 2);
        s2 += __shfl_xor_sync(0xFFFFFFFFu, s2, 2);
        float mu = s * (1.0f / 192.0f);
        float rs = rsqrtf(s2 * (1.0f / 192.0f) - mu * mu + 1e-5f);
#pragma unroll
        for (int nt = 0; nt < 24; nt++) {
            int col = nt * 8 + 2 * lq;
            float2 gg = *(const float2*)(n2g + col);
            float2 bb2 = *(const float2*)(n2b + col);
            float2 o;
            o.x = (vals[nt * 2] - mu) * rs * gg.x + bb2.x;
            o.y = (vals[nt * 2 + 1] - mu) * rs * gg.y + bb2.y;
            *(__nv_bfloat162*)(ln2out + ob + col) = __float22bfloat162_rn(o);
        }
    }
}

// ---------------------------------------------------------------------------
// Tensor-core windowed attention (round-7 version, unchanged)
// ---------------------------------------------------------------------------
#define KSTR 200
#define VSTR 72
#define ATTN_SMEM ((NWIN * KSTR + CC * VSTR) * 2)

__global__ void __launch_bounds__(384) attn_kernel(
    const __nv_bfloat16* __restrict__ qkv, __nv_bfloat16* __restrict__ outp) {
    extern __shared__ __nv_bfloat16 smh[];
    __nv_bfloat16* k_s = smh;
    __nv_bfloat16* vt_s = smh + NWIN * KSTR;

    int w = blockIdx.x;
    int tid = threadIdx.x;
    int lane = tid & 31, wid = tid >> 5;
    const __nv_bfloat16* base = qkv + (size_t)w * NWIN * 576;

    for (int idx = tid; idx < NWIN * 24; idx += 384) {
        int j = idx / 24, c = idx % 24;
        uint4 uk = *(const uint4*)(base + (size_t)j * 576 + 192 + c * 8);
        *(uint4*)(k_s + j * KSTR + c * 8) = uk;
        uint4 uv = *(const uint4*)(base + (size_t)j * 576 + 384 + c * 8);
        const unsigned short* e = (const unsigned short*)&uv;
#pragma unroll
        for (int i = 0; i < 8; i++) {
            int k = (i + lane) & 7;
            *((unsigned short*)vt_s + (c * 8 + k) * VSTR + j) = e[k];
        }
    }
    __syncthreads();

    int h = wid >> 1;
    int mbase = (wid & 1) * 32;
    int winloc = w & 255;
    int wy = winloc >> 4, wx = winloc & 15;
    int type = ((wy == 15) ? 2 : 0) | ((wx == 15) ? 1 : 0);
    const float* btab = g_bias + ((size_t)(type * HEADS + h) * NWIN) * NWIN;

    int rq = lane >> 2, cq = 2 * (lane & 3);
    int brow = ((lane >> 4) << 3) + (lane & 7);
    int bchlo = (lane >> 3) & 1;

    uint32_t a[2][2][4];
#pragma unroll
    for (int mt = 0; mt < 2; mt++)
#pragma unroll
        for (int ks = 0; ks < 2; ks++)
#pragma unroll
            for (int i = 0; i < 4; i++) {
                int row = mbase + mt * 16 + rq + (i & 1) * 8;
                int col = h * HD + ks * 16 + cq + (i >> 1) * 8;
                a[mt][ks][i] = *(const uint32_t*)(base + (size_t)row * 576 + col);
            }

    float p[2][8][4];
#pragma unroll
    for (int i = 0; i < 2; i++)
#pragma unroll
        for (int j = 0; j < 8; j++)
#pragma unroll
            for (int k = 0; k < 4; k++) p[i][j][k] = 0.f;

    uint32_t ksm = smem_u32(k_s);
#pragma unroll
    for (int kg = 0; kg < 4; kg++) {
#pragma unroll
        for (int ks = 0; ks < 2; ks++) {
            uint32_t b[4];
            uint32_t addr = ksm + ((kg * 16 + brow) * KSTR + (h * 4 + ks * 2 + bchlo) * 8) * 2;
            ldsm_x4(addr, b);
#pragma unroll
            for (int mt = 0; mt < 2; mt++) {
                mma_bf16(p[mt][kg * 2 + 0], a[mt][ks], &b[0]);
                mma_bf16(p[mt][kg * 2 + 1], a[mt][ks], &b[2]);
            }
        }
    }

    float sums[2][2];
#pragma unroll
    for (int mt = 0; mt < 2; mt++) {
#pragma unroll
        for (int rl = 0; rl < 2; rl++) {
            int r = mbase + mt * 16 + rq + rl * 8;
            const float* br_ = btab + r * NWIN;
            float m = -1e30f;
#pragma unroll
            for (int nt = 0; nt < 8; nt++) {
                float2 bv = *(const float2*)(br_ + nt * 8 + cq);
                p[mt][nt][rl * 2 + 0] += bv.x;
                p[mt][nt][rl * 2 + 1] += bv.y;
                m = fmaxf(m, fmaxf(p[mt][nt][rl * 2], p[mt][nt][rl * 2 + 1]));
            }
            m = fmaxf(m, __shfl_xor_sync(0xFFFFFFFFu, m, 1));
            m = fmaxf(m, __shfl_xor_sync(0xFFFFFFFFu, m, 2));
            float s = 0.f;
#pragma unroll
            for (int nt = 0; nt < 8; nt++) {
                float e0 = __expf(p[mt][nt][rl * 2] - m);
                float e1 = __expf(p[mt][nt][rl * 2 + 1] - m);
                p[mt][nt][rl * 2] = e0; p[mt][nt][rl * 2 + 1] = e1;
                s += e0 + e1;
            }
            s += __shfl_xor_sync(0xFFFFFFFFu, s, 1);
            s += __shfl_xor_sync(0xFFFFFFFFu, s, 2);
            sums[mt][rl] = s;
        }
    }

    uint32_t pa[2][4][4];
#pragma unroll
    for (int mt = 0; mt < 2; mt++)
#pragma unroll
        for (int s4 = 0; s4 < 4; s4++) {
            pa[mt][s4][0] = packbf2(p[mt][2 * s4][0], p[mt][2 * s4][1]);
            pa[mt][s4][1] = packbf2(p[mt][2 * s4][2], p[mt][2 * s4][3]);
            pa[mt][s4][2] = packbf2(p[mt][2 * s4 + 1][0], p[mt][2 * s4 + 1][1]);
            pa[mt][s4][3] = packbf2(p[mt][2 * s4 + 1][2], p[mt][2 * s4 + 1][3]);
        }

    float o[2][4][4];
#pragma unroll
    for (int i = 0; i < 2; i++)
#pragma unroll
        for (int j = 0; j < 4; j++)
#pragma unroll
            for (int k = 0; k < 4; k++) o[i][j][k] = 0.f;

    uint32_t vsm = smem_u32(vt_s);
#pragma unroll
    for (int s4 = 0; s4 < 4; s4++) {
#pragma unroll
        for (int n16 = 0; n16 < 2; n16++) {
            uint32_t b[4];
            uint32_t addr = vsm + ((h * HD + n16 * 16 + brow) * VSTR + (s4 * 2 + bchlo) * 8) * 2;
            ldsm_x4(addr, b);
#pragma unroll
            for (int mt = 0; mt < 2; mt++) {
                mma_bf16(o[mt][n16 * 2 + 0], pa[mt][s4], &b[0]);
                mma_bf16(o[mt][n16 * 2 + 1], pa[mt][s4], &b[2]);
            }
        }
    }

#pragma unroll
    for (int mt = 0; mt < 2; mt++) {
        float i0 = 1.0f / sums[mt][0];
        float i1 = 1.0f / sums[mt][1];
        int r0 = mbase + mt * 16 + rq;
        __nv_bfloat16* op0 = outp + (size_t)(w * NWIN + r0) * CC + h * HD;
        __nv_bfloat16* op1 = op0 + 8 * CC;
#pragma unroll
        for (int nt = 0; nt < 4; nt++) {
            *(__nv_bfloat162*)(op0 + nt * 8 + cq) =
                __float22bfloat162_rn(make_float2(o[mt][nt][0] * i0, o[mt][nt][1] * i0));
            *(__nv_bfloat162*)(op1 + nt * 8 + cq) =
                __float22bfloat162_rn(make_float2(o[mt][nt][2] * i1, o[mt][nt][3] * i1));
        }
    }
}

// ---------------------------------------------------------------------------
// Launch
// ---------------------------------------------------------------------------
extern "C" void kernel_launch(void* const* d_in, const int* in_sizes, int n_in,
                              void* d_out, int out_size) {
    const float* x      = (const float*)d_in[0];
    const float* n1_g   = (const float*)d_in[4];
    const float* n1_b   = (const float*)d_in[5];
    const float* qkv_w  = (const float*)d_in[6];
    const float* qkv_b  = (const float*)d_in[7];
    const float* proj_w = (const float*)d_in[8];
    const float* proj_b = (const float*)d_in[9];
    const float* pp_w   = (const float*)d_in[10];
    const float* pp_b   = (const float*)d_in[11];
    const float* p1_g   = (const float*)d_in[12];
    const float* p1_b   = (const float*)d_in[13];
    const float* p1_w   = (const float*)d_in[14];
    const float* p1_bi  = (const float*)d_in[15];
    const float* p2_g   = (const float*)d_in[16];
    const float* p2_b   = (const float*)d_in[17];
    const float* p2_w   = (const float*)d_in[18];
    const float* p2_bi  = (const float*)d_in[19];
    const float* p3_g   = (const float*)d_in[20];
    const float* p3_b   = (const float*)d_in[21];
    const float* p3_w   = (const float*)d_in[22];
    const float* p3_bi  = (const float*)d_in[23];
    const float* n2_g   = (const float*)d_in[24];
    const float* n2_b   = (const float*)d_in[25];
    const float* fc1_w  = (const float*)d_in[26];
    const float* fc1_b  = (const float*)d_in[27];
    const float* fc2_w  = (const float*)d_in[28];
    const float* fc2_b  = (const float*)d_in[29];
    float* out = (float*)d_out;

    __nv_bfloat16 *xw, *qkv, *attn, *ln2, *hid;
    __nv_bfloat16 *wt_qkv, *wt_proj, *wt_fc1, *wt_fc2;
    cudaGetSymbolAddress((void**)&xw,   gb_xw);
    cudaGetSymbolAddress((void**)&qkv,  gb_qkv);
    cudaGetSymbolAddress((void**)&attn, gb_attn);
    cudaGetSymbolAddress((void**)&ln2,  gb_ln2);
    cudaGetSymbolAddress((void**)&hid,  gb_hid);
    cudaGetSymbolAddress((void**)&wt_qkv,  gb_wt_qkv);
    cudaGetSymbolAddress((void**)&wt_proj, gb_wt_proj);
    cudaGetSymbolAddress((void**)&wt_fc1,  gb_wt_fc1);
    cudaGetSymbolAddress((void**)&wt_fc2,  gb_wt_fc2);

    static bool attr_set = false;
    if (!attr_set) {
        cudaFuncSetAttribute(attn_kernel, cudaFuncAttributeMaxDynamicSharedMemorySize,
                             ATTN_SMEM);
        cudaFuncSetAttribute(gemm_proj_ln, cudaFuncAttributeMaxDynamicSharedMemorySize,
                             PROJ_SMEM);
        cudaFuncSetAttribute(gemm_k192<0>, cudaFuncAttributeMaxDynamicSharedMemorySize,
                             K192_SMEM);
        cudaFuncSetAttribute(gemm_k192<1>, cudaFuncAttributeMaxDynamicSharedMemorySize,
                             K192_SMEM);
        attr_set = true;
    }

    // 0. weight transposes
    transpose_all<<<(TW_TOTAL + 255) / 256, 256>>>(qkv_w, proj_w, fc1_w, fc2_w);

    // 1. position-bias MLP + bias table
    pos_mlp_kernel<<<1, 256>>>(pp_w, pp_b, p1_g, p1_b, p1_w, p1_bi,
                               p2_g, p2_b, p2_w, p2_bi, p3_g, p3_b, p3_w, p3_bi);
    bias_build<<<(4 * HEADS * NWIN * NWIN + 255) / 256, 256>>>();

    // 2. LN1 + shift + window partition -> bf16
    ln1_kernel<<<MROWS / 8, 256>>>(x, xw, n1_g, n1_b);

    // 3. QKV GEMM (K=192, triple-buffer full prefetch) -> bf16, Q pre-scaled
    gemm_k192<0><<<dim3(576 / 64, MROWS / 128), 256, K192_SMEM>>>(xw, wt_qkv, qkv_b, qkv, 576);

    // 4. tensor-core attention -> bf16
    attn_kernel<<<NWINDOWS, 384, ATTN_SMEM>>>(qkv, attn);

    // 5. proj + scatter + residual + LN2 (fused)
    gemm_proj_ln<<<MROWS / 128, 256, PROJ_SMEM>>>(attn, wt_proj, proj_b, x, out, ln2, n2_g, n2_b);

    // 6. FC1 + GELU (K=192, triple-buffer full prefetch) -> bf16
    gemm_k192<1><<<dim3(HIDDEN / 64, MROWS / 128), 256, K192_SMEM>>>(ln2, wt_fc1, fc1_b, hid, HIDDEN);

    // 7. FC2 + residual -> fp32 out (round-7 tiled config, K=768)
    gemm_mma<3><<<dim3(CC / 64, MROWS / 128), 256>>>(hid, wt_fc2, fc2_b, out, out, HIDDEN, CC);
}

// round 12
// speedup vs baseline: 1.2237x; 1.0047x over previous
#include <cuda_runtime.h>
#include <cuda_bf16.h>
#include <math.h>
#include <stdint.h>

// ---------------------------------------------------------------------------
// Problem constants
// ---------------------------------------------------------------------------
#define BATCH   8
#define HH      128
#define WW_     128
#define LL      (HH*WW_)
#define CC      192
#define HEADS   6
#define HD      32
#define WS      8
#define NWIN    64
#define SHIFT   4
#define HIDDEN  768
#define MROWS   (BATCH*LL)                 // 131072
#define NWINDOWS (BATCH*(HH/WS)*(WW_/WS))  // 2048
#define POS_DIM 12
#define POS_TAB 225
#define QSCALE  0.17677669529663687f

// ---------------------------------------------------------------------------
// Device scratch
// ---------------------------------------------------------------------------
__device__ __nv_bfloat16 gb_xw[(size_t)MROWS * CC];
__device__ __nv_bfloat16 gb_qkv[(size_t)MROWS * 3 * CC];
__device__ __nv_bfloat16 gb_attn[(size_t)MROWS * CC];
__device__ __nv_bfloat16 gb_ln2[(size_t)MROWS * CC];
__device__ __nv_bfloat16 gb_hid[(size_t)MROWS * HIDDEN];
__device__ float g_pos[POS_TAB * HEADS];
__device__ float g_bias[4 * HEADS * NWIN * NWIN];   // [type][h][r][j]
__device__ __nv_bfloat16 gb_wt_qkv[3 * CC * CC];
__device__ __nv_bfloat16 gb_wt_proj[CC * CC];
__device__ __nv_bfloat16 gb_wt_fc1[HIDDEN * CC];
__device__ __nv_bfloat16 gb_wt_fc2[CC * HIDDEN];

// ---------------------------------------------------------------------------
// Helpers
// ---------------------------------------------------------------------------
__device__ __forceinline__ uint32_t smem_u32(const void* p) {
    uint32_t a;
    asm("{ .reg .u64 t; cvta.to.shared.u64 t, %1; cvt.u32.u64 %0, t; }" : "=r"(a) : "l"(p));
    return a;
}
__device__ __forceinline__ void cpasync16(uint32_t s, const void* g) {
    asm volatile("cp.async.cg.shared.global [%0], [%1], 16;" :: "r"(s), "l"(g));
}
__device__ __forceinline__ void cp_commit() {
    asm volatile("cp.async.commit_group;" ::: "memory");
}
__device__ __forceinline__ void cp_wait1() {
    asm volatile("cp.async.wait_group 1;" ::: "memory");
}
__device__ __forceinline__ void ldsm_x4(uint32_t addr, uint32_t* r) {
    asm volatile("ldmatrix.sync.aligned.m8n8.x4.shared.b16 {%0,%1,%2,%3}, [%4];"
                 : "=r"(r[0]), "=r"(r[1]), "=r"(r[2]), "=r"(r[3]) : "r"(addr));
}
__device__ __forceinline__ void mma_bf16(float* d, const uint32_t* a, const uint32_t* b) {
    asm volatile(
        "mma.sync.aligned.m16n8k16.row.col.f32.bf16.bf16.f32 "
        "{%0,%1,%2,%3}, {%4,%5,%6,%7}, {%8,%9}, {%0,%1,%2,%3};"
        : "+f"(d[0]), "+f"(d[1]), "+f"(d[2]), "+f"(d[3])
        : "r"(a[0]), "r"(a[1]), "r"(a[2]), "r"(a[3]), "r"(b[0]), "r"(b[1]));
}
__device__ __forceinline__ uint32_t packbf2(float x, float y) {
    __nv_bfloat162 t = __float22bfloat162_rn(make_float2(x, y));
    return *(uint32_t*)&t;
}
__device__ __forceinline__ float gelu_exact(float x) {
    return 0.5f * x * (1.0f + erff(x * 0.7071067811865476f));
}

// ---------------------------------------------------------------------------
// Combined weight transpose
// ---------------------------------------------------------------------------
#define TW_QKV (3*CC*CC)
#define TW_PROJ (CC*CC)
#define TW_FC1 (CC*HIDDEN)
#define TW_FC2 (HIDDEN*CC)
#define TW_TOTAL (TW_QKV + TW_PROJ + TW_FC1 + TW_FC2)

__global__ void transpose_all(const float* __restrict__ qkv_w, const float* __restrict__ proj_w,
                              const float* __restrict__ fc1_w, const float* __restrict__ fc2_w) {
    int i = blockIdx.x * 256 + threadIdx.x;
    if (i >= TW_TOTAL) return;
    const float* w; __nv_bfloat16* wt; int K, N, off;
    if (i < TW_QKV) { w = qkv_w; wt = gb_wt_qkv; K = CC; N = 3 * CC; off = i; }
    else if (i < TW_QKV + TW_PROJ) { w = proj_w; wt = gb_wt_proj; K = CC; N = CC; off = i - TW_QKV; }
    else if (i < TW_QKV + TW_PROJ + TW_FC1) { w = fc1_w; wt = gb_wt_fc1; K = CC; N = HIDDEN; off = i - TW_QKV - TW_PROJ; }
    else { w = fc2_w; wt = gb_wt_fc2; K = HIDDEN; N = CC; off = i - TW_QKV - TW_PROJ - TW_FC1; }
    int k = off / N, n = off % N;
    wt[(size_t)n * K + k] = __float2bfloat16(w[off]);
}

// ---------------------------------------------------------------------------
// Position-bias MLP
// ---------------------------------------------------------------------------
__device__ __forceinline__ void ln_relu12(const float* p, float* q,
                                          const float* g, const float* b) {
    float s = 0.f, s2 = 0.f;
#pragma unroll
    for (int i = 0; i < POS_DIM; i++) { s += p[i]; s2 += p[i] * p[i]; }
    float mu = s / 12.0f;
    float var = s2 / 12.0f - mu * mu;
    float rs = rsqrtf(var + 1e-5f);
#pragma unroll
    for (int i = 0; i < POS_DIM; i++) q[i] = fmaxf((p[i] - mu) * rs * g[i] + b[i], 0.0f);
}

__global__ void pos_mlp_kernel(
    const float* __restrict__ pp_w, const float* __restrict__ pp_b,
    const float* __restrict__ p1_g, const float* __restrict__ p1_b,
    const float* __restrict__ p1_w, const float* __restrict__ p1_bias,
    const float* __restrict__ p2_g, const float* __restrict__ p2_b,
    const float* __restrict__ p2_w, const float* __restrict__ p2_bias,
    const float* __restrict__ p3_g, const float* __restrict__ p3_b,
    const float* __restrict__ p3_w, const float* __restrict__ p3_bias) {
    int t = blockIdx.x * blockDim.x + threadIdx.x;
    if (t >= POS_TAB) return;
    float bh = (float)(t / 15 - 7), bw = (float)(t % 15 - 7);
    float p[POS_DIM], q[POS_DIM];
#pragma unroll
    for (int j = 0; j < POS_DIM; j++) p[j] = bh * pp_w[j] + bw * pp_w[POS_DIM + j] + pp_b[j];
    ln_relu12(p, q, p1_g, p1_b);
#pragma unroll
    for (int j = 0; j < POS_DIM; j++) {
        float s = p1_bias[j];
#pragma unroll
        for (int i = 0; i < POS_DIM; i++) s += q[i] * p1_w[i * POS_DIM + j];
        p[j] = s;
    }
    ln_relu12(p, q, p2_g, p2_b);
#pragma unroll
    for (int j = 0; j < POS_DIM; j++) {
        float s = p2_bias[j];
#pragma unroll
        for (int i = 0; i < POS_DIM; i++) s += q[i] * p2_w[i * POS_DIM + j];
        p[j] = s;
    }
    ln_relu12(p, q, p3_g, p3_b);
#pragma unroll
    for (int h = 0; h < HEADS; h++) {
        float s = p3_bias[h];
#pragma unroll
        for (int i = 0; i < POS_DIM; i++) s += q[i] * p3_w[i * HEADS + h];
        g_pos[t * HEADS + h] = s;
    }
}

// ---------------------------------------------------------------------------
// Bias table: [type][h][r][j]
// ---------------------------------------------------------------------------
__global__ void bias_build() {
    int idx = blockIdx.x * 256 + threadIdx.x;
    if (idx >= 4 * HEADS * NWIN * NWIN) return;
    int j = idx & 63;
    int r = (idx >> 6) & 63;
    int h = (idx >> 12) % HEADS;
    int t = idx / (HEADS * NWIN * NWIN);
    int ry = r >> 3, rx = r & 7, jy = j >> 3, jx = j & 7;
    float bias = g_pos[(((ry - jy + 7) * 15) + (rx - jx + 7)) * HEADS + h];
    int lhr = (t & 2) ? (ry < (WS - SHIFT) ? 1 : 2) : 0;
    int lhj = (t & 2) ? (jy < (WS - SHIFT) ? 1 : 2) : 0;
    int lwr = (t & 1) ? (rx < (WS - SHIFT) ? 1 : 2) : 0;
    int lwj = (t & 1) ? (jx < (WS - SHIFT) ? 1 : 2) : 0;
    if (lhr != lhj || lwr != lwj) bias -= 100.0f;
    g_bias[idx] = bias;
}

// ---------------------------------------------------------------------------
// LayerNorm1: warp per row, fp32 in -> bf16 out, shift+window gather
// ---------------------------------------------------------------------------
__global__ void __launch_bounds__(256) ln1_kernel(
    const float* __restrict__ in, __nv_bfloat16* __restrict__ out,
    const float* __restrict__ gamma, const float* __restrict__ beta) {
    int warp = threadIdx.x >> 5, lane = threadIdx.x & 31;
    int row = blockIdx.x * 8 + warp;
    int bb = row >> 14, rem = row & 16383;
    int win = rem >> 6, r = rem & 63;
    int wy = win >> 4, wx = win & 15, ry = r >> 3, rx = r & 7;
    int hh = (wy * WS + ry + SHIFT) & 127;
    int ww = (wx * WS + rx + SHIFT) & 127;
    size_t src = (size_t)bb * LL + hh * WW_ + ww;

    const float* p = in + src * CC;
    float v[6], s = 0.f, s2 = 0.f;
#pragma unroll
    for (int k = 0; k < 6; k++) { v[k] = p[lane + 32 * k]; s += v[k]; s2 += v[k] * v[k]; }
#pragma unroll
    for (int o = 16; o > 0; o >>= 1) {
        s += __shfl_xor_sync(0xFFFFFFFFu, s, o);
        s2 += __shfl_xor_sync(0xFFFFFFFFu, s2, o);
    }
    float mu = s * (1.0f / 192.0f);
    float rs = rsqrtf(s2 * (1.0f / 192.0f) - mu * mu + 1e-5f);
    __nv_bfloat16* q = out + (size_t)row * CC;
#pragma unroll
    for (int k = 0; k < 6; k++) {
        int c = lane + 32 * k;
        q[c] = __float2bfloat16((v[k] - mu) * rs * gamma[c] + beta[c]);
    }
}

#define CH_PER_BUF (192 * 8)

// ---------------------------------------------------------------------------
// K=192 GEMM: 128x64 tile, 8 warps, TRIPLE buffer, full-K prefetch.
// EPI 0: +bias, Q-scale cols<192 -> bf16   1: gelu(+bias) -> bf16
// ---------------------------------------------------------------------------
#define K192_SMEM (3 * CH_PER_BUF * 16)

template <int EPI>
__global__ void __launch_bounds__(256) gemm_k192(
    const __nv_bfloat16* __restrict__ A, const __nv_bfloat16* __restrict__ BT,
    const float* __restrict__ bias, void* __restrict__ outv, int NOUT) {
    extern __shared__ __align__(16) uint4 ksmq[];
    uint32_t sbase = smem_u32(ksmq);
    int tid = threadIdx.x;
    int wid = tid >> 5, lane = tid & 31;
    int wm = wid & 3, wn = wid >> 2;
    int m0 = blockIdx.y * 128, n0 = blockIdx.x * 64;
    const __nv_bfloat16* Ab = A + (size_t)m0 * CC;
    const __nv_bfloat16* Bb = BT + (size_t)n0 * CC;

    float acc[2][4][4];
#pragma unroll
    for (int i = 0; i < 2; i++)
#pragma unroll
        for (int j = 0; j < 4; j++)
#pragma unroll
            for (int k = 0; k < 4; k++) acc[i][j][k] = 0.f;

    int a_row = tid >> 1;
    int a_ch0 = (tid & 1) * 4;
    int b_row = tid >> 2;
    int b_ch0 = (tid & 3) * 2;

    int l15 = lane & 15, lhi = lane >> 4;
    int a_lrow = wm * 32 + l15;
    int a_sw = l15 & 7;
    int b_lrow = 128 + wn * 32 + (lhi << 3) + (lane & 7);
    int b_sw = lane & 7;
    int b_chlo = (lane >> 3) & 1;

#pragma unroll
    for (int c = 0; c < 3; c++) {
        uint32_t dst = sbase + c * CH_PER_BUF * 16;
        int k0 = c << 6;
#pragma unroll
        for (int i = 0; i < 4; i++) {
            int ch = a_ch0 + i;
            cpasync16(dst + (a_row * 8 + (ch ^ (a_row & 7))) * 16,
                      Ab + (size_t)a_row * CC + k0 + ch * 8);
        }
#pragma unroll
        for (int i = 0; i < 2; i++) {
            int ch = b_ch0 + i;
            cpasync16(dst + ((128 + b_row) * 8 + (ch ^ (b_row & 7))) * 16,
                      Bb + (size_t)b_row * CC + k0 + ch * 8);
        }
        cp_commit();
    }

#pragma unroll
    for (int c = 0; c < 3; c++) {
        if (c == 0)      asm volatile("cp.async.wait_group 2;" ::: "memory");
        else if (c == 1) asm volatile("cp.async.wait_group 1;" ::: "memory");
        else             asm volatile("cp.async.wait_group 0;" ::: "memory");
        __syncthreads();

        uint32_t buf = sbase + c * CH_PER_BUF * 16;
#pragma unroll
        for (int ks = 0; ks < 4; ks++) {
            uint32_t a[2][4], b[2][4];
            int achk = 2 * ks + lhi;
#pragma unroll
            for (int mt = 0; mt < 2; mt++) {
                uint32_t idx = (a_lrow + mt * 16) * 8 + (achk ^ a_sw);
                ldsm_x4(buf + idx * 16, a[mt]);
            }
            int bchk = 2 * ks + b_chlo;
#pragma unroll
            for (int nt16 = 0; nt16 < 2; nt16++) {
                uint32_t idx = (b_lrow + nt16 * 16) * 8 + (bchk ^ b_sw);
                ldsm_x4(buf + idx * 16, b[nt16]);
            }
#pragma unroll
            for (int mt = 0; mt < 2; mt++) {
#pragma unroll
                for (int nt16 = 0; nt16 < 2; nt16++) {
                    mma_bf16(acc[mt][nt16 * 2 + 0], a[mt], &b[nt16][0]);
                    mma_bf16(acc[mt][nt16 * 2 + 1], a[mt], &b[nt16][2]);
                }
            }
        }
    }

#pragma unroll
    for (int mt = 0; mt < 2; mt++) {
        int g0 = m0 + wm * 32 + mt * 16 + (lane >> 2);
        int g1 = g0 + 8;
        size_t ob0 = (size_t)g0 * NOUT;
        size_t ob1 = (size_t)g1 * NOUT;
#pragma unroll
        for (int nt = 0; nt < 4; nt++) {
            int col = n0 + wn * 32 + nt * 8 + 2 * (lane & 3);
            float b0 = bias[col], b1 = bias[col + 1];
            float2 v0 = make_float2(acc[mt][nt][0] + b0, acc[mt][nt][1] + b1);
            float2 v1 = make_float2(acc[mt][nt][2] + b0, acc[mt][nt][3] + b1);
            if (EPI == 0) {
                float sc = (col < CC) ? QSCALE : 1.0f;
                v0.x *= sc; v0.y *= sc; v1.x *= sc; v1.y *= sc;
            }
            if (EPI == 1) {
                v0.x = gelu_exact(v0.x); v0.y = gelu_exact(v0.y);
                v1.x = gelu_exact(v1.x); v1.y = gelu_exact(v1.y);
            }
            __nv_bfloat16* out = (__nv_bfloat16*)outv;
            *(__nv_bfloat162*)(out + ob0 + col) = __float22bfloat162_rn(v0);
            *(__nv_bfloat162*)(out + ob1 + col) = __float22bfloat162_rn(v1);
        }
    }
}

// ---------------------------------------------------------------------------
// FC2 GEMM (K=768): 128x64 tile, 8 warps, 3-STAGE circular pipeline.
// Issue chunk c+2 after the barrier; 2 loads in flight during compute.
// +bias +res -> fp32.
// ---------------------------------------------------------------------------
#define FC2_SMEM (3 * CH_PER_BUF * 16)

__global__ void __launch_bounds__(256) gemm_fc2(
    const __nv_bfloat16* __restrict__ A, const __nv_bfloat16* __restrict__ BT,
    const float* __restrict__ bias, const float* __restrict__ res,
    float* __restrict__ out) {
    extern __shared__ __align__(16) uint4 fsmq[];
    uint32_t sbase = smem_u32(fsmq);
    const int K = HIDDEN;
    const int NCH = K >> 6;  // 12
    int tid = threadIdx.x;
    int wid = tid >> 5, lane = tid & 31;
    int wm = wid & 3, wn = wid >> 2;
    int m0 = blockIdx.y * 128, n0 = blockIdx.x * 64;
    const __nv_bfloat16* Ab = A + (size_t)m0 * K;
    const __nv_bfloat16* Bb = BT + (size_t)n0 * K;

    float acc[2][4][4];
#pragma unroll
    for (int i = 0; i < 2; i++)
#pragma unroll
        for (int j = 0; j < 4; j++)
#pragma unroll
            for (int k = 0; k < 4; k++) acc[i][j][k] = 0.f;

    int a_row = tid >> 1;
    int a_ch0 = (tid & 1) * 4;
    int b_row = tid >> 2;
    int b_ch0 = (tid & 3) * 2;

    int l15 = lane & 15, lhi = lane >> 4;
    int a_lrow = wm * 32 + l15;
    int a_sw = l15 & 7;
    int b_lrow = 128 + wn * 32 + (lhi << 3) + (lane & 7);
    int b_sw = lane & 7;
    int b_chlo = (lane >> 3) & 1;

    // prologue: issue chunks 0 and 1 (2 commit groups)
#pragma unroll
    for (int c = 0; c < 2; c++) {
        uint32_t dst = sbase + c * CH_PER_BUF * 16;
        int k0 = c << 6;
#pragma unroll
        for (int i = 0; i < 4; i++) {
            int ch = a_ch0 + i;
            cpasync16(dst + (a_row * 8 + (ch ^ (a_row & 7))) * 16,
                      Ab + (size_t)a_row * K + k0 + ch * 8);
        }
#pragma unroll
        for (int i = 0; i < 2; i++) {
            int ch = b_ch0 + i;
            cpasync16(dst + ((128 + b_row) * 8 + (ch ^ (b_row & 7))) * 16,
                      Bb + (size_t)b_row * K + k0 + ch * 8);
        }
        cp_commit();
    }

    int bufsel = 0;
    for (int c = 0; c < NCH; c++) {
        // chunk c ready: allow 1 pending group (chunk c+1)
        cp_wait1();
        __syncthreads();

        // issue chunk c+2 into buffer (c+2)%3 (all warps past chunk c-1 now)
        if (c + 2 < NCH) {
            int nb = bufsel + 2; if (nb >= 3) nb -= 3;
            uint32_t dst = sbase + nb * CH_PER_BUF * 16;
            int k0 = (c + 2) << 6;
#pragma unroll
            for (int i = 0; i < 4; i++) {
                int ch = a_ch0 + i;
                cpasync16(dst + (a_row * 8 + (ch ^ (a_row & 7))) * 16,
                          Ab + (size_t)a_row * K + k0 + ch * 8);
            }
#pragma unroll
            for (int i = 0; i < 2; i++) {
                int ch = b_ch0 + i;
                cpasync16(dst + ((128 + b_row) * 8 + (ch ^ (b_row & 7))) * 16,
                          Bb + (size_t)b_row * K + k0 + ch * 8);
            }
        }
        cp_commit();   // commit every iteration (possibly empty) to keep counts aligned

        uint32_t buf = sbase + bufsel * CH_PER_BUF * 16;
#pragma unroll
        for (int ks = 0; ks < 4; ks++) {
            uint32_t a[2][4], b[2][4];
            int achk = 2 * ks + lhi;
#pragma unroll
            for (int mt = 0; mt < 2; mt++) {
                uint32_t idx = (a_lrow + mt * 16) * 8 + (achk ^ a_sw);
                ldsm_x4(buf + idx * 16, a[mt]);
            }
            int bchk = 2 * ks + b_chlo;
#pragma unroll
            for (int nt16 = 0; nt16 < 2; nt16++) {
                uint32_t idx = (b_lrow + nt16 * 16) * 8 + (bchk ^ b_sw);
                ldsm_x4(buf + idx * 16, b[nt16]);
            }
#pragma unroll
            for (int mt = 0; mt < 2; mt++) {
#pragma unroll
                for (int nt16 = 0; nt16 < 2; nt16++) {
                    mma_bf16(acc[mt][nt16 * 2 + 0], a[mt], &b[nt16][0]);
                    mma_bf16(acc[mt][nt16 * 2 + 1], a[mt], &b[nt16][2]);
                }
            }
        }
        bufsel++; if (bufsel == 3) bufsel = 0;
    }

#pragma unroll
    for (int mt = 0; mt < 2; mt++) {
        int g0 = m0 + wm * 32 + mt * 16 + (lane >> 2);
        int g1 = g0 + 8;
        size_t ob0 = (size_t)g0 * CC;
        size_t ob1 = (size_t)g1 * CC;
#pragma unroll
        for (int nt = 0; nt < 4; nt++) {
            int col = n0 + wn * 32 + nt * 8 + 2 * (lane & 3);
            float b0 = bias[col], b1 = bias[col + 1];
            float2 v0 = make_float2(acc[mt][nt][0] + b0, acc[mt][nt][1] + b1);
            float2 v1 = make_float2(acc[mt][nt][2] + b0, acc[mt][nt][3] + b1);
            float2 r0 = *(const float2*)(res + ob0 + col);
            float2 r1 = *(const float2*)(res + ob1 + col);
            v0.x += r0.x; v0.y += r0.y;
            v1.x += r1.x; v1.y += r1.y;
            *(float2*)(out + ob0 + col) = v0;
            *(float2*)(out + ob1 + col) = v1;
        }
    }
}

// ---------------------------------------------------------------------------
// Proj GEMM + scatter + residual + LN2 (fused)
// ---------------------------------------------------------------------------
#define PCH_PER_BUF (320 * 8)
#define PROJ_SMEM (2 * PCH_PER_BUF * 16)

__global__ void __launch_bounds__(256) gemm_proj_ln(
    const __nv_bfloat16* __restrict__ A, const __nv_bfloat16* __restrict__ BT,
    const float* __restrict__ bias, const float* __restrict__ x,
    float* __restrict__ y, __nv_bfloat16* __restrict__ ln2out,
    const float* __restrict__ n2g, const float* __restrict__ n2b) {
    extern __shared__ __align__(16) uint4 psm[];
    uint32_t sbase = smem_u32(psm);
    int tid = threadIdx.x;
    int wid = tid >> 5, lane = tid & 31;
    int m0 = blockIdx.x * 128;
    const __nv_bfloat16* Ab = A + (size_t)m0 * CC;

    float acc[24][4];
#pragma unroll
    for (int j = 0; j < 24; j++)
#pragma unroll
        for (int k = 0; k < 4; k++) acc[j][k] = 0.f;

    int a_row = tid >> 1;
    int a_ch0 = (tid & 1) * 4;
    int b_row = tid >> 2;
    int b_ch0 = (tid & 3) * 2;

    int l15 = lane & 15, lhi = lane >> 4;
    int a_lrow = wid * 16 + l15;
    int a_sw = l15 & 7;
    int b_lbase = 128 + (lhi << 3) + (lane & 7);
    int b_sw = lane & 7;
    int b_chlo = (lane >> 3) & 1;

    {
        uint32_t dst = sbase;
#pragma unroll
        for (int i = 0; i < 4; i++) {
            int ch = a_ch0 + i;
            cpasync16(dst + (a_row * 8 + (ch ^ (a_row & 7))) * 16,
                      Ab + (size_t)a_row * CC + ch * 8);
        }
#pragma unroll
        for (int r3 = 0; r3 < 3; r3++) {
            int row = r3 * 64 + b_row;
#pragma unroll
            for (int i = 0; i < 2; i++) {
                int ch = b_ch0 + i;
                cpasync16(dst + ((128 + row) * 8 + (ch ^ (row & 7))) * 16,
                          BT + (size_t)row * CC + ch * 8);
            }
        }
        cp_commit();
    }

    for (int c = 0; c < 3; c++) {
        if (c + 1 < 3) {
            int k0 = (c + 1) << 6;
            uint32_t dst = sbase + ((c + 1) & 1) * PCH_PER_BUF * 16;
#pragma unroll
            for (int i = 0; i < 4; i++) {
                int ch = a_ch0 + i;
                cpasync16(dst + (a_row * 8 + (ch ^ (a_row & 7))) * 16,
                          Ab + (size_t)a_row * CC + k0 + ch * 8);
            }
#pragma unroll
            for (int r3 = 0; r3 < 3; r3++) {
                int row = r3 * 64 + b_row;
#pragma unroll
                for (int i = 0; i < 2; i++) {
                    int ch = b_ch0 + i;
                    cpasync16(dst + ((128 + row) * 8 + (ch ^ (row & 7))) * 16,
                              BT + (size_t)row * CC + k0 + ch * 8);
                }
            }
        }
        cp_commit();
        cp_wait1();
        __syncthreads();

        uint32_t buf = sbase + (c & 1) * PCH_PER_BUF * 16;
#pragma unroll
        for (int ks = 0; ks < 4; ks++) {
            uint32_t a[4];
            int achk = 2 * ks + lhi;
            ldsm_x4(buf + (a_lrow * 8 + (achk ^ a_sw)) * 16, a);
            int bchk = 2 * ks + b_chlo;
#pragma unroll
            for (int nt16 = 0; nt16 < 12; nt16++) {
                uint32_t b[4];
                ldsm_x4(buf + ((b_lbase + nt16 * 16) * 8 + (bchk ^ b_sw)) * 16, b);
                mma_bf16(acc[nt16 * 2 + 0], a, &b[0]);
                mma_bf16(acc[nt16 * 2 + 1], a, &b[2]);
            }
        }
        __syncthreads();
    }

    int lq = lane & 3;
#pragma unroll
    for (int half = 0; half < 2; half++) {
        int g = m0 + wid * 16 + (lane >> 2) + half * 8;
        int bb = g >> 14, rem = g & 16383;
        int win = rem >> 6, rr = rem & 63;
        int wy = win >> 4, wx = win & 15, ry = rr >> 3, rx = rr & 7;
        int hh = (wy * WS + ry + SHIFT) & 127;
        int ww = (wx * WS + rx + SHIFT) & 127;
        size_t ob = ((size_t)bb * LL + hh * WW_ + ww) * CC;

        float vals[48];
        float s = 0.f, s2 = 0.f;
#pragma unroll
        for (int nt = 0; nt < 24; nt++) {
            int col = nt * 8 + 2 * lq;
            float v0 = acc[nt][half * 2 + 0] + bias[col];
            float v1 = acc[nt][half * 2 + 1] + bias[col + 1];
            float2 rv = *(const float2*)(x + ob + col);
            v0 += rv.x; v1 += rv.y;
            *(float2*)(y + ob + col) = make_float2(v0, v1);
            s += v0 + v1;
            s2 += v0 * v0 + v1 * v1;
            vals[nt * 2] = v0; vals[nt * 2 + 1] = v1;
        }
        s += __shfl_xor_sync(0xFFFFFFFFu, s, 1);
        s2 += __shfl_xor_sync(0xFFFFFFFFu, s2, 1);
        s += __shfl_xor_sync(0xFFFFFFFFu, s, 2);
        s2 += __shfl_xor_sync(0xFFFFFFFFu, s2, 2);
        float mu = s * (1.0f / 192.0f);
        float rs = rsqrtf(s2 * (1.0f / 192.0f) - mu * mu + 1e-5f);
#pragma unroll
        for (int nt = 0; nt < 24; nt++) {
            int col = nt * 8 + 2 * lq;
            float2 gg = *(const float2*)(n2g + col);
            float2 bb2 = *(const float2*)(n2b + col);
            float2 o;
            o.x = (vals[nt * 2] - mu) * rs * gg.x + bb2.x;
            o.y = (vals[nt * 2 + 1] - mu) * rs * gg.y + bb2.y;
            *(__nv_bfloat162*)(ln2out + ob + col) = __float22bfloat162_rn(o);
        }
    }
}

// ---------------------------------------------------------------------------
// Tensor-core windowed attention (round-7 version, unchanged)
// ---------------------------------------------------------------------------
#define KSTR 200
#define VSTR 72
#define ATTN_SMEM ((NWIN * KSTR + CC * VSTR) * 2)

__global__ void __launch_bounds__(384) attn_kernel(
    const __nv_bfloat16* __restrict__ qkv, __nv_bfloat16* __restrict__ outp) {
    extern __shared__ __nv_bfloat16 smh[];
    __nv_bfloat16* k_s = smh;
    __nv_bfloat16* vt_s = smh + NWIN * KSTR;

    int w = blockIdx.x;
    int tid = threadIdx.x;
    int lane = tid & 31, wid = tid >> 5;
    const __nv_bfloat16* base = qkv + (size_t)w * NWIN * 576;

    for (int idx = tid; idx < NWIN * 24; idx += 384) {
        int j = idx / 24, c = idx % 24;
        uint4 uk = *(const uint4*)(base + (size_t)j * 576 + 192 + c * 8);
        *(uint4*)(k_s + j * KSTR + c * 8) = uk;
        uint4 uv = *(const uint4*)(base + (size_t)j * 576 + 384 + c * 8);
        const unsigned short* e = (const unsigned short*)&uv;
#pragma unroll
        for (int i = 0; i < 8; i++) {
            int k = (i + lane) & 7;
            *((unsigned short*)vt_s + (c * 8 + k) * VSTR + j) = e[k];
        }
    }
    __syncthreads();

    int h = wid >> 1;
    int mbase = (wid & 1) * 32;
    int winloc = w & 255;
    int wy = winloc >> 4, wx = winloc & 15;
    int type = ((wy == 15) ? 2 : 0) | ((wx == 15) ? 1 : 0);
    const float* btab = g_bias + ((size_t)(type * HEADS + h) * NWIN) * NWIN;

    int rq = lane >> 2, cq = 2 * (lane & 3);
    int brow = ((lane >> 4) << 3) + (lane & 7);
    int bchlo = (lane >> 3) & 1;

    uint32_t a[2][2][4];
#pragma unroll
    for (int mt = 0; mt < 2; mt++)
#pragma unroll
        for (int ks = 0; ks < 2; ks++)
#pragma unroll
            for (int i = 0; i < 4; i++) {
                int row = mbase + mt * 16 + rq + (i & 1) * 8;
                int col = h * HD + ks * 16 + cq + (i >> 1) * 8;
                a[mt][ks][i] = *(const uint32_t*)(base + (size_t)row * 576 + col);
            }

    float p[2][8][4];
#pragma unroll
    for (int i = 0; i < 2; i++)
#pragma unroll
        for (int j = 0; j < 8; j++)
#pragma unroll
            for (int k = 0; k < 4; k++) p[i][j][k] = 0.f;

    uint32_t ksm = smem_u32(k_s);
#pragma unroll
    for (int kg = 0; kg < 4; kg++) {
#pragma unroll
        for (int ks = 0; ks < 2; ks++) {
            uint32_t b[4];
            uint32_t addr = ksm + ((kg * 16 + brow) * KSTR + (h * 4 + ks * 2 + bchlo) * 8) * 2;
            ldsm_x4(addr, b);
#pragma unroll
            for (int mt = 0; mt < 2; mt++) {
                mma_bf16(p[mt][kg * 2 + 0], a[mt][ks], &b[0]);
                mma_bf16(p[mt][kg * 2 + 1], a[mt][ks], &b[2]);
            }
        }
    }

    float sums[2][2];
#pragma unroll
    for (int mt = 0; mt < 2; mt++) {
#pragma unroll
        for (int rl = 0; rl < 2; rl++) {
            int r = mbase + mt * 16 + rq + rl * 8;
            const float* br_ = btab + r * NWIN;
            float m = -1e30f;
#pragma unroll
            for (int nt = 0; nt < 8; nt++) {
                float2 bv = *(const float2*)(br_ + nt * 8 + cq);
                p[mt][nt][rl * 2 + 0] += bv.x;
                p[mt][nt][rl * 2 + 1] += bv.y;
                m = fmaxf(m, fmaxf(p[mt][nt][rl * 2], p[mt][nt][rl * 2 + 1]));
            }
            m = fmaxf(m, __shfl_xor_sync(0xFFFFFFFFu, m, 1));
            m = fmaxf(m, __shfl_xor_sync(0xFFFFFFFFu, m, 2));
            float s = 0.f;
#pragma unroll
            for (int nt = 0; nt < 8; nt++) {
                float e0 = __expf(p[mt][nt][rl * 2] - m);
                float e1 = __expf(p[mt][nt][rl * 2 + 1] - m);
                p[mt][nt][rl * 2] = e0; p[mt][nt][rl * 2 + 1] = e1;
                s += e0 + e1;
            }
            s += __shfl_xor_sync(0xFFFFFFFFu, s, 1);
            s += __shfl_xor_sync(0xFFFFFFFFu, s, 2);
            sums[mt][rl] = s;
        }
    }

    uint32_t pa[2][4][4];
#pragma unroll
    for (int mt = 0; mt < 2; mt++)
#pragma unroll
        for (int s4 = 0; s4 < 4; s4++) {
            pa[mt][s4][0] = packbf2(p[mt][2 * s4][0], p[mt][2 * s4][1]);
            pa[mt][s4][1] = packbf2(p[mt][2 * s4][2], p[mt][2 * s4][3]);
            pa[mt][s4][2] = packbf2(p[mt][2 * s4 + 1][0], p[mt][2 * s4 + 1][1]);
            pa[mt][s4][3] = packbf2(p[mt][2 * s4 + 1][2], p[mt][2 * s4 + 1][3]);
        }

    float o[2][4][4];
#pragma unroll
    for (int i = 0; i < 2; i++)
#pragma unroll
        for (int j = 0; j < 4; j++)
#pragma unroll
            for (int k = 0; k < 4; k++) o[i][j][k] = 0.f;

    uint32_t vsm = smem_u32(vt_s);
#pragma unroll
    for (int s4 = 0; s4 < 4; s4++) {
#pragma unroll
        for (int n16 = 0; n16 < 2; n16++) {
            uint32_t b[4];
            uint32_t addr = vsm + ((h * HD + n16 * 16 + brow) * VSTR + (s4 * 2 + bchlo) * 8) * 2;
            ldsm_x4(addr, b);
#pragma unroll
            for (int mt = 0; mt < 2; mt++) {
                mma_bf16(o[mt][n16 * 2 + 0], pa[mt][s4], &b[0]);
                mma_bf16(o[mt][n16 * 2 + 1], pa[mt][s4], &b[2]);
            }
        }
    }

#pragma unroll
    for (int mt = 0; mt < 2; mt++) {
        float i0 = 1.0f / sums[mt][0];
        float i1 = 1.0f / sums[mt][1];
        int r0 = mbase + mt * 16 + rq;
        __nv_bfloat16* op0 = outp + (size_t)(w * NWIN + r0) * CC + h * HD;
        __nv_bfloat16* op1 = op0 + 8 * CC;
#pragma unroll
        for (int nt = 0; nt < 4; nt++) {
            *(__nv_bfloat162*)(op0 + nt * 8 + cq) =
                __float22bfloat162_rn(make_float2(o[mt][nt][0] * i0, o[mt][nt][1] * i0));
            *(__nv_bfloat162*)(op1 + nt * 8 + cq) =
                __float22bfloat162_rn(make_float2(o[mt][nt][2] * i1, o[mt][nt][3] * i1));
        }
    }
}

// ---------------------------------------------------------------------------
// Launch
// ---------------------------------------------------------------------------
extern "C" void kernel_launch(void* const* d_in, const int* in_sizes, int n_in,
                              void* d_out, int out_size) {
    const float* x      = (const float*)d_in[0];
    const float* n1_g   = (const float*)d_in[4];
    const float* n1_b   = (const float*)d_in[5];
    const float* qkv_w  = (const float*)d_in[6];
    const float* qkv_b  = (const float*)d_in[7];
    const float* proj_w = (const float*)d_in[8];
    const float* proj_b = (const float*)d_in[9];
    const float* pp_w   = (const float*)d_in[10];
    const float* pp_b   = (const float*)d_in[11];
    const float* p1_g   = (const float*)d_in[12];
    const float* p1_b   = (const float*)d_in[13];
    const float* p1_w   = (const float*)d_in[14];
    const float* p1_bi  = (const float*)d_in[15];
    const float* p2_g   = (const float*)d_in[16];
    const float* p2_b   = (const float*)d_in[17];
    const float* p2_w   = (const float*)d_in[18];
    const float* p2_bi  = (const float*)d_in[19];
    const float* p3_g   = (const float*)d_in[20];
    const float* p3_b   = (const float*)d_in[21];
    const float* p3_w   = (const float*)d_in[22];
    const float* p3_bi  = (const float*)d_in[23];
    const float* n2_g   = (const float*)d_in[24];
    const float* n2_b   = (const float*)d_in[25];
    const float* fc1_w  = (const float*)d_in[26];
    const float* fc1_b  = (const float*)d_in[27];
    const float* fc2_w  = (const float*)d_in[28];
    const float* fc2_b  = (const float*)d_in[29];
    float* out = (float*)d_out;

    __nv_bfloat16 *xw, *qkv, *attn, *ln2, *hid;
    __nv_bfloat16 *wt_qkv, *wt_proj, *wt_fc1, *wt_fc2;
    cudaGetSymbolAddress((void**)&xw,   gb_xw);
    cudaGetSymbolAddress((void**)&qkv,  gb_qkv);
    cudaGetSymbolAddress((void**)&attn, gb_attn);
    cudaGetSymbolAddress((void**)&ln2,  gb_ln2);
    cudaGetSymbolAddress((void**)&hid,  gb_hid);
    cudaGetSymbolAddress((void**)&wt_qkv,  gb_wt_qkv);
    cudaGetSymbolAddress((void**)&wt_proj, gb_wt_proj);
    cudaGetSymbolAddress((void**)&wt_fc1,  gb_wt_fc1);
    cudaGetSymbolAddress((void**)&wt_fc2,  gb_wt_fc2);

    static bool attr_set = false;
    if (!attr_set) {
        cudaFuncSetAttribute(attn_kernel, cudaFuncAttributeMaxDynamicSharedMemorySize,
                             ATTN_SMEM);
        cudaFuncSetAttribute(gemm_proj_ln, cudaFuncAttributeMaxDynamicSharedMemorySize,
                             PROJ_SMEM);
        cudaFuncSetAttribute(gemm_k192<0>, cudaFuncAttributeMaxDynamicSharedMemorySize,
                             K192_SMEM);
        cudaFuncSetAttribute(gemm_k192<1>, cudaFuncAttributeMaxDynamicSharedMemorySize,
                             K192_SMEM);
        cudaFuncSetAttribute(gemm_fc2, cudaFuncAttributeMaxDynamicSharedMemorySize,
                             FC2_SMEM);
        attr_set = true;
    }

    // 0. weight transposes
    transpose_all<<<(TW_TOTAL + 255) / 256, 256>>>(qkv_w, proj_w, fc1_w, fc2_w);

    // 1. position-bias MLP + bias table
    pos_mlp_kernel<<<1, 256>>>(pp_w, pp_b, p1_g, p1_b, p1_w, p1_bi,
                               p2_g, p2_b, p2_w, p2_bi, p3_g, p3_b, p3_w, p3_bi);
    bias_build<<<(4 * HEADS * NWIN * NWIN + 255) / 256, 256>>>();

    // 2. LN1 + shift + window partition -> bf16
    ln1_kernel<<<MROWS / 8, 256>>>(x, xw, n1_g, n1_b);

    // 3. QKV GEMM (K=192, full prefetch) -> bf16, Q pre-scaled
    gemm_k192<0><<<dim3(576 / 64, MROWS / 128), 256, K192_SMEM>>>(xw, wt_qkv, qkv_b, qkv, 576);

    // 4. tensor-core attention -> bf16
    attn_kernel<<<NWINDOWS, 384, ATTN_SMEM>>>(qkv, attn);

    // 5. proj + scatter + residual + LN2 (fused)
    gemm_proj_ln<<<MROWS / 128, 256, PROJ_SMEM>>>(attn, wt_proj, proj_b, x, out, ln2, n2_g, n2_b);

    // 6. FC1 + GELU (K=192, full prefetch) -> bf16
    gemm_k192<1><<<dim3(HIDDEN / 64, MROWS / 128), 256, K192_SMEM>>>(ln2, wt_fc1, fc1_b, hid, HIDDEN);

    // 7. FC2 + residual -> fp32 out (3-stage pipeline, K=768)
    gemm_fc2<<<dim3(CC / 64, MROWS / 128), 256, FC2_SMEM>>>(hid, wt_fc2, fc2_b, out, out);
}

// round 13
// speedup vs baseline: 1.2299x; 1.0051x over previous
#include <cuda_runtime.h>
#include <cuda_bf16.h>
#include <math.h>
#include <stdint.h>

// ---------------------------------------------------------------------------
// Problem constants
// ---------------------------------------------------------------------------
#define BATCH   8
#define HH      128
#define WW_     128
#define LL      (HH*WW_)
#define CC      192
#define HEADS   6
#define HD      32
#define WS      8
#define NWIN    64
#define SHIFT   4
#define HIDDEN  768
#define MROWS   (BATCH*LL)                 // 131072
#define NWINDOWS (BATCH*(HH/WS)*(WW_/WS))  // 2048
#define POS_DIM 12
#define POS_TAB 225
#define QSCALE  0.17677669529663687f

// ---------------------------------------------------------------------------
// Device scratch
// ---------------------------------------------------------------------------
__device__ __nv_bfloat16 gb_xw[(size_t)MROWS * CC];
__device__ __nv_bfloat16 gb_qkv[(size_t)MROWS * 3 * CC];
__device__ __nv_bfloat16 gb_attn[(size_t)MROWS * CC];
__device__ __nv_bfloat16 gb_ln2[(size_t)MROWS * CC];
__device__ __nv_bfloat16 gb_hid[(size_t)MROWS * HIDDEN];
__device__ float g_bias[4 * HEADS * NWIN * NWIN];   // [type][h][r][j]
__device__ __nv_bfloat16 gb_wt_qkv[3 * CC * CC];
__device__ __nv_bfloat16 gb_wt_proj[CC * CC];
__device__ __nv_bfloat16 gb_wt_fc1[HIDDEN * CC];
__device__ __nv_bfloat16 gb_wt_fc2[CC * HIDDEN];

// ---------------------------------------------------------------------------
// Helpers
// ---------------------------------------------------------------------------
__device__ __forceinline__ uint32_t smem_u32(const void* p) {
    uint32_t a;
    asm("{ .reg .u64 t; cvta.to.shared.u64 t, %1; cvt.u32.u64 %0, t; }" : "=r"(a) : "l"(p));
    return a;
}
__device__ __forceinline__ void cpasync16(uint32_t s, const void* g) {
    asm volatile("cp.async.cg.shared.global [%0], [%1], 16;" :: "r"(s), "l"(g));
}
__device__ __forceinline__ void cp_commit() {
    asm volatile("cp.async.commit_group;" ::: "memory");
}
__device__ __forceinline__ void cp_wait1() {
    asm volatile("cp.async.wait_group 1;" ::: "memory");
}
__device__ __forceinline__ void ldsm_x4(uint32_t addr, uint32_t* r) {
    asm volatile("ldmatrix.sync.aligned.m8n8.x4.shared.b16 {%0,%1,%2,%3}, [%4];"
                 : "=r"(r[0]), "=r"(r[1]), "=r"(r[2]), "=r"(r[3]) : "r"(addr));
}
__device__ __forceinline__ void mma_bf16(float* d, const uint32_t* a, const uint32_t* b) {
    asm volatile(
        "mma.sync.aligned.m16n8k16.row.col.f32.bf16.bf16.f32 "
        "{%0,%1,%2,%3}, {%4,%5,%6,%7}, {%8,%9}, {%0,%1,%2,%3};"
        : "+f"(d[0]), "+f"(d[1]), "+f"(d[2]), "+f"(d[3])
        : "r"(a[0]), "r"(a[1]), "r"(a[2]), "r"(a[3]), "r"(b[0]), "r"(b[1]));
}
__device__ __forceinline__ uint32_t packbf2(float x, float y) {
    __nv_bfloat162 t = __float22bfloat162_rn(make_float2(x, y));
    return *(uint32_t*)&t;
}
__device__ __forceinline__ float gelu_exact(float x) {
    return 0.5f * x * (1.0f + erff(x * 0.7071067811865476f));
}

// ---------------------------------------------------------------------------
// Combined weight transpose
// ---------------------------------------------------------------------------
#define TW_QKV (3*CC*CC)
#define TW_PROJ (CC*CC)
#define TW_FC1 (CC*HIDDEN)
#define TW_FC2 (HIDDEN*CC)
#define TW_TOTAL (TW_QKV + TW_PROJ + TW_FC1 + TW_FC2)

__global__ void transpose_all(const float* __restrict__ qkv_w, const float* __restrict__ proj_w,
                              const float* __restrict__ fc1_w, const float* __restrict__ fc2_w) {
    int i = blockIdx.x * 256 + threadIdx.x;
    if (i >= TW_TOTAL) return;
    const float* w; __nv_bfloat16* wt; int K, N, off;
    if (i < TW_QKV) { w = qkv_w; wt = gb_wt_qkv; K = CC; N = 3 * CC; off = i; }
    else if (i < TW_QKV + TW_PROJ) { w = proj_w; wt = gb_wt_proj; K = CC; N = CC; off = i - TW_QKV; }
    else if (i < TW_QKV + TW_PROJ + TW_FC1) { w = fc1_w; wt = gb_wt_fc1; K = CC; N = HIDDEN; off = i - TW_QKV - TW_PROJ; }
    else { w = fc2_w; wt = gb_wt_fc2; K = HIDDEN; N = CC; off = i - TW_QKV - TW_PROJ - TW_FC1; }
    int k = off / N, n = off % N;
    wt[(size_t)n * K + k] = __float2bfloat16(w[off]);
}

// ---------------------------------------------------------------------------
// Bias table with inline position-MLP: [type][h][r][j]
// ---------------------------------------------------------------------------
__device__ __forceinline__ void ln_relu12(const float* p, float* q,
                                          const float* g, const float* b) {
    float s = 0.f, s2 = 0.f;
#pragma unroll
    for (int i = 0; i < POS_DIM; i++) { s += p[i]; s2 += p[i] * p[i]; }
    float mu = s / 12.0f;
    float var = s2 / 12.0f - mu * mu;
    float rs = rsqrtf(var + 1e-5f);
#pragma unroll
    for (int i = 0; i < POS_DIM; i++) q[i] = fmaxf((p[i] - mu) * rs * g[i] + b[i], 0.0f);
}

__global__ void bias_build(
    const float* __restrict__ pp_w, const float* __restrict__ pp_b,
    const float* __restrict__ p1_g, const float* __restrict__ p1_b,
    const float* __restrict__ p1_w, const float* __restrict__ p1_bias,
    const float* __restrict__ p2_g, const float* __restrict__ p2_b,
    const float* __restrict__ p2_w, const float* __restrict__ p2_bias,
    const float* __restrict__ p3_g, const float* __restrict__ p3_b,
    const float* __restrict__ p3_w, const float* __restrict__ p3_bias) {
    int idx = blockIdx.x * 256 + threadIdx.x;
    if (idx >= 4 * HEADS * NWIN * NWIN) return;
    int j = idx & 63;
    int r = (idx >> 6) & 63;
    int h = (idx >> 12) % HEADS;
    int t = idx / (HEADS * NWIN * NWIN);
    int ry = r >> 3, rx = r & 7, jy = j >> 3, jx = j & 7;

    // inline 3-layer position MLP for (bh, bw) = (ry-jy, rx-jx), head h
    float bh = (float)(ry - jy), bw = (float)(rx - jx);
    float p[POS_DIM], q[POS_DIM];
#pragma unroll
    for (int k = 0; k < POS_DIM; k++) p[k] = bh * pp_w[k] + bw * pp_w[POS_DIM + k] + pp_b[k];
    ln_relu12(p, q, p1_g, p1_b);
#pragma unroll
    for (int k = 0; k < POS_DIM; k++) {
        float s = p1_bias[k];
#pragma unroll
        for (int i = 0; i < POS_DIM; i++) s += q[i] * p1_w[i * POS_DIM + k];
        p[k] = s;
    }
    ln_relu12(p, q, p2_g, p2_b);
#pragma unroll
    for (int k = 0; k < POS_DIM; k++) {
        float s = p2_bias[k];
#pragma unroll
        for (int i = 0; i < POS_DIM; i++) s += q[i] * p2_w[i * POS_DIM + k];
        p[k] = s;
    }
    ln_relu12(p, q, p3_g, p3_b);
    float bias = p3_bias[h];
#pragma unroll
    for (int i = 0; i < POS_DIM; i++) bias += q[i] * p3_w[i * HEADS + h];

    int lhr = (t & 2) ? (ry < (WS - SHIFT) ? 1 : 2) : 0;
    int lhj = (t & 2) ? (jy < (WS - SHIFT) ? 1 : 2) : 0;
    int lwr = (t & 1) ? (rx < (WS - SHIFT) ? 1 : 2) : 0;
    int lwj = (t & 1) ? (jx < (WS - SHIFT) ? 1 : 2) : 0;
    if (lhr != lhj || lwr != lwj) bias -= 100.0f;
    g_bias[idx] = bias;
}

// ---------------------------------------------------------------------------
// LayerNorm1: warp per row, fp32 in -> bf16 out, shift+window gather
// ---------------------------------------------------------------------------
__global__ void __launch_bounds__(256) ln1_kernel(
    const float* __restrict__ in, __nv_bfloat16* __restrict__ out,
    const float* __restrict__ gamma, const float* __restrict__ beta) {
    int warp = threadIdx.x >> 5, lane = threadIdx.x & 31;
    int row = blockIdx.x * 8 + warp;
    int bb = row >> 14, rem = row & 16383;
    int win = rem >> 6, r = rem & 63;
    int wy = win >> 4, wx = win & 15, ry = r >> 3, rx = r & 7;
    int hh = (wy * WS + ry + SHIFT) & 127;
    int ww = (wx * WS + rx + SHIFT) & 127;
    size_t src = (size_t)bb * LL + hh * WW_ + ww;

    const float* p = in + src * CC;
    float v[6], s = 0.f, s2 = 0.f;
#pragma unroll
    for (int k = 0; k < 6; k++) { v[k] = p[lane + 32 * k]; s += v[k]; s2 += v[k] * v[k]; }
#pragma unroll
    for (int o = 16; o > 0; o >>= 1) {
        s += __shfl_xor_sync(0xFFFFFFFFu, s, o);
        s2 += __shfl_xor_sync(0xFFFFFFFFu, s2, o);
    }
    float mu = s * (1.0f / 192.0f);
    float rs = rsqrtf(s2 * (1.0f / 192.0f) - mu * mu + 1e-5f);
    __nv_bfloat16* q = out + (size_t)row * CC;
#pragma unroll
    for (int k = 0; k < 6; k++) {
        int c = lane + 32 * k;
        q[c] = __float2bfloat16((v[k] - mu) * rs * gamma[c] + beta[c]);
    }
}

#define CH_PER_BUF (192 * 8)

// ---------------------------------------------------------------------------
// K=192 GEMM: 128x64 tile, 8 warps, TRIPLE buffer, full-K prefetch.
// EPI 0: +bias, Q-scale cols<192 -> bf16   1: gelu(+bias) -> bf16
// ---------------------------------------------------------------------------
#define K192_SMEM (3 * CH_PER_BUF * 16)

template <int EPI>
__global__ void __launch_bounds__(256) gemm_k192(
    const __nv_bfloat16* __restrict__ A, const __nv_bfloat16* __restrict__ BT,
    const float* __restrict__ bias, void* __restrict__ outv, int NOUT) {
    extern __shared__ __align__(16) uint4 ksmq[];
    uint32_t sbase = smem_u32(ksmq);
    int tid = threadIdx.x;
    int wid = tid >> 5, lane = tid & 31;
    int wm = wid & 3, wn = wid >> 2;
    int m0 = blockIdx.y * 128, n0 = blockIdx.x * 64;
    const __nv_bfloat16* Ab = A + (size_t)m0 * CC;
    const __nv_bfloat16* Bb = BT + (size_t)n0 * CC;

    float acc[2][4][4];
#pragma unroll
    for (int i = 0; i < 2; i++)
#pragma unroll
        for (int j = 0; j < 4; j++)
#pragma unroll
            for (int k = 0; k < 4; k++) acc[i][j][k] = 0.f;

    int a_row = tid >> 1;
    int a_ch0 = (tid & 1) * 4;
    int b_row = tid >> 2;
    int b_ch0 = (tid & 3) * 2;

    int l15 = lane & 15, lhi = lane >> 4;
    int a_lrow = wm * 32 + l15;
    int a_sw = l15 & 7;
    int b_lrow = 128 + wn * 32 + (lhi << 3) + (lane & 7);
    int b_sw = lane & 7;
    int b_chlo = (lane >> 3) & 1;

#pragma unroll
    for (int c = 0; c < 3; c++) {
        uint32_t dst = sbase + c * CH_PER_BUF * 16;
        int k0 = c << 6;
#pragma unroll
        for (int i = 0; i < 4; i++) {
            int ch = a_ch0 + i;
            cpasync16(dst + (a_row * 8 + (ch ^ (a_row & 7))) * 16,
                      Ab + (size_t)a_row * CC + k0 + ch * 8);
        }
#pragma unroll
        for (int i = 0; i < 2; i++) {
            int ch = b_ch0 + i;
            cpasync16(dst + ((128 + b_row) * 8 + (ch ^ (b_row & 7))) * 16,
                      Bb + (size_t)b_row * CC + k0 + ch * 8);
        }
        cp_commit();
    }

#pragma unroll
    for (int c = 0; c < 3; c++) {
        if (c == 0)      asm volatile("cp.async.wait_group 2;" ::: "memory");
        else if (c == 1) asm volatile("cp.async.wait_group 1;" ::: "memory");
        else             asm volatile("cp.async.wait_group 0;" ::: "memory");
        __syncthreads();

        uint32_t buf = sbase + c * CH_PER_BUF * 16;
#pragma unroll
        for (int ks = 0; ks < 4; ks++) {
            uint32_t a[2][4], b[2][4];
            int achk = 2 * ks + lhi;
#pragma unroll
            for (int mt = 0; mt < 2; mt++) {
                uint32_t idx = (a_lrow + mt * 16) * 8 + (achk ^ a_sw);
                ldsm_x4(buf + idx * 16, a[mt]);
            }
            int bchk = 2 * ks + b_chlo;
#pragma unroll
            for (int nt16 = 0; nt16 < 2; nt16++) {
                uint32_t idx = (b_lrow + nt16 * 16) * 8 + (bchk ^ b_sw);
                ldsm_x4(buf + idx * 16, b[nt16]);
            }
#pragma unroll
            for (int mt = 0; mt < 2; mt++) {
#pragma unroll
                for (int nt16 = 0; nt16 < 2; nt16++) {
                    mma_bf16(acc[mt][nt16 * 2 + 0], a[mt], &b[nt16][0]);
                    mma_bf16(acc[mt][nt16 * 2 + 1], a[mt], &b[nt16][2]);
                }
            }
        }
    }

#pragma unroll
    for (int mt = 0; mt < 2; mt++) {
        int g0 = m0 + wm * 32 + mt * 16 + (lane >> 2);
        int g1 = g0 + 8;
        size_t ob0 = (size_t)g0 * NOUT;
        size_t ob1 = (size_t)g1 * NOUT;
#pragma unroll
        for (int nt = 0; nt < 4; nt++) {
            int col = n0 + wn * 32 + nt * 8 + 2 * (lane & 3);
            float b0 = bias[col], b1 = bias[col + 1];
            float2 v0 = make_float2(acc[mt][nt][0] + b0, acc[mt][nt][1] + b1);
            float2 v1 = make_float2(acc[mt][nt][2] + b0, acc[mt][nt][3] + b1);
            if (EPI == 0) {
                float sc = (col < CC) ? QSCALE : 1.0f;
                v0.x *= sc; v0.y *= sc; v1.x *= sc; v1.y *= sc;
            }
            if (EPI == 1) {
                v0.x = gelu_exact(v0.x); v0.y = gelu_exact(v0.y);
                v1.x = gelu_exact(v1.x); v1.y = gelu_exact(v1.y);
            }
            __nv_bfloat16* out = (__nv_bfloat16*)outv;
            *(__nv_bfloat162*)(out + ob0 + col) = __float22bfloat162_rn(v0);
            *(__nv_bfloat162*)(out + ob1 + col) = __float22bfloat162_rn(v1);
        }
    }
}

// ---------------------------------------------------------------------------
// FC2 GEMM (K=768): 128x64 tile, 8 warps, 3-STAGE circular pipeline.
// +bias +res -> fp32.
// ---------------------------------------------------------------------------
#define FC2_SMEM (3 * CH_PER_BUF * 16)

__global__ void __launch_bounds__(256) gemm_fc2(
    const __nv_bfloat16* __restrict__ A, const __nv_bfloat16* __restrict__ BT,
    const float* __restrict__ bias, const float* __restrict__ res,
    float* __restrict__ out) {
    extern __shared__ __align__(16) uint4 fsmq[];
    uint32_t sbase = smem_u32(fsmq);
    const int K = HIDDEN;
    const int NCH = K >> 6;  // 12
    int tid = threadIdx.x;
    int wid = tid >> 5, lane = tid & 31;
    int wm = wid & 3, wn = wid >> 2;
    int m0 = blockIdx.y * 128, n0 = blockIdx.x * 64;
    const __nv_bfloat16* Ab = A + (size_t)m0 * K;
    const __nv_bfloat16* Bb = BT + (size_t)n0 * K;

    float acc[2][4][4];
#pragma unroll
    for (int i = 0; i < 2; i++)
#pragma unroll
        for (int j = 0; j < 4; j++)
#pragma unroll
            for (int k = 0; k < 4; k++) acc[i][j][k] = 0.f;

    int a_row = tid >> 1;
    int a_ch0 = (tid & 1) * 4;
    int b_row = tid >> 2;
    int b_ch0 = (tid & 3) * 2;

    int l15 = lane & 15, lhi = lane >> 4;
    int a_lrow = wm * 32 + l15;
    int a_sw = l15 & 7;
    int b_lrow = 128 + wn * 32 + (lhi << 3) + (lane & 7);
    int b_sw = lane & 7;
    int b_chlo = (lane >> 3) & 1;

#pragma unroll
    for (int c = 0; c < 2; c++) {
        uint32_t dst = sbase + c * CH_PER_BUF * 16;
        int k0 = c << 6;
#pragma unroll
        for (int i = 0; i < 4; i++) {
            int ch = a_ch0 + i;
            cpasync16(dst + (a_row * 8 + (ch ^ (a_row & 7))) * 16,
                      Ab + (size_t)a_row * K + k0 + ch * 8);
        }
#pragma unroll
        for (int i = 0; i < 2; i++) {
            int ch = b_ch0 + i;
            cpasync16(dst + ((128 + b_row) * 8 + (ch ^ (b_row & 7))) * 16,
                      Bb + (size_t)b_row * K + k0 + ch * 8);
        }
        cp_commit();
    }

    int bufsel = 0;
    for (int c = 0; c < NCH; c++) {
        cp_wait1();
        __syncthreads();

        if (c + 2 < NCH) {
            int nb = bufsel + 2; if (nb >= 3) nb -= 3;
            uint32_t dst = sbase + nb * CH_PER_BUF * 16;
            int k0 = (c + 2) << 6;
#pragma unroll
            for (int i = 0; i < 4; i++) {
                int ch = a_ch0 + i;
                cpasync16(dst + (a_row * 8 + (ch ^ (a_row & 7))) * 16,
                          Ab + (size_t)a_row * K + k0 + ch * 8);
            }
#pragma unroll
            for (int i = 0; i < 2; i++) {
                int ch = b_ch0 + i;
                cpasync16(dst + ((128 + b_row) * 8 + (ch ^ (b_row & 7))) * 16,
                          Bb + (size_t)b_row * K + k0 + ch * 8);
            }
        }
        cp_commit();

        uint32_t buf = sbase + bufsel * CH_PER_BUF * 16;
#pragma unroll
        for (int ks = 0; ks < 4; ks++) {
            uint32_t a[2][4], b[2][4];
            int achk = 2 * ks + lhi;
#pragma unroll
            for (int mt = 0; mt < 2; mt++) {
                uint32_t idx = (a_lrow + mt * 16) * 8 + (achk ^ a_sw);
                ldsm_x4(buf + idx * 16, a[mt]);
            }
            int bchk = 2 * ks + b_chlo;
#pragma unroll
            for (int nt16 = 0; nt16 < 2; nt16++) {
                uint32_t idx = (b_lrow + nt16 * 16) * 8 + (bchk ^ b_sw);
                ldsm_x4(buf + idx * 16, b[nt16]);
            }
#pragma unroll
            for (int mt = 0; mt < 2; mt++) {
#pragma unroll
                for (int nt16 = 0; nt16 < 2; nt16++) {
                    mma_bf16(acc[mt][nt16 * 2 + 0], a[mt], &b[nt16][0]);
                    mma_bf16(acc[mt][nt16 * 2 + 1], a[mt], &b[nt16][2]);
                }
            }
        }
        bufsel++; if (bufsel == 3) bufsel = 0;
    }

#pragma unroll
    for (int mt = 0; mt < 2; mt++) {
        int g0 = m0 + wm * 32 + mt * 16 + (lane >> 2);
        int g1 = g0 + 8;
        size_t ob0 = (size_t)g0 * CC;
        size_t ob1 = (size_t)g1 * CC;
#pragma unroll
        for (int nt = 0; nt < 4; nt++) {
            int col = n0 + wn * 32 + nt * 8 + 2 * (lane & 3);
            float b0 = bias[col], b1 = bias[col + 1];
            float2 v0 = make_float2(acc[mt][nt][0] + b0, acc[mt][nt][1] + b1);
            float2 v1 = make_float2(acc[mt][nt][2] + b0, acc[mt][nt][3] + b1);
            float2 r0 = *(const float2*)(res + ob0 + col);
            float2 r1 = *(const float2*)(res + ob1 + col);
            v0.x += r0.x; v0.y += r0.y;
            v1.x += r1.x; v1.y += r1.y;
            *(float2*)(out + ob0 + col) = v0;
            *(float2*)(out + ob1 + col) = v1;
        }
    }
}

// ---------------------------------------------------------------------------
// Proj GEMM + scatter + residual + LN2 (fused)
// ---------------------------------------------------------------------------
#define PCH_PER_BUF (320 * 8)
#define PROJ_SMEM (2 * PCH_PER_BUF * 16)

__global__ void __launch_bounds__(256) gemm_proj_ln(
    const __nv_bfloat16* __restrict__ A, const __nv_bfloat16* __restrict__ BT,
    const float* __restrict__ bias, const float* __restrict__ x,
    float* __restrict__ y, __nv_bfloat16* __restrict__ ln2out,
    const float* __restrict__ n2g, const float* __restrict__ n2b) {
    extern __shared__ __align__(16) uint4 psm[];
    uint32_t sbase = smem_u32(psm);
    int tid = threadIdx.x;
    int wid = tid >> 5, lane = tid & 31;
    int m0 = blockIdx.x * 128;
    const __nv_bfloat16* Ab = A + (size_t)m0 * CC;

    float acc[24][4];
#pragma unroll
    for (int j = 0; j < 24; j++)
#pragma unroll
        for (int k = 0; k < 4; k++) acc[j][k] = 0.f;

    int a_row = tid >> 1;
    int a_ch0 = (tid & 1) * 4;
    int b_row = tid >> 2;
    int b_ch0 = (tid & 3) * 2;

    int l15 = lane & 15, lhi = lane >> 4;
    int a_lrow = wid * 16 + l15;
    int a_sw = l15 & 7;
    int b_lbase = 128 + (lhi << 3) + (lane & 7);
    int b_sw = lane & 7;
    int b_chlo = (lane >> 3) & 1;

    {
        uint32_t dst = sbase;
#pragma unroll
        for (int i = 0; i < 4; i++) {
            int ch = a_ch0 + i;
            cpasync16(dst + (a_row * 8 + (ch ^ (a_row & 7))) * 16,
                      Ab + (size_t)a_row * CC + ch * 8);
        }
#pragma unroll
        for (int r3 = 0; r3 < 3; r3++) {
            int row = r3 * 64 + b_row;
#pragma unroll
            for (int i = 0; i < 2; i++) {
                int ch = b_ch0 + i;
                cpasync16(dst + ((128 + row) * 8 + (ch ^ (row & 7))) * 16,
                          BT + (size_t)row * CC + ch * 8);
            }
        }
        cp_commit();
    }

    for (int c = 0; c < 3; c++) {
        if (c + 1 < 3) {
            int k0 = (c + 1) << 6;
            uint32_t dst = sbase + ((c + 1) & 1) * PCH_PER_BUF * 16;
#pragma unroll
            for (int i = 0; i < 4; i++) {
                int ch = a_ch0 + i;
                cpasync16(dst + (a_row * 8 + (ch ^ (a_row & 7))) * 16,
                          Ab + (size_t)a_row * CC + k0 + ch * 8);
            }
#pragma unroll
            for (int r3 = 0; r3 < 3; r3++) {
                int row = r3 * 64 + b_row;
#pragma unroll
                for (int i = 0; i < 2; i++) {
                    int ch = b_ch0 + i;
                    cpasync16(dst + ((128 + row) * 8 + (ch ^ (row & 7))) * 16,
                              BT + (size_t)row * CC + k0 + ch * 8);
                }
            }
        }
        cp_commit();
        cp_wait1();
        __syncthreads();

        uint32_t buf = sbase + (c & 1) * PCH_PER_BUF * 16;
#pragma unroll
        for (int ks = 0; ks < 4; ks++) {
            uint32_t a[4];
            int achk = 2 * ks + lhi;
            ldsm_x4(buf + (a_lrow * 8 + (achk ^ a_sw)) * 16, a);
            int bchk = 2 * ks + b_chlo;
#pragma unroll
            for (int nt16 = 0; nt16 < 12; nt16++) {
                uint32_t b[4];
                ldsm_x4(buf + ((b_lbase + nt16 * 16) * 8 + (bchk ^ b_sw)) * 16, b);
                mma_bf16(acc[nt16 * 2 + 0], a, &b[0]);
                mma_bf16(acc[nt16 * 2 + 1], a, &b[2]);
            }
        }
        __syncthreads();
    }

    int lq = lane & 3;
#pragma unroll
    for (int half = 0; half < 2; half++) {
        int g = m0 + wid * 16 + (lane >> 2) + half * 8;
        int bb = g >> 14, rem = g & 16383;
        int win = rem >> 6, rr = rem & 63;
        int wy = win >> 4, wx = win & 15, ry = rr >> 3, rx = rr & 7;
        int hh = (wy * WS + ry + SHIFT) & 127;
        int ww = (wx * WS + rx + SHIFT) & 127;
        size_t ob = ((size_t)bb * LL + hh * WW_ + ww) * CC;

        float vals[48];
        float s = 0.f, s2 = 0.f;
#pragma unroll
        for (int nt = 0; nt < 24; nt++) {
            int col = nt * 8 + 2 * lq;
            float v0 = acc[nt][half * 2 + 0] + bias[col];
            float v1 = acc[nt][half * 2 + 1] + bias[col + 1];
            float2 rv = *(const float2*)(x + ob + col);
            v0 += rv.x; v1 += rv.y;
            *(float2*)(y + ob + col) = make_float2(v0, v1);
            s += v0 + v1;
            s2 += v0 * v0 + v1 * v1;
            vals[nt * 2] = v0; vals[nt * 2 + 1] = v1;
        }
        s += __shfl_xor_sync(0xFFFFFFFFu, s, 1);
        s2 += __shfl_xor_sync(0xFFFFFFFFu, s2, 1);
        s += __shfl_xor_sync(0xFFFFFFFFu, s, 2);
        s2 += __shfl_xor_sync(0xFFFFFFFFu, s2, 2);
        float mu = s * (1.0f / 192.0f);
        float rs = rsqrtf(s2 * (1.0f / 192.0f) - mu * mu + 1e-5f);
#pragma unroll
        for (int nt = 0; nt < 24; nt++) {
            int col = nt * 8 + 2 * lq;
            float2 gg = *(const float2*)(n2g + col);
            float2 bb2 = *(const float2*)(n2b + col);
            float2 o;
            o.x = (vals[nt * 2] - mu) * rs * gg.x + bb2.x;
            o.y = (vals[nt * 2 + 1] - mu) * rs * gg.y + bb2.y;
            *(__nv_bfloat162*)(ln2out + ob + col) = __float22bfloat162_rn(o);
        }
    }
}

// ---------------------------------------------------------------------------
// Tensor-core windowed attention. Q now staged through SMEM (coalesced)
// and A-fragments fetched via ldmatrix.
// ---------------------------------------------------------------------------
#define KSTR 200
#define VSTR 72
#define ATTN_SMEM ((2 * NWIN * KSTR + CC * VSTR) * 2)

__global__ void __launch_bounds__(384) attn_kernel(
    const __nv_bfloat16* __restrict__ qkv, __nv_bfloat16* __restrict__ outp) {
    extern __shared__ __nv_bfloat16 smh[];
    __nv_bfloat16* q_s = smh;                       // [64][KSTR]
    __nv_bfloat16* k_s = smh + NWIN * KSTR;         // [64][KSTR]
    __nv_bfloat16* vt_s = smh + 2 * NWIN * KSTR;    // [192][VSTR]

    int w = blockIdx.x;
    int tid = threadIdx.x;
    int lane = tid & 31, wid = tid >> 5;
    const __nv_bfloat16* base = qkv + (size_t)w * NWIN * 576;

    for (int idx = tid; idx < NWIN * 24; idx += 384) {
        int j = idx / 24, c = idx % 24;
        const __nv_bfloat16* rowp = base + (size_t)j * 576 + c * 8;
        uint4 uq = *(const uint4*)(rowp);
        *(uint4*)(q_s + j * KSTR + c * 8) = uq;
        uint4 uk = *(const uint4*)(rowp + 192);
        *(uint4*)(k_s + j * KSTR + c * 8) = uk;
        uint4 uv = *(const uint4*)(rowp + 384);
        const unsigned short* e = (const unsigned short*)&uv;
#pragma unroll
        for (int i = 0; i < 8; i++) {
            int k = (i + lane) & 7;
            *((unsigned short*)vt_s + (c * 8 + k) * VSTR + j) = e[k];
        }
    }
    __syncthreads();

    int h = wid >> 1;
    int mbase = (wid & 1) * 32;
    int winloc = w & 255;
    int wy = winloc >> 4, wx = winloc & 15;
    int type = ((wy == 15) ? 2 : 0) | ((wx == 15) ? 1 : 0);
    const float* btab = g_bias + ((size_t)(type * HEADS + h) * NWIN) * NWIN;

    int rq = lane >> 2, cq = 2 * (lane & 3);
    int l15 = lane & 15, lhi = lane >> 4;
    int brow = (lhi << 3) + (lane & 7);
    int bchlo = (lane >> 3) & 1;

    // A fragments (Q) via ldmatrix from smem
    uint32_t qsm = smem_u32(q_s);
    uint32_t a[2][2][4];
#pragma unroll
    for (int mt = 0; mt < 2; mt++)
#pragma unroll
        for (int ks = 0; ks < 2; ks++) {
            uint32_t addr = qsm +
                ((mbase + mt * 16 + l15) * KSTR + h * HD + ks * 16 + lhi * 8) * 2;
            ldsm_x4(addr, a[mt][ks]);
        }

    float p[2][8][4];
#pragma unroll
    for (int i = 0; i < 2; i++)
#pragma unroll
        for (int j = 0; j < 8; j++)
#pragma unroll
            for (int k = 0; k < 4; k++) p[i][j][k] = 0.f;

    uint32_t ksm = smem_u32(k_s);
#pragma unroll
    for (int kg = 0; kg < 4; kg++) {
#pragma unroll
        for (int ks = 0; ks < 2; ks++) {
            uint32_t b[4];
            uint32_t addr = ksm + ((kg * 16 + brow) * KSTR + (h * 4 + ks * 2 + bchlo) * 8) * 2;
            ldsm_x4(addr, b);
#pragma unroll
            for (int mt = 0; mt < 2; mt++) {
                mma_bf16(p[mt][kg * 2 + 0], a[mt][ks], &b[0]);
                mma_bf16(p[mt][kg * 2 + 1], a[mt][ks], &b[2]);
            }
        }
    }

    float sums[2][2];
#pragma unroll
    for (int mt = 0; mt < 2; mt++) {
#pragma unroll
        for (int rl = 0; rl < 2; rl++) {
            int r = mbase + mt * 16 + rq + rl * 8;
            const float* br_ = btab + r * NWIN;
            float m = -1e30f;
#pragma unroll
            for (int nt = 0; nt < 8; nt++) {
                float2 bv = *(const float2*)(br_ + nt * 8 + cq);
                p[mt][nt][rl * 2 + 0] += bv.x;
                p[mt][nt][rl * 2 + 1] += bv.y;
                m = fmaxf(m, fmaxf(p[mt][nt][rl * 2], p[mt][nt][rl * 2 + 1]));
            }
            m = fmaxf(m, __shfl_xor_sync(0xFFFFFFFFu, m, 1));
            m = fmaxf(m, __shfl_xor_sync(0xFFFFFFFFu, m, 2));
            float s = 0.f;
#pragma unroll
            for (int nt = 0; nt < 8; nt++) {
                float e0 = __expf(p[mt][nt][rl * 2] - m);
                float e1 = __expf(p[mt][nt][rl * 2 + 1] - m);
                p[mt][nt][rl * 2] = e0; p[mt][nt][rl * 2 + 1] = e1;
                s += e0 + e1;
            }
            s += __shfl_xor_sync(0xFFFFFFFFu, s, 1);
            s += __shfl_xor_sync(0xFFFFFFFFu, s, 2);
            sums[mt][rl] = s;
        }
    }

    uint32_t pa[2][4][4];
#pragma unroll
    for (int mt = 0; mt < 2; mt++)
#pragma unroll
        for (int s4 = 0; s4 < 4; s4++) {
            pa[mt][s4][0] = packbf2(p[mt][2 * s4][0], p[mt][2 * s4][1]);
            pa[mt][s4][1] = packbf2(p[mt][2 * s4][2], p[mt][2 * s4][3]);
            pa[mt][s4][2] = packbf2(p[mt][2 * s4 + 1][0], p[mt][2 * s4 + 1][1]);
            pa[mt][s4][3] = packbf2(p[mt][2 * s4 + 1][2], p[mt][2 * s4 + 1][3]);
        }

    float o[2][4][4];
#pragma unroll
    for (int i = 0; i < 2; i++)
#pragma unroll
        for (int j = 0; j < 4; j++)
#pragma unroll
            for (int k = 0; k < 4; k++) o[i][j][k] = 0.f;

    uint32_t vsm = smem_u32(vt_s);
#pragma unroll
    for (int s4 = 0; s4 < 4; s4++) {
#pragma unroll
        for (int n16 = 0; n16 < 2; n16++) {
            uint32_t b[4];
            uint32_t addr = vsm + ((h * HD + n16 * 16 + brow) * VSTR + (s4 * 2 + bchlo) * 8) * 2;
            ldsm_x4(addr, b);
#pragma unroll
            for (int mt = 0; mt < 2; mt++) {
                mma_bf16(o[mt][n16 * 2 + 0], pa[mt][s4], &b[0]);
                mma_bf16(o[mt][n16 * 2 + 1], pa[mt][s4], &b[2]);
            }
        }
    }

#pragma unroll
    for (int mt = 0; mt < 2; mt++) {
        float i0 = 1.0f / sums[mt][0];
        float i1 = 1.0f / sums[mt][1];
        int r0 = mbase + mt * 16 + rq;
        __nv_bfloat16* op0 = outp + (size_t)(w * NWIN + r0) * CC + h * HD;
        __nv_bfloat16* op1 = op0 + 8 * CC;
#pragma unroll
        for (int nt = 0; nt < 4; nt++) {
            *(__nv_bfloat162*)(op0 + nt * 8 + cq) =
                __float22bfloat162_rn(make_float2(o[mt][nt][0] * i0, o[mt][nt][1] * i0));
            *(__nv_bfloat162*)(op1 + nt * 8 + cq) =
                __float22bfloat162_rn(make_float2(o[mt][nt][2] * i1, o[mt][nt][3] * i1));
        }
    }
}

// ---------------------------------------------------------------------------
// Launch
// ---------------------------------------------------------------------------
extern "C" void kernel_launch(void* const* d_in, const int* in_sizes, int n_in,
                              void* d_out, int out_size) {
    const float* x      = (const float*)d_in[0];
    const float* n1_g   = (const float*)d_in[4];
    const float* n1_b   = (const float*)d_in[5];
    const float* qkv_w  = (const float*)d_in[6];
    const float* qkv_b  = (const float*)d_in[7];
    const float* proj_w = (const float*)d_in[8];
    const float* proj_b = (const float*)d_in[9];
    const float* pp_w   = (const float*)d_in[10];
    const float* pp_b   = (const float*)d_in[11];
    const float* p1_g   = (const float*)d_in[12];
    const float* p1_b   = (const float*)d_in[13];
    const float* p1_w   = (const float*)d_in[14];
    const float* p1_bi  = (const float*)d_in[15];
    const float* p2_g   = (const float*)d_in[16];
    const float* p2_b   = (const float*)d_in[17];
    const float* p2_w   = (const float*)d_in[18];
    const float* p2_bi  = (const float*)d_in[19];
    const float* p3_g   = (const float*)d_in[20];
    const float* p3_b   = (const float*)d_in[21];
    const float* p3_w   = (const float*)d_in[22];
    const float* p3_bi  = (const float*)d_in[23];
    const float* n2_g   = (const float*)d_in[24];
    const float* n2_b   = (const float*)d_in[25];
    const float* fc1_w  = (const float*)d_in[26];
    const float* fc1_b  = (const float*)d_in[27];
    const float* fc2_w  = (const float*)d_in[28];
    const float* fc2_b  = (const float*)d_in[29];
    float* out = (float*)d_out;

    __nv_bfloat16 *xw, *qkv, *attn, *ln2, *hid;
    __nv_bfloat16 *wt_qkv, *wt_proj, *wt_fc1, *wt_fc2;
    cudaGetSymbolAddress((void**)&xw,   gb_xw);
    cudaGetSymbolAddress((void**)&qkv,  gb_qkv);
    cudaGetSymbolAddress((void**)&attn, gb_attn);
    cudaGetSymbolAddress((void**)&ln2,  gb_ln2);
    cudaGetSymbolAddress((void**)&hid,  gb_hid);
    cudaGetSymbolAddress((void**)&wt_qkv,  gb_wt_qkv);
    cudaGetSymbolAddress((void**)&wt_proj, gb_wt_proj);
    cudaGetSymbolAddress((void**)&wt_fc1,  gb_wt_fc1);
    cudaGetSymbolAddress((void**)&wt_fc2,  gb_wt_fc2);

    static bool attr_set = false;
    if (!attr_set) {
        cudaFuncSetAttribute(attn_kernel, cudaFuncAttributeMaxDynamicSharedMemorySize,
                             ATTN_SMEM);
        cudaFuncSetAttribute(gemm_proj_ln, cudaFuncAttributeMaxDynamicSharedMemorySize,
                             PROJ_SMEM);
        cudaFuncSetAttribute(gemm_k192<0>, cudaFuncAttributeMaxDynamicSharedMemorySize,
                             K192_SMEM);
        cudaFuncSetAttribute(gemm_k192<1>, cudaFuncAttributeMaxDynamicSharedMemorySize,
                             K192_SMEM);
        cudaFuncSetAttribute(gemm_fc2, cudaFuncAttributeMaxDynamicSharedMemorySize,
                             FC2_SMEM);
        attr_set = true;
    }

    // 0. weight transposes
    transpose_all<<<(TW_TOTAL + 255) / 256, 256>>>(qkv_w, proj_w, fc1_w, fc2_w);

    // 1. bias table with inline position-MLP (one launch)
    bias_build<<<(4 * HEADS * NWIN * NWIN + 255) / 256, 256>>>(
        pp_w, pp_b, p1_g, p1_b, p1_w, p1_bi,
        p2_g, p2_b, p2_w, p2_bi, p3_g, p3_b, p3_w, p3_bi);

    // 2. LN1 + shift + window partition -> bf16
    ln1_kernel<<<MROWS / 8, 256>>>(x, xw, n1_g, n1_b);

    // 3. QKV GEMM (K=192, full prefetch) -> bf16, Q pre-scaled
    gemm_k192<0><<<dim3(576 / 64, MROWS / 128), 256, K192_SMEM>>>(xw, wt_qkv, qkv_b, qkv, 576);

    // 4. tensor-core attention (Q via smem) -> bf16
    attn_kernel<<<NWINDOWS, 384, ATTN_SMEM>>>(qkv, attn);

    // 5. proj + scatter + residual + LN2 (fused)
    gemm_proj_ln<<<MROWS / 128, 256, PROJ_SMEM>>>(attn, wt_proj, proj_b, x, out, ln2, n2_g, n2_b);

    // 6. FC1 + GELU (K=192, full prefetch) -> bf16
    gemm_k192<1><<<dim3(HIDDEN / 64, MROWS / 128), 256, K192_SMEM>>>(ln2, wt_fc1, fc1_b, hid, HIDDEN);

    // 7. FC2 + residual -> fp32 out (3-stage pipeline, K=768)
    gemm_fc2<<<dim3(CC / 64, MROWS / 128), 256, FC2_SMEM>>>(hid, wt_fc2, fc2_b, out, out);
}

// round 14
// speedup vs baseline: 1.2494x; 1.0158x over previous
#include <cuda_runtime.h>
#include <cuda_bf16.h>
#include <math.h>
#include <stdint.h>

// ---------------------------------------------------------------------------
// Problem constants
// ---------------------------------------------------------------------------
#define BATCH   8
#define HH      128
#define WW_     128
#define LL      (HH*WW_)
#define CC      192
#define HEADS   6
#define HD      32
#define WS      8
#define NWIN    64
#define SHIFT   4
#define HIDDEN  768
#define MROWS   (BATCH*LL)                 // 131072
#define NWINDOWS (BATCH*(HH/WS)*(WW_/WS))  // 2048
#define POS_DIM 12
#define POS_TAB 225
#define QSCALE  0.17677669529663687f

// ---------------------------------------------------------------------------
// Device scratch
// ---------------------------------------------------------------------------
__device__ __nv_bfloat16 gb_xw[(size_t)MROWS * CC];
__device__ __nv_bfloat16 gb_qkv[(size_t)MROWS * 3 * CC];
__device__ __nv_bfloat16 gb_attn[(size_t)MROWS * CC];
__device__ __nv_bfloat16 gb_ln2[(size_t)MROWS * CC];
__device__ __nv_bfloat16 gb_hid[(size_t)MROWS * HIDDEN];
__device__ float g_bias[4 * HEADS * NWIN * NWIN];   // [type][h][r][j]
__device__ __nv_bfloat16 gb_wt_qkv[3 * CC * CC];
__device__ __nv_bfloat16 gb_wt_proj[CC * CC];
__device__ __nv_bfloat16 gb_wt_fc1[HIDDEN * CC];
__device__ __nv_bfloat16 gb_wt_fc2[CC * HIDDEN];

// ---------------------------------------------------------------------------
// Helpers
// ---------------------------------------------------------------------------
__device__ __forceinline__ uint32_t smem_u32(const void* p) {
    uint32_t a;
    asm("{ .reg .u64 t; cvta.to.shared.u64 t, %1; cvt.u32.u64 %0, t; }" : "=r"(a) : "l"(p));
    return a;
}
__device__ __forceinline__ void cpasync16(uint32_t s, const void* g) {
    asm volatile("cp.async.cg.shared.global [%0], [%1], 16;" :: "r"(s), "l"(g));
}
__device__ __forceinline__ void cp_commit() {
    asm volatile("cp.async.commit_group;" ::: "memory");
}
__device__ __forceinline__ void cp_wait1() {
    asm volatile("cp.async.wait_group 1;" ::: "memory");
}
__device__ __forceinline__ void ldsm_x4(uint32_t addr, uint32_t* r) {
    asm volatile("ldmatrix.sync.aligned.m8n8.x4.shared.b16 {%0,%1,%2,%3}, [%4];"
                 : "=r"(r[0]), "=r"(r[1]), "=r"(r[2]), "=r"(r[3]) : "r"(addr));
}
__device__ __forceinline__ void mma_bf16(float* d, const uint32_t* a, const uint32_t* b) {
    asm volatile(
        "mma.sync.aligned.m16n8k16.row.col.f32.bf16.bf16.f32 "
        "{%0,%1,%2,%3}, {%4,%5,%6,%7}, {%8,%9}, {%0,%1,%2,%3};"
        : "+f"(d[0]), "+f"(d[1]), "+f"(d[2]), "+f"(d[3])
        : "r"(a[0]), "r"(a[1]), "r"(a[2]), "r"(a[3]), "r"(b[0]), "r"(b[1]));
}
__device__ __forceinline__ uint32_t packbf2(float x, float y) {
    __nv_bfloat162 t = __float22bfloat162_rn(make_float2(x, y));
    return *(uint32_t*)&t;
}
__device__ __forceinline__ float gelu_exact(float x) {
    return 0.5f * x * (1.0f + erff(x * 0.7071067811865476f));
}

// ---------------------------------------------------------------------------
// Combined weight transpose
// ---------------------------------------------------------------------------
#define TW_QKV (3*CC*CC)
#define TW_PROJ (CC*CC)
#define TW_FC1 (CC*HIDDEN)
#define TW_FC2 (HIDDEN*CC)
#define TW_TOTAL (TW_QKV + TW_PROJ + TW_FC1 + TW_FC2)

__global__ void transpose_all(const float* __restrict__ qkv_w, const float* __restrict__ proj_w,
                              const float* __restrict__ fc1_w, const float* __restrict__ fc2_w) {
    int i = blockIdx.x * 256 + threadIdx.x;
    if (i >= TW_TOTAL) return;
    const float* w; __nv_bfloat16* wt; int K, N, off;
    if (i < TW_QKV) { w = qkv_w; wt = gb_wt_qkv; K = CC; N = 3 * CC; off = i; }
    else if (i < TW_QKV + TW_PROJ) { w = proj_w; wt = gb_wt_proj; K = CC; N = CC; off = i - TW_QKV; }
    else if (i < TW_QKV + TW_PROJ + TW_FC1) { w = fc1_w; wt = gb_wt_fc1; K = CC; N = HIDDEN; off = i - TW_QKV - TW_PROJ; }
    else { w = fc2_w; wt = gb_wt_fc2; K = HIDDEN; N = CC; off = i - TW_QKV - TW_PROJ - TW_FC1; }
    int k = off / N, n = off % N;
    wt[(size_t)n * K + k] = __float2bfloat16(w[off]);
}

// ---------------------------------------------------------------------------
// Bias table with inline position-MLP
// ---------------------------------------------------------------------------
__device__ __forceinline__ void ln_relu12(const float* p, float* q,
                                          const float* g, const float* b) {
    float s = 0.f, s2 = 0.f;
#pragma unroll
    for (int i = 0; i < POS_DIM; i++) { s += p[i]; s2 += p[i] * p[i]; }
    float mu = s / 12.0f;
    float var = s2 / 12.0f - mu * mu;
    float rs = rsqrtf(var + 1e-5f);
#pragma unroll
    for (int i = 0; i < POS_DIM; i++) q[i] = fmaxf((p[i] - mu) * rs * g[i] + b[i], 0.0f);
}

__global__ void bias_build(
    const float* __restrict__ pp_w, const float* __restrict__ pp_b,
    const float* __restrict__ p1_g, const float* __restrict__ p1_b,
    const float* __restrict__ p1_w, const float* __restrict__ p1_bias,
    const float* __restrict__ p2_g, const float* __restrict__ p2_b,
    const float* __restrict__ p2_w, const float* __restrict__ p2_bias,
    const float* __restrict__ p3_g, const float* __restrict__ p3_b,
    const float* __restrict__ p3_w, const float* __restrict__ p3_bias) {
    int idx = blockIdx.x * 256 + threadIdx.x;
    if (idx >= 4 * HEADS * NWIN * NWIN) return;
    int j = idx & 63;
    int r = (idx >> 6) & 63;
    int h = (idx >> 12) % HEADS;
    int t = idx / (HEADS * NWIN * NWIN);
    int ry = r >> 3, rx = r & 7, jy = j >> 3, jx = j & 7;

    float bh = (float)(ry - jy), bw = (float)(rx - jx);
    float p[POS_DIM], q[POS_DIM];
#pragma unroll
    for (int k = 0; k < POS_DIM; k++) p[k] = bh * pp_w[k] + bw * pp_w[POS_DIM + k] + pp_b[k];
    ln_relu12(p, q, p1_g, p1_b);
#pragma unroll
    for (int k = 0; k < POS_DIM; k++) {
        float s = p1_bias[k];
#pragma unroll
        for (int i = 0; i < POS_DIM; i++) s += q[i] * p1_w[i * POS_DIM + k];
        p[k] = s;
    }
    ln_relu12(p, q, p2_g, p2_b);
#pragma unroll
    for (int k = 0; k < POS_DIM; k++) {
        float s = p2_bias[k];
#pragma unroll
        for (int i = 0; i < POS_DIM; i++) s += q[i] * p2_w[i * POS_DIM + k];
        p[k] = s;
    }
    ln_relu12(p, q, p3_g, p3_b);
    float bias = p3_bias[h];
#pragma unroll
    for (int i = 0; i < POS_DIM; i++) bias += q[i] * p3_w[i * HEADS + h];

    int lhr = (t & 2) ? (ry < (WS - SHIFT) ? 1 : 2) : 0;
    int lhj = (t & 2) ? (jy < (WS - SHIFT) ? 1 : 2) : 0;
    int lwr = (t & 1) ? (rx < (WS - SHIFT) ? 1 : 2) : 0;
    int lwj = (t & 1) ? (jx < (WS - SHIFT) ? 1 : 2) : 0;
    if (lhr != lhj || lwr != lwj) bias -= 100.0f;
    g_bias[idx] = bias;
}

// ---------------------------------------------------------------------------
// LayerNorm1: warp per row, fp32 in -> bf16 out, shift+window gather
// ---------------------------------------------------------------------------
__global__ void __launch_bounds__(256) ln1_kernel(
    const float* __restrict__ in, __nv_bfloat16* __restrict__ out,
    const float* __restrict__ gamma, const float* __restrict__ beta) {
    int warp = threadIdx.x >> 5, lane = threadIdx.x & 31;
    int row = blockIdx.x * 8 + warp;
    int bb = row >> 14, rem = row & 16383;
    int win = rem >> 6, r = rem & 63;
    int wy = win >> 4, wx = win & 15, ry = r >> 3, rx = r & 7;
    int hh = (wy * WS + ry + SHIFT) & 127;
    int ww = (wx * WS + rx + SHIFT) & 127;
    size_t src = (size_t)bb * LL + hh * WW_ + ww;

    const float* p = in + src * CC;
    float v[6], s = 0.f, s2 = 0.f;
#pragma unroll
    for (int k = 0; k < 6; k++) { v[k] = p[lane + 32 * k]; s += v[k]; s2 += v[k] * v[k]; }
#pragma unroll
    for (int o = 16; o > 0; o >>= 1) {
        s += __shfl_xor_sync(0xFFFFFFFFu, s, o);
        s2 += __shfl_xor_sync(0xFFFFFFFFu, s2, o);
    }
    float mu = s * (1.0f / 192.0f);
    float rs = rsqrtf(s2 * (1.0f / 192.0f) - mu * mu + 1e-5f);
    __nv_bfloat16* q = out + (size_t)row * CC;
#pragma unroll
    for (int k = 0; k < 6; k++) {
        int c = lane + 32 * k;
        q[c] = __float2bfloat16((v[k] - mu) * rs * gamma[c] + beta[c]);
    }
}

#define CH_PER_BUF (192 * 8)

// ---------------------------------------------------------------------------
// K=192 multi-N GEMM: one CTA owns a 128-row block, A resident in SMEM,
// loops over NT N-tiles with double-buffered B (24KB each).
// SMEM: A = 3 kchunk-regions of 128x8 chunks (48KB); B = 2 bufs x 3 regions
// of 64x8 chunks (24KB each). Total 96KB -> 2 CTAs/SM.
// EPI 0: +bias, Q-scale cols<192 -> bf16   1: gelu(+bias) -> bf16
// ---------------------------------------------------------------------------
#define A_CHB  (128 * 8)                 // chunks per A k-region
#define B_CHB  (64 * 8)                  // chunks per B k-region
#define ABYTES (3 * A_CHB * 16)          // 49152
#define BBYTES (3 * B_CHB * 16)          // 24576
#define KM_SMEM (ABYTES + 2 * BBYTES)    // 98304

template <int EPI>
__global__ void __launch_bounds__(256) gemm_k192_multi(
    const __nv_bfloat16* __restrict__ A, const __nv_bfloat16* __restrict__ BT,
    const float* __restrict__ bias, void* __restrict__ outv, int NOUT) {
    extern __shared__ __align__(16) uint4 kmsq[];
    uint32_t sbase = smem_u32(kmsq);
    int tid = threadIdx.x;
    int wid = tid >> 5, lane = tid & 31;
    int wm = wid & 3, wn = wid >> 2;
    int m0 = blockIdx.x * 128;
    const int NT = NOUT >> 6;
    const __nv_bfloat16* Ab = A + (size_t)m0 * CC;

    int a_row = tid >> 1;
    int a_ch0 = (tid & 1) * 4;
    int b_row = tid >> 2;
    int b_ch0 = (tid & 3) * 2;

    int l15 = lane & 15, lhi = lane >> 4;
    int a_lrow = wm * 32 + l15;
    int a_sw = l15 & 7;
    int b_lrow = wn * 32 + (lhi << 3) + (lane & 7);
    int b_sw = lane & 7;
    int b_chlo = (lane >> 3) & 1;

    // prologue: A (all 3 k-regions) + B tile 0 -> group 0; B tile 1 -> group 1
#pragma unroll
    for (int kc = 0; kc < 3; kc++) {
        uint32_t dst = sbase + kc * A_CHB * 16;
        int k0 = kc << 6;
#pragma unroll
        for (int i = 0; i < 4; i++) {
            int ch = a_ch0 + i;
            cpasync16(dst + (a_row * 8 + (ch ^ (a_row & 7))) * 16,
                      Ab + (size_t)a_row * CC + k0 + ch * 8);
        }
    }
    {
        const __nv_bfloat16* Bb = BT;  // n-tile 0
#pragma unroll
        for (int kc = 0; kc < 3; kc++) {
            uint32_t dst = sbase + ABYTES + kc * B_CHB * 16;
            int k0 = kc << 6;
#pragma unroll
            for (int i = 0; i < 2; i++) {
                int ch = b_ch0 + i;
                cpasync16(dst + (b_row * 8 + (ch ^ (b_row & 7))) * 16,
                          Bb + (size_t)b_row * CC + k0 + ch * 8);
            }
        }
        cp_commit();
    }
    if (NT > 1) {
        const __nv_bfloat16* Bb = BT + (size_t)64 * CC;
#pragma unroll
        for (int kc = 0; kc < 3; kc++) {
            uint32_t dst = sbase + ABYTES + BBYTES + kc * B_CHB * 16;
            int k0 = kc << 6;
#pragma unroll
            for (int i = 0; i < 2; i++) {
                int ch = b_ch0 + i;
                cpasync16(dst + (b_row * 8 + (ch ^ (b_row & 7))) * 16,
                          Bb + (size_t)b_row * CC + k0 + ch * 8);
            }
        }
    }
    cp_commit();

    for (int nt = 0; nt < NT; nt++) {
        cp_wait1();
        __syncthreads();

        float acc[2][4][4];
#pragma unroll
        for (int i = 0; i < 2; i++)
#pragma unroll
            for (int j = 0; j < 4; j++)
#pragma unroll
                for (int k = 0; k < 4; k++) acc[i][j][k] = 0.f;

        uint32_t bbase = sbase + ABYTES + (nt & 1) * BBYTES;
#pragma unroll
        for (int kc = 0; kc < 3; kc++) {
            uint32_t abuf = sbase + kc * A_CHB * 16;
            uint32_t bbuf = bbase + kc * B_CHB * 16;
#pragma unroll
            for (int ks = 0; ks < 4; ks++) {
                uint32_t a[2][4], b[2][4];
                int achk = 2 * ks + lhi;
#pragma unroll
                for (int mt = 0; mt < 2; mt++) {
                    uint32_t idx = (a_lrow + mt * 16) * 8 + (achk ^ a_sw);
                    ldsm_x4(abuf + idx * 16, a[mt]);
                }
                int bchk = 2 * ks + b_chlo;
#pragma unroll
                for (int nt16 = 0; nt16 < 2; nt16++) {
                    uint32_t idx = (b_lrow + nt16 * 16) * 8 + (bchk ^ b_sw);
                    ldsm_x4(bbuf + idx * 16, b[nt16]);
                }
#pragma unroll
                for (int mt = 0; mt < 2; mt++) {
#pragma unroll
                    for (int nt16 = 0; nt16 < 2; nt16++) {
                        mma_bf16(acc[mt][nt16 * 2 + 0], a[mt], &b[nt16][0]);
                        mma_bf16(acc[mt][nt16 * 2 + 1], a[mt], &b[nt16][2]);
                    }
                }
            }
        }
        __syncthreads();   // all warps done with buffer (nt&1)

        // issue B tile nt+2 into buffer (nt&1); overlaps with epilogue
        if (nt + 2 < NT) {
            const __nv_bfloat16* Bb = BT + (size_t)(nt + 2) * 64 * CC;
            uint32_t dst0 = sbase + ABYTES + (nt & 1) * BBYTES;
#pragma unroll
            for (int kc = 0; kc < 3; kc++) {
                uint32_t dst = dst0 + kc * B_CHB * 16;
                int k0 = kc << 6;
#pragma unroll
                for (int i = 0; i < 2; i++) {
                    int ch = b_ch0 + i;
                    cpasync16(dst + (b_row * 8 + (ch ^ (b_row & 7))) * 16,
                              Bb + (size_t)b_row * CC + k0 + ch * 8);
                }
            }
        }
        cp_commit();

        // epilogue for this n-tile
        int n0 = nt * 64;
#pragma unroll
        for (int mt = 0; mt < 2; mt++) {
            int g0 = m0 + wm * 32 + mt * 16 + (lane >> 2);
            int g1 = g0 + 8;
            size_t ob0 = (size_t)g0 * NOUT;
            size_t ob1 = (size_t)g1 * NOUT;
#pragma unroll
            for (int ne = 0; ne < 4; ne++) {
                int col = n0 + wn * 32 + ne * 8 + 2 * (lane & 3);
                float b0 = bias[col], b1 = bias[col + 1];
                float2 v0 = make_float2(acc[mt][ne][0] + b0, acc[mt][ne][1] + b1);
                float2 v1 = make_float2(acc[mt][ne][2] + b0, acc[mt][ne][3] + b1);
                if (EPI == 0) {
                    float sc = (col < CC) ? QSCALE : 1.0f;
                    v0.x *= sc; v0.y *= sc; v1.x *= sc; v1.y *= sc;
                }
                if (EPI == 1) {
                    v0.x = gelu_exact(v0.x); v0.y = gelu_exact(v0.y);
                    v1.x = gelu_exact(v1.x); v1.y = gelu_exact(v1.y);
                }
                __nv_bfloat16* out = (__nv_bfloat16*)outv;
                *(__nv_bfloat162*)(out + ob0 + col) = __float22bfloat162_rn(v0);
                *(__nv_bfloat162*)(out + ob1 + col) = __float22bfloat162_rn(v1);
            }
        }
    }
}

// ---------------------------------------------------------------------------
// FC2 GEMM (K=768): 3-stage circular pipeline. +bias +res -> fp32.
// ---------------------------------------------------------------------------
#define FC2_SMEM (3 * CH_PER_BUF * 16)

__global__ void __launch_bounds__(256) gemm_fc2(
    const __nv_bfloat16* __restrict__ A, const __nv_bfloat16* __restrict__ BT,
    const float* __restrict__ bias, const float* __restrict__ res,
    float* __restrict__ out) {
    extern __shared__ __align__(16) uint4 fsmq[];
    uint32_t sbase = smem_u32(fsmq);
    const int K = HIDDEN;
    const int NCH = K >> 6;
    int tid = threadIdx.x;
    int wid = tid >> 5, lane = tid & 31;
    int wm = wid & 3, wn = wid >> 2;
    int m0 = blockIdx.y * 128, n0 = blockIdx.x * 64;
    const __nv_bfloat16* Ab = A + (size_t)m0 * K;
    const __nv_bfloat16* Bb = BT + (size_t)n0 * K;

    float acc[2][4][4];
#pragma unroll
    for (int i = 0; i < 2; i++)
#pragma unroll
        for (int j = 0; j < 4; j++)
#pragma unroll
            for (int k = 0; k < 4; k++) acc[i][j][k] = 0.f;

    int a_row = tid >> 1;
    int a_ch0 = (tid & 1) * 4;
    int b_row = tid >> 2;
    int b_ch0 = (tid & 3) * 2;

    int l15 = lane & 15, lhi = lane >> 4;
    int a_lrow = wm * 32 + l15;
    int a_sw = l15 & 7;
    int b_lrow = 128 + wn * 32 + (lhi << 3) + (lane & 7);
    int b_sw = lane & 7;
    int b_chlo = (lane >> 3) & 1;

#pragma unroll
    for (int c = 0; c < 2; c++) {
        uint32_t dst = sbase + c * CH_PER_BUF * 16;
        int k0 = c << 6;
#pragma unroll
        for (int i = 0; i < 4; i++) {
            int ch = a_ch0 + i;
            cpasync16(dst + (a_row * 8 + (ch ^ (a_row & 7))) * 16,
                      Ab + (size_t)a_row * K + k0 + ch * 8);
        }
#pragma unroll
        for (int i = 0; i < 2; i++) {
            int ch = b_ch0 + i;
            cpasync16(dst + ((128 + b_row) * 8 + (ch ^ (b_row & 7))) * 16,
                      Bb + (size_t)b_row * K + k0 + ch * 8);
        }
        cp_commit();
    }

    int bufsel = 0;
    for (int c = 0; c < NCH; c++) {
        cp_wait1();
        __syncthreads();

        if (c + 2 < NCH) {
            int nb = bufsel + 2; if (nb >= 3) nb -= 3;
            uint32_t dst = sbase + nb * CH_PER_BUF * 16;
            int k0 = (c + 2) << 6;
#pragma unroll
            for (int i = 0; i < 4; i++) {
                int ch = a_ch0 + i;
                cpasync16(dst + (a_row * 8 + (ch ^ (a_row & 7))) * 16,
                          Ab + (size_t)a_row * K + k0 + ch * 8);
            }
#pragma unroll
            for (int i = 0; i < 2; i++) {
                int ch = b_ch0 + i;
                cpasync16(dst + ((128 + b_row) * 8 + (ch ^ (b_row & 7))) * 16,
                          Bb + (size_t)b_row * K + k0 + ch * 8);
            }
        }
        cp_commit();

        uint32_t buf = sbase + bufsel * CH_PER_BUF * 16;
#pragma unroll
        for (int ks = 0; ks < 4; ks++) {
            uint32_t a[2][4], b[2][4];
            int achk = 2 * ks + lhi;
#pragma unroll
            for (int mt = 0; mt < 2; mt++) {
                uint32_t idx = (a_lrow + mt * 16) * 8 + (achk ^ a_sw);
                ldsm_x4(buf + idx * 16, a[mt]);
            }
            int bchk = 2 * ks + b_chlo;
#pragma unroll
            for (int nt16 = 0; nt16 < 2; nt16++) {
                uint32_t idx = (b_lrow + nt16 * 16) * 8 + (bchk ^ b_sw);
                ldsm_x4(buf + idx * 16, b[nt16]);
            }
#pragma unroll
            for (int mt = 0; mt < 2; mt++) {
#pragma unroll
                for (int nt16 = 0; nt16 < 2; nt16++) {
                    mma_bf16(acc[mt][nt16 * 2 + 0], a[mt], &b[nt16][0]);
                    mma_bf16(acc[mt][nt16 * 2 + 1], a[mt], &b[nt16][2]);
                }
            }
        }
        bufsel++; if (bufsel == 3) bufsel = 0;
    }

#pragma unroll
    for (int mt = 0; mt < 2; mt++) {
        int g0 = m0 + wm * 32 + mt * 16 + (lane >> 2);
        int g1 = g0 + 8;
        size_t ob0 = (size_t)g0 * CC;
        size_t ob1 = (size_t)g1 * CC;
#pragma unroll
        for (int nt = 0; nt < 4; nt++) {
            int col = n0 + wn * 32 + nt * 8 + 2 * (lane & 3);
            float b0 = bias[col], b1 = bias[col + 1];
            float2 v0 = make_float2(acc[mt][nt][0] + b0, acc[mt][nt][1] + b1);
            float2 v1 = make_float2(acc[mt][nt][2] + b0, acc[mt][nt][3] + b1);
            float2 r0 = *(const float2*)(res + ob0 + col);
            float2 r1 = *(const float2*)(res + ob1 + col);
            v0.x += r0.x; v0.y += r0.y;
            v1.x += r1.x; v1.y += r1.y;
            *(float2*)(out + ob0 + col) = v0;
            *(float2*)(out + ob1 + col) = v1;
        }
    }
}

// ---------------------------------------------------------------------------
// Proj GEMM + scatter + residual + LN2 (fused)
// ---------------------------------------------------------------------------
#define PCH_PER_BUF (320 * 8)
#define PROJ_SMEM (2 * PCH_PER_BUF * 16)

__global__ void __launch_bounds__(256) gemm_proj_ln(
    const __nv_bfloat16* __restrict__ A, const __nv_bfloat16* __restrict__ BT,
    const float* __restrict__ bias, const float* __restrict__ x,
    float* __restrict__ y, __nv_bfloat16* __restrict__ ln2out,
    const float* __restrict__ n2g, const float* __restrict__ n2b) {
    extern __shared__ __align__(16) uint4 psm[];
    uint32_t sbase = smem_u32(psm);
    int tid = threadIdx.x;
    int wid = tid >> 5, lane = tid & 31;
    int m0 = blockIdx.x * 128;
    const __nv_bfloat16* Ab = A + (size_t)m0 * CC;

    float acc[24][4];
#pragma unroll
    for (int j = 0; j < 24; j++)
#pragma unroll
        for (int k = 0; k < 4; k++) acc[j][k] = 0.f;

    int a_row = tid >> 1;
    int a_ch0 = (tid & 1) * 4;
    int b_row = tid >> 2;
    int b_ch0 = (tid & 3) * 2;

    int l15 = lane & 15, lhi = lane >> 4;
    int a_lrow = wid * 16 + l15;
    int a_sw = l15 & 7;
    int b_lbase = 128 + (lhi << 3) + (lane & 7);
    int b_sw = lane & 7;
    int b_chlo = (lane >> 3) & 1;

    {
        uint32_t dst = sbase;
#pragma unroll
        for (int i = 0; i < 4; i++) {
            int ch = a_ch0 + i;
            cpasync16(dst + (a_row * 8 + (ch ^ (a_row & 7))) * 16,
                      Ab + (size_t)a_row * CC + ch * 8);
        }
#pragma unroll
        for (int r3 = 0; r3 < 3; r3++) {
            int row = r3 * 64 + b_row;
#pragma unroll
            for (int i = 0; i < 2; i++) {
                int ch = b_ch0 + i;
                cpasync16(dst + ((128 + row) * 8 + (ch ^ (row & 7))) * 16,
                          BT + (size_t)row * CC + ch * 8);
            }
        }
        cp_commit();
    }

    for (int c = 0; c < 3; c++) {
        if (c + 1 < 3) {
            int k0 = (c + 1) << 6;
            uint32_t dst = sbase + ((c + 1) & 1) * PCH_PER_BUF * 16;
#pragma unroll
            for (int i = 0; i < 4; i++) {
                int ch = a_ch0 + i;
                cpasync16(dst + (a_row * 8 + (ch ^ (a_row & 7))) * 16,
                          Ab + (size_t)a_row * CC + k0 + ch * 8);
            }
#pragma unroll
            for (int r3 = 0; r3 < 3; r3++) {
                int row = r3 * 64 + b_row;
#pragma unroll
                for (int i = 0; i < 2; i++) {
                    int ch = b_ch0 + i;
                    cpasync16(dst + ((128 + row) * 8 + (ch ^ (row & 7))) * 16,
                              BT + (size_t)row * CC + k0 + ch * 8);
                }
            }
        }
        cp_commit();
        cp_wait1();
        __syncthreads();

        uint32_t buf = sbase + (c & 1) * PCH_PER_BUF * 16;
#pragma unroll
        for (int ks = 0; ks < 4; ks++) {
            uint32_t a[4];
            int achk = 2 * ks + lhi;
            ldsm_x4(buf + (a_lrow * 8 + (achk ^ a_sw)) * 16, a);
            int bchk = 2 * ks + b_chlo;
#pragma unroll
            for (int nt16 = 0; nt16 < 12; nt16++) {
                uint32_t b[4];
                ldsm_x4(buf + ((b_lbase + nt16 * 16) * 8 + (bchk ^ b_sw)) * 16, b);
                mma_bf16(acc[nt16 * 2 + 0], a, &b[0]);
                mma_bf16(acc[nt16 * 2 + 1], a, &b[2]);
            }
        }
        __syncthreads();
    }

    int lq = lane & 3;
#pragma unroll
    for (int half = 0; half < 2; half++) {
        int g = m0 + wid * 16 + (lane >> 2) + half * 8;
        int bb = g >> 14, rem = g & 16383;
        int win = rem >> 6, rr = rem & 63;
        int wy = win >> 4, wx = win & 15, ry = rr >> 3, rx = rr & 7;
        int hh = (wy * WS + ry + SHIFT) & 127;
        int ww = (wx * WS + rx + SHIFT) & 127;
        size_t ob = ((size_t)bb * LL + hh * WW_ + ww) * CC;

        float vals[48];
        float s = 0.f, s2 = 0.f;
#pragma unroll
        for (int nt = 0; nt < 24; nt++) {
            int col = nt * 8 + 2 * lq;
            float v0 = acc[nt][half * 2 + 0] + bias[col];
            float v1 = acc[nt][half * 2 + 1] + bias[col + 1];
            float2 rv = *(const float2*)(x + ob + col);
            v0 += rv.x; v1 += rv.y;
            *(float2*)(y + ob + col) = make_float2(v0, v1);
            s += v0 + v1;
            s2 += v0 * v0 + v1 * v1;
            vals[nt * 2] = v0; vals[nt * 2 + 1] = v1;
        }
        s += __shfl_xor_sync(0xFFFFFFFFu, s, 1);
        s2 += __shfl_xor_sync(0xFFFFFFFFu, s2, 1);
        s += __shfl_xor_sync(0xFFFFFFFFu, s, 2);
        s2 += __shfl_xor_sync(0xFFFFFFFFu, s2, 2);
        float mu = s * (1.0f / 192.0f);
        float rs = rsqrtf(s2 * (1.0f / 192.0f) - mu * mu + 1e-5f);
#pragma unroll
        for (int nt = 0; nt < 24; nt++) {
            int col = nt * 8 + 2 * lq;
            float2 gg = *(const float2*)(n2g + col);
            float2 bb2 = *(const float2*)(n2b + col);
            float2 o;
            o.x = (vals[nt * 2] - mu) * rs * gg.x + bb2.x;
            o.y = (vals[nt * 2 + 1] - mu) * rs * gg.y + bb2.y;
            *(__nv_bfloat162*)(ln2out + ob + col) = __float22bfloat162_rn(o);
        }
    }
}

// ---------------------------------------------------------------------------
// Tensor-core windowed attention (round-13 version)
// ---------------------------------------------------------------------------
#define KSTR 200
#define VSTR 72
#define ATTN_SMEM ((2 * NWIN * KSTR + CC * VSTR) * 2)

__global__ void __launch_bounds__(384) attn_kernel(
    const __nv_bfloat16* __restrict__ qkv, __nv_bfloat16* __restrict__ outp) {
    extern __shared__ __nv_bfloat16 smh[];
    __nv_bfloat16* q_s = smh;
    __nv_bfloat16* k_s = smh + NWIN * KSTR;
    __nv_bfloat16* vt_s = smh + 2 * NWIN * KSTR;

    int w = blockIdx.x;
    int tid = threadIdx.x;
    int lane = tid & 31, wid = tid >> 5;
    const __nv_bfloat16* base = qkv + (size_t)w * NWIN * 576;

    for (int idx = tid; idx < NWIN * 24; idx += 384) {
        int j = idx / 24, c = idx % 24;
        const __nv_bfloat16* rowp = base + (size_t)j * 576 + c * 8;
        uint4 uq = *(const uint4*)(rowp);
        *(uint4*)(q_s + j * KSTR + c * 8) = uq;
        uint4 uk = *(const uint4*)(rowp + 192);
        *(uint4*)(k_s + j * KSTR + c * 8) = uk;
        uint4 uv = *(const uint4*)(rowp + 384);
        const unsigned short* e = (const unsigned short*)&uv;
#pragma unroll
        for (int i = 0; i < 8; i++) {
            int k = (i + lane) & 7;
            *((unsigned short*)vt_s + (c * 8 + k) * VSTR + j) = e[k];
        }
    }
    __syncthreads();

    int h = wid >> 1;
    int mbase = (wid & 1) * 32;
    int winloc = w & 255;
    int wy = winloc >> 4, wx = winloc & 15;
    int type = ((wy == 15) ? 2 : 0) | ((wx == 15) ? 1 : 0);
    const float* btab = g_bias + ((size_t)(type * HEADS + h) * NWIN) * NWIN;

    int rq = lane >> 2, cq = 2 * (lane & 3);
    int l15 = lane & 15, lhi = lane >> 4;
    int brow = (lhi << 3) + (lane & 7);
    int bchlo = (lane >> 3) & 1;

    uint32_t qsm = smem_u32(q_s);
    uint32_t a[2][2][4];
#pragma unroll
    for (int mt = 0; mt < 2; mt++)
#pragma unroll
        for (int ks = 0; ks < 2; ks++) {
            uint32_t addr = qsm +
                ((mbase + mt * 16 + l15) * KSTR + h * HD + ks * 16 + lhi * 8) * 2;
            ldsm_x4(addr, a[mt][ks]);
        }

    float p[2][8][4];
#pragma unroll
    for (int i = 0; i < 2; i++)
#pragma unroll
        for (int j = 0; j < 8; j++)
#pragma unroll
            for (int k = 0; k < 4; k++) p[i][j][k] = 0.f;

    uint32_t ksm = smem_u32(k_s);
#pragma unroll
    for (int kg = 0; kg < 4; kg++) {
#pragma unroll
        for (int ks = 0; ks < 2; ks++) {
            uint32_t b[4];
            uint32_t addr = ksm + ((kg * 16 + brow) * KSTR + (h * 4 + ks * 2 + bchlo) * 8) * 2;
            ldsm_x4(addr, b);
#pragma unroll
            for (int mt = 0; mt < 2; mt++) {
                mma_bf16(p[mt][kg * 2 + 0], a[mt][ks], &b[0]);
                mma_bf16(p[mt][kg * 2 + 1], a[mt][ks], &b[2]);
            }
        }
    }

    float sums[2][2];
#pragma unroll
    for (int mt = 0; mt < 2; mt++) {
#pragma unroll
        for (int rl = 0; rl < 2; rl++) {
            int r = mbase + mt * 16 + rq + rl * 8;
            const float* br_ = btab + r * NWIN;
            float m = -1e30f;
#pragma unroll
            for (int nt = 0; nt < 8; nt++) {
                float2 bv = *(const float2*)(br_ + nt * 8 + cq);
                p[mt][nt][rl * 2 + 0] += bv.x;
                p[mt][nt][rl * 2 + 1] += bv.y;
                m = fmaxf(m, fmaxf(p[mt][nt][rl * 2], p[mt][nt][rl * 2 + 1]));
            }
            m = fmaxf(m, __shfl_xor_sync(0xFFFFFFFFu, m, 1));
            m = fmaxf(m, __shfl_xor_sync(0xFFFFFFFFu, m, 2));
            float s = 0.f;
#pragma unroll
            for (int nt = 0; nt < 8; nt++) {
                float e0 = __expf(p[mt][nt][rl * 2] - m);
                float e1 = __expf(p[mt][nt][rl * 2 + 1] - m);
                p[mt][nt][rl * 2] = e0; p[mt][nt][rl * 2 + 1] = e1;
                s += e0 + e1;
            }
            s += __shfl_xor_sync(0xFFFFFFFFu, s, 1);
            s += __shfl_xor_sync(0xFFFFFFFFu, s, 2);
            sums[mt][rl] = s;
        }
    }

    uint32_t pa[2][4][4];
#pragma unroll
    for (int mt = 0; mt < 2; mt++)
#pragma unroll
        for (int s4 = 0; s4 < 4; s4++) {
            pa[mt][s4][0] = packbf2(p[mt][2 * s4][0], p[mt][2 * s4][1]);
            pa[mt][s4][1] = packbf2(p[mt][2 * s4][2], p[mt][2 * s4][3]);
            pa[mt][s4][2] = packbf2(p[mt][2 * s4 + 1][0], p[mt][2 * s4 + 1][1]);
            pa[mt][s4][3] = packbf2(p[mt][2 * s4 + 1][2], p[mt][2 * s4 + 1][3]);
        }

    float o[2][4][4];
#pragma unroll
    for (int i = 0; i < 2; i++)
#pragma unroll
        for (int j = 0; j < 4; j++)
#pragma unroll
            for (int k = 0; k < 4; k++) o[i][j][k] = 0.f;

    uint32_t vsm = smem_u32(vt_s);
#pragma unroll
    for (int s4 = 0; s4 < 4; s4++) {
#pragma unroll
        for (int n16 = 0; n16 < 2; n16++) {
            uint32_t b[4];
            uint32_t addr = vsm + ((h * HD + n16 * 16 + brow) * VSTR + (s4 * 2 + bchlo) * 8) * 2;
            ldsm_x4(addr, b);
#pragma unroll
            for (int mt = 0; mt < 2; mt++) {
                mma_bf16(o[mt][n16 * 2 + 0], pa[mt][s4], &b[0]);
                mma_bf16(o[mt][n16 * 2 + 1], pa[mt][s4], &b[2]);
            }
        }
    }

#pragma unroll
    for (int mt = 0; mt < 2; mt++) {
        float i0 = 1.0f / sums[mt][0];
        float i1 = 1.0f / sums[mt][1];
        int r0 = mbase + mt * 16 + rq;
        __nv_bfloat16* op0 = outp + (size_t)(w * NWIN + r0) * CC + h * HD;
        __nv_bfloat16* op1 = op0 + 8 * CC;
#pragma unroll
        for (int nt = 0; nt < 4; nt++) {
            *(__nv_bfloat162*)(op0 + nt * 8 + cq) =
                __float22bfloat162_rn(make_float2(o[mt][nt][0] * i0, o[mt][nt][1] * i0));
            *(__nv_bfloat162*)(op1 + nt * 8 + cq) =
                __float22bfloat162_rn(make_float2(o[mt][nt][2] * i1, o[mt][nt][3] * i1));
        }
    }
}

// ---------------------------------------------------------------------------
// Launch
// ---------------------------------------------------------------------------
extern "C" void kernel_launch(void* const* d_in, const int* in_sizes, int n_in,
                              void* d_out, int out_size) {
    const float* x      = (const float*)d_in[0];
    const float* n1_g   = (const float*)d_in[4];
    const float* n1_b   = (const float*)d_in[5];
    const float* qkv_w  = (const float*)d_in[6];
    const float* qkv_b  = (const float*)d_in[7];
    const float* proj_w = (const float*)d_in[8];
    const float* proj_b = (const float*)d_in[9];
    const float* pp_w   = (const float*)d_in[10];
    const float* pp_b   = (const float*)d_in[11];
    const float* p1_g   = (const float*)d_in[12];
    const float* p1_b   = (const float*)d_in[13];
    const float* p1_w   = (const float*)d_in[14];
    const float* p1_bi  = (const float*)d_in[15];
    const float* p2_g   = (const float*)d_in[16];
    const float* p2_b   = (const float*)d_in[17];
    const float* p2_w   = (const float*)d_in[18];
    const float* p2_bi  = (const float*)d_in[19];
    const float* p3_g   = (const float*)d_in[20];
    const float* p3_b   = (const float*)d_in[21];
    const float* p3_w   = (const float*)d_in[22];
    const float* p3_bi  = (const float*)d_in[23];
    const float* n2_g   = (const float*)d_in[24];
    const float* n2_b   = (const float*)d_in[25];
    const float* fc1_w  = (const float*)d_in[26];
    const float* fc1_b  = (const float*)d_in[27];
    const float* fc2_w  = (const float*)d_in[28];
    const float* fc2_b  = (const float*)d_in[29];
    float* out = (float*)d_out;

    __nv_bfloat16 *xw, *qkv, *attn, *ln2, *hid;
    __nv_bfloat16 *wt_qkv, *wt_proj, *wt_fc1, *wt_fc2;
    cudaGetSymbolAddress((void**)&xw,   gb_xw);
    cudaGetSymbolAddress((void**)&qkv,  gb_qkv);
    cudaGetSymbolAddress((void**)&attn, gb_attn);
    cudaGetSymbolAddress((void**)&ln2,  gb_ln2);
    cudaGetSymbolAddress((void**)&hid,  gb_hid);
    cudaGetSymbolAddress((void**)&wt_qkv,  gb_wt_qkv);
    cudaGetSymbolAddress((void**)&wt_proj, gb_wt_proj);
    cudaGetSymbolAddress((void**)&wt_fc1,  gb_wt_fc1);
    cudaGetSymbolAddress((void**)&wt_fc2,  gb_wt_fc2);

    static bool attr_set = false;
    if (!attr_set) {
        cudaFuncSetAttribute(attn_kernel, cudaFuncAttributeMaxDynamicSharedMemorySize,
                             ATTN_SMEM);
        cudaFuncSetAttribute(gemm_proj_ln, cudaFuncAttributeMaxDynamicSharedMemorySize,
                             PROJ_SMEM);
        cudaFuncSetAttribute(gemm_k192_multi<0>, cudaFuncAttributeMaxDynamicSharedMemorySize,
                             KM_SMEM);
        cudaFuncSetAttribute(gemm_k192_multi<1>, cudaFuncAttributeMaxDynamicSharedMemorySize,
                             KM_SMEM);
        cudaFuncSetAttribute(gemm_fc2, cudaFuncAttributeMaxDynamicSharedMemorySize,
                             FC2_SMEM);
        attr_set = true;
    }

    // 0. weight transposes
    transpose_all<<<(TW_TOTAL + 255) / 256, 256>>>(qkv_w, proj_w, fc1_w, fc2_w);

    // 1. bias table with inline position-MLP
    bias_build<<<(4 * HEADS * NWIN * NWIN + 255) / 256, 256>>>(
        pp_w, pp_b, p1_g, p1_b, p1_w, p1_bi,
        p2_g, p2_b, p2_w, p2_bi, p3_g, p3_b, p3_w, p3_bi);

    // 2. LN1 + shift + window partition -> bf16
    ln1_kernel<<<MROWS / 8, 256>>>(x, xw, n1_g, n1_b);

    // 3. QKV GEMM (multi-N, A resident) -> bf16, Q pre-scaled
    gemm_k192_multi<0><<<MROWS / 128, 256, KM_SMEM>>>(xw, wt_qkv, qkv_b, qkv, 576);

    // 4. tensor-core attention -> bf16
    attn_kernel<<<NWINDOWS, 384, ATTN_SMEM>>>(qkv, attn);

    // 5. proj + scatter + residual + LN2 (fused)
    gemm_proj_ln<<<MROWS / 128, 256, PROJ_SMEM>>>(attn, wt_proj, proj_b, x, out, ln2, n2_g, n2_b);

    // 6. FC1 + GELU (multi-N, A resident) -> bf16
    gemm_k192_multi<1><<<MROWS / 128, 256, KM_SMEM>>>(ln2, wt_fc1, fc1_b, hid, HIDDEN);

    // 7. FC2 + residual -> fp32 out (3-stage pipeline, K=768)
    gemm_fc2<<<dim3(CC / 64, MROWS / 128), 256, FC2_SMEM>>>(hid, wt_fc2, fc2_b, out, out);
}